// round 4
// baseline (speedup 1.0000x reference)
#include <cuda_runtime.h>

// ---------------- problem constants ----------------
#define DI   128
#define BATCH 2
#define HDm  64
#define WDm  96
#define HUm  128
#define WUm  192
#define SDL  (HDm*WDm)           // 6144
#define SPL  (HUm*WUm)           // 24576
#define ND   (BATCH*SDL)         // 12288
#define NP   (BATCH*SPL)         // 49152
#define KVP  640                 // kv0(256) | kv1(256) | ctxp(128)

typedef unsigned long long u64;

// ---------------- device scratch ----------------
__device__ float g_ctxln[ND*DI];
__device__ float g_x[NP*DI];
__device__ float g_kvp[ND*KVP];
__device__ float g_W[DI*KVP];
__device__ float g_bias[KVP];

// ---------------- packed f32x2 helpers ----------------
__device__ __forceinline__ u64 fma2(u64 a, u64 b, u64 c) {
    u64 d;
    asm("fma.rn.f32x2 %0, %1, %2, %3;" : "=l"(d) : "l"(a), "l"(b), "l"(c));
    return d;
}
__device__ __forceinline__ float2 unpack2(u64 v) {
    float2 r;
    asm("mov.b64 {%0, %1}, %2;" : "=f"(r.x), "=f"(r.y) : "l"(v));
    return r;
}

// ========================================================================
// K1: fold nc_w/nc_b into combined weight
// ========================================================================
__global__ void prep_kernel(const float* __restrict__ nc_w,
                            const float* __restrict__ nc_b,
                            const float* __restrict__ wkv,
                            const float* __restrict__ bkv,
                            const float* __restrict__ wcf,
                            const float* __restrict__ bcf) {
    int j = blockIdx.x * blockDim.x + threadIdx.x;
    if (j >= KVP) return;
    if (j < 512) {
        int l  = j >> 8;
        int jj = j & 255;
        const float* w = wkv + (size_t)l * DI * 256;
        float bias = bkv[l*256 + jj];
        for (int c = 0; c < DI; c++) {
            float wv = w[c*256 + jj];
            g_W[c*KVP + j] = nc_w[l*DI + c] * wv;
            bias += nc_b[l*DI + c] * wv;
        }
        g_bias[j] = bias;
    } else {
        int jj = j - 512;
        for (int c = 0; c < DI; c++)
            g_W[c*KVP + j] = wcf[c*DI + jj];
        g_bias[j] = bcf[jj];
    }
}

// ========================================================================
// K2: transpose feat_map + fused LayerNorm
// ========================================================================
__global__ void trln_kernel(const float* __restrict__ fm) {
    __shared__ float st[DI][33];
    int dp0 = blockIdx.x * 32;
    int b = dp0 / SDL, hw0 = dp0 % SDL;
    const float* src = fm + (size_t)b * DI * SDL + hw0;
    int t = threadIdx.x;
    #pragma unroll
    for (int i = 0; i < 16; i++) {
        int e = t + i*256;
        int c = e >> 5, p = e & 31;
        st[c][p] = src[(size_t)c*SDL + p];
    }
    __syncthreads();
    int p = t >> 3, g = t & 7;
    float s = 0.f, s2 = 0.f;
    #pragma unroll
    for (int i = 0; i < 16; i++) {
        float v = st[g*16 + i][p];
        s += v; s2 += v*v;
    }
    #pragma unroll
    for (int off = 4; off; off >>= 1) {
        s  += __shfl_xor_sync(0xffffffffu, s,  off, 8);
        s2 += __shfl_xor_sync(0xffffffffu, s2, off, 8);
    }
    float mu   = s * (1.f/128.f);
    float rstd = rsqrtf(s2*(1.f/128.f) - mu*mu + 1e-6f);
    float* dst = g_ctxln + (size_t)(dp0 + p) * DI;
    #pragma unroll
    for (int i = 0; i < 16; i++) {
        int c = g*16 + i;
        dst[c] = (st[c][p] - mu) * rstd;
    }
}

// ========================================================================
// K3: transpose feat_map_up -> x rows
// ========================================================================
__global__ void trx_kernel(const float* __restrict__ fmu) {
    __shared__ float st[DI][33];
    int n0 = blockIdx.x * 32;
    int b = n0 / SPL, s0 = n0 % SPL;
    const float* src = fmu + (size_t)b * DI * SPL + s0;
    int t = threadIdx.x;
    #pragma unroll
    for (int i = 0; i < 16; i++) {
        int e = t + i*256;
        int c = e >> 5, p = e & 31;
        st[c][p] = src[(size_t)c*SPL + p];
    }
    __syncthreads();
    int p = t >> 3, g = t & 7;
    float* dst = g_x + (size_t)(n0 + p) * DI;
    #pragma unroll
    for (int i = 0; i < 16; i++) {
        int c = g*16 + i;
        dst[c] = st[c][p];
    }
}

// ========================================================================
// GEMM engine: A[64 rows][pitch 132], output chunk = 128 cols, K chunk = 64
// sW layout: [k2 0..31][j*2 + parity], row = 256 floats
// thread (tx = t&15, ty = t>>4): rows ty*4..+3, cols tx*8..+7
// ========================================================================
__device__ __forceinline__ void loadW(float* sW, const float* __restrict__ src,
                                      int ldw, int kbase, int t) {
    #pragma unroll
    for (int f = t; f < 32*128; f += 256) {
        int k2 = f >> 7, j = f & 127;
        const float* p = src + (size_t)(kbase + 2*k2)*ldw + j;
        float2 v;
        v.x = __ldg(p);
        v.y = __ldg(p + ldw);
        *(float2*)(sW + k2*256 + j*2) = v;
    }
}

__device__ __forceinline__ void gemm128(const float* __restrict__ sA,
                                        const float* __restrict__ sW,
                                        u64 acc[4][8], int r0, int tx,
                                        int kbase) {
    #pragma unroll 2
    for (int k2 = 0; k2 < 32; k2++) {
        u64 a[4];
        #pragma unroll
        for (int i = 0; i < 4; i++)
            a[i] = *(const u64*)(sA + (r0 + i)*132 + kbase + 2*k2);
        const float* wp = sW + k2*256 + tx*16;
        ulonglong2 w0 = *(const ulonglong2*)(wp);
        ulonglong2 w1 = *(const ulonglong2*)(wp + 4);
        ulonglong2 w2 = *(const ulonglong2*)(wp + 8);
        ulonglong2 w3 = *(const ulonglong2*)(wp + 12);
        u64 w[8] = {w0.x, w0.y, w1.x, w1.y, w2.x, w2.y, w3.x, w3.y};
        #pragma unroll
        for (int i = 0; i < 4; i++)
            #pragma unroll
            for (int j = 0; j < 8; j++)
                acc[i][j] = fma2(a[i], w[j], acc[i][j]);
    }
}

__device__ __forceinline__ float gelu_tanh(float v) {
    float u = 0.7978845608028654f * (v + 0.044715f * v * v * v);
    u = fminf(fmaxf(u, -15.f), 15.f);
    float e = __expf(-2.f * u);
    float th = (1.f - e) / (1.f + e);
    return 0.5f * v * (1.f + th);
}

// LayerNorm xr -> sIn; thread owns rows ty*4..+3, cols tx*8..+7
__device__ __forceinline__ void ln_rows(const float xr[4][8], float* sIn,
                                        int ty, int tx) {
    #pragma unroll
    for (int i = 0; i < 4; i++) {
        float s = 0.f, s2 = 0.f;
        #pragma unroll
        for (int j = 0; j < 8; j++) {
            float v = xr[i][j];
            s += v; s2 += v*v;
        }
        #pragma unroll
        for (int off = 8; off; off >>= 1) {
            s  += __shfl_xor_sync(0xffffffffu, s,  off, 16);
            s2 += __shfl_xor_sync(0xffffffffu, s2, off, 16);
        }
        float mu   = s * (1.f/128.f);
        float rstd = rsqrtf(s2*(1.f/128.f) - mu*mu + 1e-6f);
        float4 o0, o1;
        o0.x = (xr[i][0]-mu)*rstd; o0.y = (xr[i][1]-mu)*rstd;
        o0.z = (xr[i][2]-mu)*rstd; o0.w = (xr[i][3]-mu)*rstd;
        o1.x = (xr[i][4]-mu)*rstd; o1.y = (xr[i][5]-mu)*rstd;
        o1.z = (xr[i][6]-mu)*rstd; o1.w = (xr[i][7]-mu)*rstd;
        float* dst = sIn + (ty*4 + i)*132 + tx*8;
        *(float4*)(dst)     = o0;
        *(float4*)(dst + 4) = o1;
    }
}

// neighbor dpixel indices, recomputed on demand (keeps regs cold in GEMMs)
__device__ __forceinline__ void calc_dpix(int n, int dpix[9]) {
    int b  = n / SPL, s = n % SPL;
    int hu = s / WUm, wu = s % WUm;
    int hd = hu >> 1, wd = wu >> 1;
    #pragma unroll
    for (int i = 0; i < 3; i++)
        #pragma unroll
        for (int j = 0; j < 3; j++) {
            int hs = min(max(hd - 1 + i, 0), HDm - 1);
            int ws = min(max(wd - 1 + j, 0), WDm - 1);
            dpix[i*3 + j] = b*SDL + hs*WDm + ws;
        }
}

// ========================================================================
// K4: per-dpixel GEMM  g_kvp = g_ctxln @ g_W + g_bias
//     64 rows/block, 256 threads, 2 CTAs/SM
// ========================================================================
#define DGEMM_SMEM ((64*132 + 32*256) * 4)
__global__ void __launch_bounds__(256, 2) dgemm_kernel() {
    extern __shared__ float sm[];
    float* sIn = sm;                // 64x132
    float* sW  = sm + 64*132;       // 32 k2 x 256
    int t  = threadIdx.x;
    int tx = t & 15, ty = t >> 4;
    int r0 = ty * 4;
    int n0 = blockIdx.x * 64;

    #pragma unroll
    for (int i = 0; i < 8; i++) {
        int f = t + i*256;
        int r = f >> 5, j4 = f & 31;
        *(float4*)(sIn + r*132 + j4*4) =
            *(const float4*)(g_ctxln + (size_t)(n0 + r)*DI + j4*4);
    }
    __syncthreads();

    for (int c = 0; c < 5; c++) {
        u64 acc[4][8] = {};
        #pragma unroll
        for (int kc = 0; kc < 2; kc++) {
            loadW(sW, g_W + c*128, KVP, kc*64, t);
            __syncthreads();
            gemm128(sIn, sW, acc, r0, tx, kc*64);
            __syncthreads();
        }
        float4 b0 = *(const float4*)(g_bias + c*128 + tx*8);
        float4 b1 = *(const float4*)(g_bias + c*128 + tx*8 + 4);
        float bb[8] = {b0.x,b0.y,b0.z,b0.w,b1.x,b1.y,b1.z,b1.w};
        #pragma unroll
        for (int i = 0; i < 4; i++) {
            float o[8];
            #pragma unroll
            for (int j = 0; j < 8; j++) {
                float2 p = unpack2(acc[i][j]);
                o[j] = p.x + p.y + bb[j];
            }
            float* dst = g_kvp + (size_t)(n0 + r0 + i)*KVP + c*128 + tx*8;
            *(float4*)(dst)     = make_float4(o[0],o[1],o[2],o[3]);
            *(float4*)(dst + 4) = make_float4(o[4],o[5],o[6],o[7]);
        }
    }
}

// ========================================================================
// K5: mega kernel — 64 pixels/block, 256 threads, 2 CTAs/SM
// ========================================================================
#define MEGA_SMEM ((2*64*132 + 32*256) * 4)
__global__ void __launch_bounds__(256, 2) mega_kernel(
    const float* __restrict__ wq,  const float* __restrict__ bq,
    const float* __restrict__ wo,  const float* __restrict__ bo,
    const float* __restrict__ w1,  const float* __restrict__ b1,
    const float* __restrict__ w2,  const float* __restrict__ b2,
    const float* __restrict__ wqf, const float* __restrict__ bqf,
    float* __restrict__ out)
{
    extern __shared__ float sm[];
    float* sIn  = sm;               // 64x132 : LN(x) (GEMM A)
    float* sOut = sm + 64*132;      // 64x132 : q / o / gelu(h) / xq
    float* sW   = sm + 2*64*132;    // 32 k2 x 256 : weight K-chunk

    const int t  = threadIdx.x;
    const int tx = t & 15, ty = t >> 4;
    const int r0 = ty * 4;
    const int n0 = blockIdx.x * 64;
    const int ap = t >> 2;          // attention pixel (4 thr/pixel)
    const int hh = t & 3;           // head

    // x tile in registers: rows r0..+3, cols tx*8..+7
    float xr[4][8];
    #pragma unroll
    for (int i = 0; i < 4; i++) {
        float4 v0 = *(const float4*)(g_x + (size_t)(n0+r0+i)*DI + tx*8);
        float4 v1 = *(const float4*)(g_x + (size_t)(n0+r0+i)*DI + tx*8 + 4);
        xr[i][0]=v0.x; xr[i][1]=v0.y; xr[i][2]=v0.z; xr[i][3]=v0.w;
        xr[i][4]=v1.x; xr[i][5]=v1.y; xr[i][6]=v1.z; xr[i][7]=v1.w;
    }

    for (int l = 0; l < 2; l++) {
        // ---------------- q = LN(x) @ wq + bq -> sOut ----------------
        ln_rows(xr, sIn, ty, tx);
        __syncthreads();
        {
            u64 acc[4][8] = {};
            #pragma unroll
            for (int kc = 0; kc < 2; kc++) {
                loadW(sW, wq + (size_t)l*DI*DI, DI, kc*64, t);
                __syncthreads();
                gemm128(sIn, sW, acc, r0, tx, kc*64);
                __syncthreads();
            }
            float4 b0 = *(const float4*)(bq + l*DI + tx*8);
            float4 b1 = *(const float4*)(bq + l*DI + tx*8 + 4);
            float bb[8] = {b0.x,b0.y,b0.z,b0.w,b1.x,b1.y,b1.z,b1.w};
            #pragma unroll
            for (int i = 0; i < 4; i++)
                #pragma unroll
                for (int j = 0; j < 8; j++) {
                    float2 p = unpack2(acc[i][j]);
                    sOut[(r0+i)*132 + tx*8 + j] = p.x + p.y + bb[j];
                }
        }
        __syncthreads();

        // ---------------- attention: 1 head / thread ----------------
        {
            int dpix[9];
            calc_dpix(n0 + ap, dpix);
            float* qrow = sOut + ap*132 + hh*32;
            float4 q4[8];
            #pragma unroll
            for (int i4 = 0; i4 < 8; i4++)
                q4[i4] = *(const float4*)(qrow + i4*4);
            float lo[9];
            float m = -1e30f;
            #pragma unroll
            for (int kk = 0; kk < 9; kk++) {
                const float* kv = g_kvp + (size_t)dpix[kk]*KVP + l*256 + hh*32;
                float d = 0.f;
                #pragma unroll
                for (int i4 = 0; i4 < 8; i4++) {
                    float4 k4 = __ldg((const float4*)(kv + i4*4));
                    d += q4[i4].x*k4.x + q4[i4].y*k4.y
                       + q4[i4].z*k4.z + q4[i4].w*k4.w;
                }
                lo[kk] = d * 0.17677669529663687f;
                m = fmaxf(m, lo[kk]);
            }
            float ssum = 0.f;
            #pragma unroll
            for (int kk = 0; kk < 9; kk++) {
                lo[kk] = __expf(lo[kk] - m);
                ssum += lo[kk];
            }
            float inv = 1.f / ssum;
            float4 o4[8] = {};
            #pragma unroll
            for (int kk = 0; kk < 9; kk++) {
                float w = lo[kk] * inv;
                const float* vv = g_kvp + (size_t)dpix[kk]*KVP
                                  + l*256 + 128 + hh*32;
                #pragma unroll
                for (int i4 = 0; i4 < 8; i4++) {
                    float4 v = __ldg((const float4*)(vv + i4*4));
                    o4[i4].x += w*v.x; o4[i4].y += w*v.y;
                    o4[i4].z += w*v.z; o4[i4].w += w*v.w;
                }
            }
            #pragma unroll
            for (int i4 = 0; i4 < 8; i4++)
                *(float4*)(qrow + i4*4) = o4[i4];
        }
        __syncthreads();

        // ---------------- x += o @ wo + bo ----------------
        {
            u64 acc[4][8] = {};
            #pragma unroll
            for (int kc = 0; kc < 2; kc++) {
                loadW(sW, wo + (size_t)l*DI*DI, DI, kc*64, t);
                __syncthreads();
                gemm128(sOut, sW, acc, r0, tx, kc*64);
                __syncthreads();
            }
            float4 b0 = *(const float4*)(bo + l*DI + tx*8);
            float4 b1 = *(const float4*)(bo + l*DI + tx*8 + 4);
            float bb[8] = {b0.x,b0.y,b0.z,b0.w,b1.x,b1.y,b1.z,b1.w};
            #pragma unroll
            for (int i = 0; i < 4; i++)
                #pragma unroll
                for (int j = 0; j < 8; j++) {
                    float2 p = unpack2(acc[i][j]);
                    xr[i][j] += p.x + p.y + bb[j];
                }
        }
        __syncthreads();                    // before ln overwrites sIn

        // ---------------- MLP ----------------
        ln_rows(xr, sIn, ty, tx);
        __syncthreads();
        for (int hc = 0; hc < 4; hc++) {
            // h = gelu(LN(x) @ w1[:,hc*128..+127] + b1) -> sOut
            {
                u64 acc[4][8] = {};
                #pragma unroll
                for (int kc = 0; kc < 2; kc++) {
                    loadW(sW, w1 + (size_t)l*DI*512 + hc*128, 512, kc*64, t);
                    __syncthreads();
                    gemm128(sIn, sW, acc, r0, tx, kc*64);
                    __syncthreads();
                }
                float4 b0 = *(const float4*)(b1 + l*512 + hc*128 + tx*8);
                float4 b1v = *(const float4*)(b1 + l*512 + hc*128 + tx*8 + 4);
                float bb[8] = {b0.x,b0.y,b0.z,b0.w,b1v.x,b1v.y,b1v.z,b1v.w};
                #pragma unroll
                for (int i = 0; i < 4; i++)
                    #pragma unroll
                    for (int j = 0; j < 8; j++) {
                        float2 p = unpack2(acc[i][j]);
                        sOut[(r0+i)*132 + tx*8 + j] =
                            gelu_tanh(p.x + p.y + bb[j]);
                    }
            }
            __syncthreads();
            // x += h @ w2[hc*128..+127, :]
            {
                u64 acc[4][8] = {};
                #pragma unroll
                for (int kc = 0; kc < 2; kc++) {
                    loadW(sW, w2 + (size_t)l*512*DI + (size_t)hc*128*DI,
                          DI, kc*64, t);
                    __syncthreads();
                    gemm128(sOut, sW, acc, r0, tx, kc*64);
                    __syncthreads();
                }
                #pragma unroll
                for (int i = 0; i < 4; i++)
                    #pragma unroll
                    for (int j = 0; j < 8; j++) {
                        float2 p = unpack2(acc[i][j]);
                        xr[i][j] += p.x + p.y;
                    }
            }
            __syncthreads();
        }
        {
            float4 b0 = *(const float4*)(b2 + l*DI + tx*8);
            float4 b1v = *(const float4*)(b2 + l*DI + tx*8 + 4);
            float bb[8] = {b0.x,b0.y,b0.z,b0.w,b1v.x,b1v.y,b1v.z,b1v.w};
            #pragma unroll
            for (int i = 0; i < 4; i++)
                #pragma unroll
                for (int j = 0; j < 8; j++)
                    xr[i][j] += bb[j];
        }
    }

    // ---------------- final: xq = LN(x) @ wqf + bqf -> sOut ----------------
    ln_rows(xr, sIn, ty, tx);
    __syncthreads();
    {
        u64 acc[4][8] = {};
        #pragma unroll
        for (int kc = 0; kc < 2; kc++) {
            loadW(sW, wqf, DI, kc*64, t);
            __syncthreads();
            gemm128(sIn, sW, acc, r0, tx, kc*64);
            __syncthreads();
        }
        float4 b0 = *(const float4*)(bqf + tx*8);
        float4 b1v = *(const float4*)(bqf + tx*8 + 4);
        float bb[8] = {b0.x,b0.y,b0.z,b0.w,b1v.x,b1v.y,b1v.z,b1v.w};
        #pragma unroll
        for (int i = 0; i < 4; i++)
            #pragma unroll
            for (int j = 0; j < 8; j++) {
                float2 p = unpack2(acc[i][j]);
                sOut[(r0+i)*132 + tx*8 + j] = p.x + p.y + bb[j];
            }
    }
    __syncthreads();

    // ---------------- logits + 9-way softmax ----------------
    {
        int dpix[9];
        calc_dpix(n0 + ap, dpix);
        const float* qrow = sOut + ap*132 + hh*32;
        float4 q4[8];
        #pragma unroll
        for (int i4 = 0; i4 < 8; i4++)
            q4[i4] = *(const float4*)(qrow + i4*4);
        float lo[9];
        #pragma unroll
        for (int kk = 0; kk < 9; kk++) {
            const float* cp = g_kvp + (size_t)dpix[kk]*KVP + 512 + hh*32;
            float d = 0.f;
            #pragma unroll
            for (int i4 = 0; i4 < 8; i4++) {
                float4 c = __ldg((const float4*)(cp + i4*4));
                d += q4[i4].x*c.x + q4[i4].y*c.y
                   + q4[i4].z*c.z + q4[i4].w*c.w;
            }
            lo[kk] = d;
        }
        #pragma unroll
        for (int kk = 0; kk < 9; kk++) {
            lo[kk] += __shfl_xor_sync(0xffffffffu, lo[kk], 1, 4);
            lo[kk] += __shfl_xor_sync(0xffffffffu, lo[kk], 2, 4);
            lo[kk] *= 0.08838834764831845f;
        }
        float m = -1e30f;
        #pragma unroll
        for (int kk = 0; kk < 9; kk++) m = fmaxf(m, lo[kk]);
        float ssum = 0.f;
        #pragma unroll
        for (int kk = 0; kk < 9; kk++) {
            lo[kk] = __expf(lo[kk] - m);
            ssum += lo[kk];
        }
        float inv = 1.f / ssum;
        __syncthreads();                     // sIn free
        if (hh == 0) {
            #pragma unroll
            for (int kk = 0; kk < 9; kk++)
                sIn[kk*132 + ap] = lo[kk] * inv;
        }
    }
    __syncthreads();

    // ---------------- coalesced output write ----------------
    {
        int b = n0 / SPL, s0 = n0 % SPL;
        for (int f = t; f < 9*64; f += 256) {
            int kk = f >> 6, p = f & 63;
            out[(size_t)b*9*SPL + (size_t)kk*SPL + s0 + p] = sIn[kk*132 + p];
        }
    }
}

// ========================================================================
extern "C" void kernel_launch(void* const* d_in, const int* in_sizes, int n_in,
                              void* d_out, int out_size) {
    const float* feat_map    = (const float*)d_in[0];
    const float* feat_map_up = (const float*)d_in[1];
    const float* nc_w = (const float*)d_in[2];
    const float* nc_b = (const float*)d_in[3];
    const float* wq   = (const float*)d_in[4];
    const float* bq   = (const float*)d_in[5];
    const float* wkv  = (const float*)d_in[6];
    const float* bkv  = (const float*)d_in[7];
    const float* wo   = (const float*)d_in[8];
    const float* bo   = (const float*)d_in[9];
    const float* w1   = (const float*)d_in[10];
    const float* b1   = (const float*)d_in[11];
    const float* w2   = (const float*)d_in[12];
    const float* b2   = (const float*)d_in[13];
    const float* wqf  = (const float*)d_in[14];
    const float* bqf  = (const float*)d_in[15];
    const float* wcf  = (const float*)d_in[16];
    const float* bcf  = (const float*)d_in[17];
    float* out = (float*)d_out;

    cudaFuncSetAttribute(dgemm_kernel,
                         cudaFuncAttributeMaxDynamicSharedMemorySize, DGEMM_SMEM);
    cudaFuncSetAttribute(mega_kernel,
                         cudaFuncAttributeMaxDynamicSharedMemorySize, MEGA_SMEM);

    prep_kernel<<<3, 256>>>(nc_w, nc_b, wkv, bkv, wcf, bcf);
    trln_kernel<<<ND/32, 256>>>(feat_map);
    trx_kernel<<<NP/32, 256>>>(feat_map_up);
    dgemm_kernel<<<ND/64, 256, DGEMM_SMEM>>>();
    mega_kernel<<<NP/64, 256, MEGA_SMEM>>>(wq, bq, wo, bo, w1, b1, w2, b2,
                                           wqf, bqf, out);
}

// round 8
// speedup vs baseline: 3.0022x; 3.0022x over previous
#include <cuda_runtime.h>
#include <cuda_bf16.h>
#include <cstdint>

// ---------------- problem constants ----------------
#define DI   128
#define BATCH 2
#define HDm  64
#define WDm  96
#define HUm  128
#define WUm  192
#define SDL  (HDm*WDm)           // 6144
#define SPL  (HUm*WUm)           // 24576
#define ND   (BATCH*SDL)         // 12288
#define NP   (BATCH*SPL)         // 49152
#define KVP  640                 // kv0(256) | kv1(256) | ctxp(128)
#define NTILES 21                // wq,wo,w1x4,w2x4 (L0), same (L1), wqf
#define WTS  17408               // bf16 per weight tile (128 x 136)

typedef unsigned long long u64;

// ---------------- device scratch ----------------
__device__ float g_ctxln[ND*DI];
__device__ float g_x[NP*DI];
__device__ float g_kvp[ND*KVP];
__device__ float g_W[DI*KVP];
__device__ float g_bias[KVP];
__device__ __nv_bfloat16 g_Whi[NTILES*WTS];   // [k][n] tiles, stride 136 (hi)
__device__ __nv_bfloat16 g_Wlo[NTILES*WTS];   // (lo)

// ---------------- packed f32x2 helpers (dgemm) ----------------
__device__ __forceinline__ u64 fma2(u64 a, u64 b, u64 c) {
    u64 d;
    asm("fma.rn.f32x2 %0, %1, %2, %3;" : "=l"(d) : "l"(a), "l"(b), "l"(c));
    return d;
}
__device__ __forceinline__ float2 unpack2(u64 v) {
    float2 r;
    asm("mov.b64 {%0, %1}, %2;" : "=f"(r.x), "=f"(r.y) : "l"(v));
    return r;
}

// ---------------- HMMA helpers (plain PTX, sm_80+) ----------------
__device__ __forceinline__ uint32_t smem_u32(const void* p) {
    uint32_t a;
    asm("{ .reg .u64 t; cvta.to.shared.u64 t, %1; cvt.u32.u64 %0, t; }"
        : "=r"(a) : "l"(p));
    return a;
}
__device__ __forceinline__ void ldsm_x4(uint32_t r[4], uint32_t addr) {
    asm volatile("ldmatrix.sync.aligned.m8n8.x4.shared.b16 {%0,%1,%2,%3}, [%4];"
        : "=r"(r[0]), "=r"(r[1]), "=r"(r[2]), "=r"(r[3]) : "r"(addr));
}
__device__ __forceinline__ void ldsm_x2t(uint32_t r[2], uint32_t addr) {
    asm volatile("ldmatrix.sync.aligned.m8n8.x2.trans.shared.b16 {%0,%1}, [%2];"
        : "=r"(r[0]), "=r"(r[1]) : "r"(addr));
}
__device__ __forceinline__ void mma16816(float d[4], const uint32_t a[4],
                                         const uint32_t b[2]) {
    asm volatile(
        "mma.sync.aligned.m16n8k16.row.col.f32.bf16.bf16.f32 "
        "{%0,%1,%2,%3}, {%4,%5,%6,%7}, {%8,%9}, {%0,%1,%2,%3};"
        : "+f"(d[0]), "+f"(d[1]), "+f"(d[2]), "+f"(d[3])
        : "r"(a[0]), "r"(a[1]), "r"(a[2]), "r"(a[3]), "r"(b[0]), "r"(b[1]));
}

// ========================================================================
// K1: fold nc_w/nc_b into combined kv/ctxp weight
// ========================================================================
__global__ void prep_kernel(const float* __restrict__ nc_w,
                            const float* __restrict__ nc_b,
                            const float* __restrict__ wkv,
                            const float* __restrict__ bkv,
                            const float* __restrict__ wcf,
                            const float* __restrict__ bcf) {
    int j = blockIdx.x * blockDim.x + threadIdx.x;
    if (j >= KVP) return;
    if (j < 512) {
        int l  = j >> 8;
        int jj = j & 255;
        const float* w = wkv + (size_t)l * DI * 256;
        float bias = bkv[l*256 + jj];
        for (int c = 0; c < DI; c++) {
            float wv = w[c*256 + jj];
            g_W[c*KVP + j] = nc_w[l*DI + c] * wv;
            bias += nc_b[l*DI + c] * wv;
        }
        g_bias[j] = bias;
    } else {
        int jj = j - 512;
        for (int c = 0; c < DI; c++)
            g_W[c*KVP + j] = wcf[c*DI + jj];
        g_bias[j] = bcf[jj];
    }
}

// ========================================================================
// K1b: split transformer weights into bf16 hi/lo tiles, [k][n] stride 136
// ========================================================================
__global__ void prepw_kernel(const float* __restrict__ wq,
                             const float* __restrict__ wo,
                             const float* __restrict__ w1,
                             const float* __restrict__ w2,
                             const float* __restrict__ wqf) {
    int tile = blockIdx.x;
    int l = tile / 10, s = tile % 10;
    for (int idx = threadIdx.x; idx < DI*DI; idx += blockDim.x) {
        int k = idx >> 7, n = idx & 127;
        float w;
        if (tile == 20)      w = wqf[k*DI + n];
        else if (s == 0)     w = wq[l*DI*DI + k*DI + n];
        else if (s == 1)     w = wo[l*DI*DI + k*DI + n];
        else if (s < 6)      w = w1[l*DI*512 + k*512 + (s-2)*128 + n];
        else                 w = w2[l*512*DI + ((s-6)*128 + k)*DI + n];
        __nv_bfloat16 hi = __float2bfloat16(w);
        __nv_bfloat16 lo = __float2bfloat16(w - __bfloat162float(hi));
        g_Whi[(size_t)tile*WTS + k*136 + n] = hi;
        g_Wlo[(size_t)tile*WTS + k*136 + n] = lo;
    }
}

// ========================================================================
// K2: transpose feat_map + fused LayerNorm
// ========================================================================
__global__ void trln_kernel(const float* __restrict__ fm) {
    __shared__ float st[DI][33];
    int dp0 = blockIdx.x * 32;
    int b = dp0 / SDL, hw0 = dp0 % SDL;
    const float* src = fm + (size_t)b * DI * SDL + hw0;
    int t = threadIdx.x;
    #pragma unroll
    for (int i = 0; i < 16; i++) {
        int e = t + i*256;
        int c = e >> 5, p = e & 31;
        st[c][p] = src[(size_t)c*SDL + p];
    }
    __syncthreads();
    int p = t >> 3, g = t & 7;
    float s = 0.f, s2 = 0.f;
    #pragma unroll
    for (int i = 0; i < 16; i++) {
        float v = st[g*16 + i][p];
        s += v; s2 += v*v;
    }
    #pragma unroll
    for (int off = 4; off; off >>= 1) {
        s  += __shfl_xor_sync(0xffffffffu, s,  off, 8);
        s2 += __shfl_xor_sync(0xffffffffu, s2, off, 8);
    }
    float mu   = s * (1.f/128.f);
    float rstd = rsqrtf(s2*(1.f/128.f) - mu*mu + 1e-6f);
    float* dst = g_ctxln + (size_t)(dp0 + p) * DI;
    #pragma unroll
    for (int i = 0; i < 16; i++) {
        int c = g*16 + i;
        dst[c] = (st[c][p] - mu) * rstd;
    }
}

// ========================================================================
// K3: transpose feat_map_up -> x rows
// ========================================================================
__global__ void trx_kernel(const float* __restrict__ fmu) {
    __shared__ float st[DI][33];
    int n0 = blockIdx.x * 32;
    int b = n0 / SPL, s0 = n0 % SPL;
    const float* src = fmu + (size_t)b * DI * SPL + s0;
    int t = threadIdx.x;
    #pragma unroll
    for (int i = 0; i < 16; i++) {
        int e = t + i*256;
        int c = e >> 5, p = e & 31;
        st[c][p] = src[(size_t)c*SPL + p];
    }
    __syncthreads();
    int p = t >> 3, g = t & 7;
    float* dst = g_x + (size_t)(n0 + p) * DI;
    #pragma unroll
    for (int i = 0; i < 16; i++) {
        int c = g*16 + i;
        dst[c] = st[c][p];
    }
}

// ========================================================================
// K4: per-dpixel GEMM  g_kvp = g_ctxln @ g_W + g_bias  (f32x2 engine)
// ========================================================================
template<int K>
__device__ __forceinline__ void loadWf(float* sW, const float* __restrict__ src,
                                       int ldw, int t) {
    constexpr int TOT = (K/2) * 64;
    #pragma unroll
    for (int f = t; f < TOT; f += 256) {
        int k2 = f >> 6, j = f & 63;
        const float* p = src + (size_t)(2*k2) * ldw + j;
        float2 v;
        v.x = __ldg(p);
        v.y = __ldg(p + ldw);
        *(float2*)(sW + k2*132 + j*2) = v;
    }
}
template<int K2>
__device__ __forceinline__ void gemm_core(const float* __restrict__ sA,
                                          const float* __restrict__ sW,
                                          u64 acc[8][4], int r0, int tx) {
    #pragma unroll 4
    for (int k2 = 0; k2 < K2; k2++) {
        u64 a[8];
        #pragma unroll
        for (int i = 0; i < 8; i++)
            a[i] = *(const u64*)(sA + (r0 + i)*132 + k2*2);
        const float* wp = sW + k2*132 + tx*8;
        ulonglong2 w01 = *(const ulonglong2*)(wp);
        ulonglong2 w23 = *(const ulonglong2*)(wp + 4);
        u64 w[4] = {w01.x, w01.y, w23.x, w23.y};
        #pragma unroll
        for (int i = 0; i < 8; i++)
            #pragma unroll
            for (int j = 0; j < 4; j++)
                acc[i][j] = fma2(a[i], w[j], acc[i][j]);
    }
}

#define DGEMM_SMEM ((128*132 + 64*132) * 4)
__global__ void __launch_bounds__(256, 1) dgemm_kernel() {
    extern __shared__ float sm[];
    float* sIn = sm;
    float* sW  = sm + 128*132;
    int t = threadIdx.x;
    int tx = t & 15, ty = t >> 4;
    int n0 = blockIdx.x * 128;

    #pragma unroll
    for (int i = 0; i < 16; i++) {
        int f = t + i*256;
        int r = f >> 5, j4 = f & 31;
        *(float4*)(sIn + r*132 + j4*4) =
            *(const float4*)(g_ctxln + (size_t)(n0 + r)*DI + j4*4);
    }
    __syncthreads();

    for (int c = 0; c < 10; c++) {
        loadWf<128>(sW, g_W + c*64, KVP, t);
        __syncthreads();
        u64 acc[8][4] = {};
        gemm_core<64>(sIn, sW, acc, ty*8, tx);
        float4 b4 = *(const float4*)(g_bias + c*64 + tx*4);
        float bb[4] = {b4.x, b4.y, b4.z, b4.w};
        #pragma unroll
        for (int i = 0; i < 8; i++) {
            float4 o;
            float2 p0 = unpack2(acc[i][0]);
            float2 p1 = unpack2(acc[i][1]);
            float2 p2 = unpack2(acc[i][2]);
            float2 p3 = unpack2(acc[i][3]);
            o.x = p0.x + p0.y + bb[0];
            o.y = p1.x + p1.y + bb[1];
            o.z = p2.x + p2.y + bb[2];
            o.w = p3.x + p3.y + bb[3];
            *(float4*)(g_kvp + (size_t)(n0 + ty*8 + i)*KVP + c*64 + tx*4) = o;
        }
        __syncthreads();
    }
}

// ========================================================================
// K5: HMMA mega kernel — 128 pixels/block, 256 threads (8 warps)
// SMEM float offsets (tile = 128x136 bf16 = 8704 floats):
//   0      sAhi    8704
//   8704   sAlo    8704
//   17408  sBhi    8704     (qbuf[128][132]=16896 aliases sBhi+sBlo)
//   26112  sBlo    8704
//   34816  xf [128][132]    16896
//   51712  stats   512
// total 52224 floats = 208896 B  (< 227 KB)
// ========================================================================
#define MEGA_SMEM (52224*4)

__device__ __forceinline__ float gelu_tanh(float v) {
    float u = 0.7978845608028654f * (v + 0.044715f * v * v * v);
    u = fminf(fmaxf(u, -15.f), 15.f);
    float e = __expf(-2.f * u);
    float th = (1.f - e) / (1.f + e);
    return 0.5f * v * (1.f + th);
}

__device__ __forceinline__ void calc_dpix(int n, int dpix[9]) {
    int b  = n / SPL, s = n % SPL;
    int hu = s / WUm, wu = s % WUm;
    int hd = hu >> 1, wd = wu >> 1;
    #pragma unroll
    for (int i = 0; i < 3; i++)
        #pragma unroll
        for (int j = 0; j < 3; j++) {
            int hs = min(max(hd - 1 + i, 0), HDm - 1);
            int ws = min(max(wd - 1 + j, 0), WDm - 1);
            dpix[i*3 + j] = b*SDL + hs*WDm + ws;
        }
}

// write split-bf16 pair at (r, c..c+1), row stride 272 B
__device__ __forceinline__ void w2a(char* hi, char* lo, int r, int c,
                                    float v0, float v1) {
    __nv_bfloat162 h2 = __floats2bfloat162_rn(v0, v1);
    float l0 = v0 - __bfloat162float(h2.x);
    float l1 = v1 - __bfloat162float(h2.y);
    __nv_bfloat162 l2 = __floats2bfloat162_rn(l0, l1);
    int off = r*272 + c*2;
    *(uint32_t*)(hi + off) = *(uint32_t*)&h2;
    *(uint32_t*)(lo + off) = *(uint32_t*)&l2;
}

// warp GEMM: D[16x128] (warp w) = A[16x128] * B[128x128], split-bf16 3-term
__device__ __forceinline__ void wgemm(const char* Ahi, const char* Alo,
                                      const char* Bhi, const char* Blo,
                                      float acc[16][4], int w, int lane) {
    uint32_t aHi = smem_u32(Ahi), aLo = smem_u32(Alo);
    uint32_t bHi = smem_u32(Bhi), bLo = smem_u32(Blo);
    int mat = lane >> 3, r8 = lane & 7;
    uint32_t aRow = (uint32_t)((16*w + (mat & 1)*8 + r8) * 272
                               + ((mat >> 1) * 8) * 2);
    uint32_t bRow = (uint32_t)(((mat & 1)*8 + r8) * 272);
    #pragma unroll
    for (int ks = 0; ks < 8; ks++) {
        uint32_t Ah[4], Al[4];
        ldsm_x4(Ah, aHi + aRow + ks*32);
        ldsm_x4(Al, aLo + aRow + ks*32);
        uint32_t bko = bRow + (uint32_t)(ks*16*272);
        #pragma unroll
        for (int nt = 0; nt < 16; nt++) {
            uint32_t Bh[2], Bl[2];
            ldsm_x2t(Bh, bHi + bko + nt*16);
            ldsm_x2t(Bl, bLo + bko + nt*16);
            mma16816(acc[nt], Ah, Bh);
            mma16816(acc[nt], Ah, Bl);
            mma16816(acc[nt], Al, Bh);
        }
    }
}

// copy pre-split weight tile into B smem (both hi and lo)
__device__ __forceinline__ void loadW_tile(char* Bhi, char* Blo, int tile,
                                           int t) {
    const float4* sh = (const float4*)(g_Whi + (size_t)tile*WTS);
    const float4* sl = (const float4*)(g_Wlo + (size_t)tile*WTS);
    float4* dh = (float4*)Bhi;
    float4* dl = (float4*)Blo;
    #pragma unroll
    for (int i = 0; i < 9; i++) {
        int f = t + i*256;
        if (f < 2176) {
            dh[f] = __ldg(sh + f);
            dl[f] = __ldg(sl + f);
        }
    }
}

// LayerNorm xf rows -> split-bf16 A tile (internal syncthreads for stats)
__device__ __forceinline__ void ln_writeA(const float* xf, float* stats,
                                          char* Ahi, char* Alo, int r, int ch) {
    const float* xr = xf + r*132 + ch*64;
    float s = 0.f, s2 = 0.f;
    #pragma unroll
    for (int i = 0; i < 16; i++) {
        float4 v = *(const float4*)(xr + i*4);
        s  += (v.x + v.y) + (v.z + v.w);
        s2 += (v.x*v.x + v.y*v.y) + (v.z*v.z + v.w*v.w);
    }
    stats[ch*128 + r]       = s;
    stats[256 + ch*128 + r] = s2;
    __syncthreads();
    float mu  = (stats[r] + stats[128 + r]) * (1.f/128.f);
    float var = (stats[256 + r] + stats[384 + r]) * (1.f/128.f) - mu*mu;
    float rstd = rsqrtf(var + 1e-6f);
    #pragma unroll
    for (int j = 0; j < 64; j += 2) {
        float v0 = (xr[j]   - mu) * rstd;
        float v1 = (xr[j+1] - mu) * rstd;
        w2a(Ahi, Alo, r, ch*64 + j, v0, v1);
    }
}

__global__ void __launch_bounds__(256, 1) mega_kernel(
    const float* __restrict__ bq,  const float* __restrict__ bo,
    const float* __restrict__ b1,  const float* __restrict__ b2,
    const float* __restrict__ bqf, float* __restrict__ out)
{
    extern __shared__ __align__(16) float smf[];
    char*  sAhi = (char*)(smf);
    char*  sAlo = (char*)(smf + 8704);
    char*  sBhi = (char*)(smf + 17408);
    char*  sBlo = (char*)(smf + 26112);
    float* qbuf = smf + 17408;           // aliases sB (sequenced by syncs)
    float* xf   = smf + 34816;
    float* stats = smf + 51712;

    const int t    = threadIdx.x;
    const int lane = t & 31;
    const int w    = t >> 5;
    const int gid  = lane >> 2, tid = lane & 3;
    const int r0f  = 16*w + gid;          // fragment rows
    const int r1f  = r0f + 8;
    const int r    = t & 127;             // per-pixel row
    const int ch   = t >> 7;
    const int n0   = blockIdx.x * 128;

    float acc[16][4];

    // load x into xf (stride 132)
    #pragma unroll
    for (int i = 0; i < 8; i++) {
        int c0 = ch*64 + i*8;
        *(float4*)(xf + r*132 + c0) =
            *(const float4*)(g_x + (size_t)(n0 + r)*DI + c0);
        *(float4*)(xf + r*132 + c0 + 4) =
            *(const float4*)(g_x + (size_t)(n0 + r)*DI + c0 + 4);
    }
    __syncthreads();

    for (int l = 0; l < 2; l++) {
        int tb = l*10;

        // ===== q = LN(x) @ wq (bias added in attention) =====
        ln_writeA(xf, stats, sAhi, sAlo, r, ch);
        loadW_tile(sBhi, sBlo, tb + 0, t);
        __syncthreads();
        #pragma unroll
        for (int i = 0; i < 16; i++) { acc[i][0]=acc[i][1]=acc[i][2]=acc[i][3]=0.f; }
        wgemm(sAhi, sAlo, sBhi, sBlo, acc, w, lane);
        __syncthreads();                       // all LDSM done (sB free)
        #pragma unroll
        for (int nt = 0; nt < 16; nt++) {      // frag -> qbuf rows
            int c = 8*nt + 2*tid;
            *(float2*)(qbuf + r0f*132 + c) = make_float2(acc[nt][0], acc[nt][1]);
            *(float2*)(qbuf + r1f*132 + c) = make_float2(acc[nt][2], acc[nt][3]);
        }
        __syncthreads();

        // ===== attention (per pixel r, 2 heads per thread) =====
        {
            int dpix[9];
            calc_dpix(n0 + r, dpix);
            #pragma unroll
            for (int hh = 0; hh < 2; hh++) {
                int h = ch*2 + hh;
                const float* qrow = qbuf + r*132 + h*32;
                float q[32];
                #pragma unroll
                for (int j = 0; j < 32; j += 4) {
                    float4 v = *(const float4*)(qrow + j);
                    float4 b = *(const float4*)(bq + l*DI + h*32 + j);
                    q[j] = v.x + b.x; q[j+1] = v.y + b.y;
                    q[j+2] = v.z + b.z; q[j+3] = v.w + b.w;
                }
                float lo[9];
                float m = -1e30f;
                #pragma unroll
                for (int kk = 0; kk < 9; kk++) {
                    const float* kv = g_kvp + (size_t)dpix[kk]*KVP + l*256 + h*32;
                    float d = 0.f;
                    #pragma unroll
                    for (int i4 = 0; i4 < 8; i4++) {
                        float4 k4 = __ldg((const float4*)(kv + i4*4));
                        d += q[i4*4]*k4.x + q[i4*4+1]*k4.y
                           + q[i4*4+2]*k4.z + q[i4*4+3]*k4.w;
                    }
                    lo[kk] = d * 0.17677669529663687f;
                    m = fmaxf(m, lo[kk]);
                }
                float ssum = 0.f;
                #pragma unroll
                for (int kk = 0; kk < 9; kk++) {
                    lo[kk] = __expf(lo[kk] - m);
                    ssum += lo[kk];
                }
                float inv = 1.f / ssum;
                float o[32];
                #pragma unroll
                for (int j = 0; j < 32; j++) o[j] = 0.f;
                #pragma unroll
                for (int kk = 0; kk < 9; kk++) {
                    float wgt = lo[kk] * inv;
                    const float* vv = g_kvp + (size_t)dpix[kk]*KVP
                                      + l*256 + 128 + h*32;
                    #pragma unroll
                    for (int i4 = 0; i4 < 8; i4++) {
                        float4 v = __ldg((const float4*)(vv + i4*4));
                        o[i4*4]   += wgt*v.x; o[i4*4+1] += wgt*v.y;
                        o[i4*4+2] += wgt*v.z; o[i4*4+3] += wgt*v.w;
                    }
                }
                #pragma unroll
                for (int j = 0; j < 32; j += 2)
                    w2a(sAhi, sAlo, r, h*32 + j, o[j], o[j+1]);
            }
        }
        __syncthreads();                       // qbuf reads done

        // ===== x += o @ wo + bo =====
        loadW_tile(sBhi, sBlo, tb + 1, t);
        __syncthreads();
        #pragma unroll
        for (int i = 0; i < 16; i++) { acc[i][0]=acc[i][1]=acc[i][2]=acc[i][3]=0.f; }
        wgemm(sAhi, sAlo, sBhi, sBlo, acc, w, lane);
        #pragma unroll
        for (int nt = 0; nt < 16; nt++) {
            int c = 8*nt + 2*tid;
            float2 b = *(const float2*)(bo + l*DI + c);
            float2* p0 = (float2*)(xf + r0f*132 + c);
            float2* p1 = (float2*)(xf + r1f*132 + c);
            float2 v0 = *p0, v1 = *p1;
            v0.x += acc[nt][0] + b.x; v0.y += acc[nt][1] + b.y;
            v1.x += acc[nt][2] + b.x; v1.y += acc[nt][3] + b.y;
            *p0 = v0; *p1 = v1;
        }
        __syncthreads();

        // ===== MLP: 4 chunks, LN(x) recomputed per chunk; gelu(h) -> sA =====
        for (int hc = 0; hc < 4; hc++) {
            ln_writeA(xf, stats, sAhi, sAlo, r, ch);
            loadW_tile(sBhi, sBlo, tb + 2 + hc, t);
            __syncthreads();
            #pragma unroll
            for (int i = 0; i < 16; i++) { acc[i][0]=acc[i][1]=acc[i][2]=acc[i][3]=0.f; }
            wgemm(sAhi, sAlo, sBhi, sBlo, acc, w, lane);
            __syncthreads();                    // w1 LDSM done (sA free)
            #pragma unroll
            for (int nt = 0; nt < 16; nt++) {   // gelu -> sA (overwrite LN)
                int c = 8*nt + 2*tid;
                float2 b = *(const float2*)(b1 + l*512 + hc*128 + c);
                w2a(sAhi, sAlo, r0f, c,
                    gelu_tanh(acc[nt][0] + b.x), gelu_tanh(acc[nt][1] + b.y));
                w2a(sAhi, sAlo, r1f, c,
                    gelu_tanh(acc[nt][2] + b.x), gelu_tanh(acc[nt][3] + b.y));
            }
            loadW_tile(sBhi, sBlo, tb + 6 + hc, t);
            __syncthreads();                    // sA(h) + w2 ready
            #pragma unroll
            for (int i = 0; i < 16; i++) { acc[i][0]=acc[i][1]=acc[i][2]=acc[i][3]=0.f; }
            wgemm(sAhi, sAlo, sBhi, sBlo, acc, w, lane);
            #pragma unroll
            for (int nt = 0; nt < 16; nt++) {   // += into xf (+b2 on last)
                int c = 8*nt + 2*tid;
                float2 b = (hc == 3) ? *(const float2*)(b2 + l*DI + c)
                                     : make_float2(0.f, 0.f);
                float2* p0 = (float2*)(xf + r0f*132 + c);
                float2* p1 = (float2*)(xf + r1f*132 + c);
                float2 v0 = *p0, v1 = *p1;
                v0.x += acc[nt][0] + b.x; v0.y += acc[nt][1] + b.y;
                v1.x += acc[nt][2] + b.x; v1.y += acc[nt][3] + b.y;
                *p0 = v0; *p1 = v1;
            }
            __syncthreads();                    // w2 LDSM + xf adds done
        }
    }

    // ===== final: xq = LN(x) @ wqf + bqf =====
    ln_writeA(xf, stats, sAhi, sAlo, r, ch);
    loadW_tile(sBhi, sBlo, 20, t);
    __syncthreads();
    #pragma unroll
    for (int i = 0; i < 16; i++) { acc[i][0]=acc[i][1]=acc[i][2]=acc[i][3]=0.f; }
    wgemm(sAhi, sAlo, sBhi, sBlo, acc, w, lane);
    __syncthreads();
    #pragma unroll
    for (int nt = 0; nt < 16; nt++) {           // frag + bqf -> qbuf
        int c = 8*nt + 2*tid;
        float2 b = *(const float2*)(bqf + c);
        *(float2*)(qbuf + r0f*132 + c) = make_float2(acc[nt][0]+b.x, acc[nt][1]+b.y);
        *(float2*)(qbuf + r1f*132 + c) = make_float2(acc[nt][2]+b.x, acc[nt][3]+b.y);
    }
    __syncthreads();

    // ===== logits + 9-way softmax =====
    {
        int dpix[9];
        calc_dpix(n0 + r, dpix);
        float xq[64];
        #pragma unroll
        for (int j = 0; j < 64; j += 4) {
            float4 v = *(const float4*)(qbuf + r*132 + ch*64 + j);
            xq[j] = v.x; xq[j+1] = v.y; xq[j+2] = v.z; xq[j+3] = v.w;
        }
        float* part = smf;                      // reuse sAhi region
        #pragma unroll
        for (int kk = 0; kk < 9; kk++) {
            const float* cp = g_kvp + (size_t)dpix[kk]*KVP + 512 + ch*64;
            float d = 0.f;
            #pragma unroll
            for (int i4 = 0; i4 < 16; i4++) {
                float4 c4 = __ldg((const float4*)(cp + i4*4));
                d += xq[i4*4]*c4.x + xq[i4*4+1]*c4.y
                   + xq[i4*4+2]*c4.z + xq[i4*4+3]*c4.w;
            }
            part[(r*2 + ch)*9 + kk] = d;
        }
        __syncthreads();
        float* probs = smf + 8704;              // reuse sAlo region, [kk][132]
        if (ch == 0) {
            float lo[9];
            float m = -1e30f;
            #pragma unroll
            for (int kk = 0; kk < 9; kk++) {
                lo[kk] = (part[(r*2)*9 + kk] + part[(r*2+1)*9 + kk])
                         * 0.08838834764831845f;
                m = fmaxf(m, lo[kk]);
            }
            float ssum = 0.f;
            #pragma unroll
            for (int kk = 0; kk < 9; kk++) {
                lo[kk] = __expf(lo[kk] - m);
                ssum += lo[kk];
            }
            float inv = 1.f / ssum;
            #pragma unroll
            for (int kk = 0; kk < 9; kk++)
                probs[kk*132 + r] = lo[kk] * inv;
        }
        __syncthreads();
        int b = n0 / SPL, s0 = n0 % SPL;
        #pragma unroll
        for (int i = 0; i < 5; i++) {
            int f = t + i*256;
            if (f < 9*128) {
                int kk = f >> 7, p = f & 127;
                out[(size_t)b*9*SPL + (size_t)kk*SPL + s0 + p] =
                    probs[kk*132 + p];
            }
        }
    }
}

// ========================================================================
extern "C" void kernel_launch(void* const* d_in, const int* in_sizes, int n_in,
                              void* d_out, int out_size) {
    const float* feat_map    = (const float*)d_in[0];
    const float* feat_map_up = (const float*)d_in[1];
    const float* nc_w = (const float*)d_in[2];
    const float* nc_b = (const float*)d_in[3];
    const float* wq   = (const float*)d_in[4];
    const float* bq   = (const float*)d_in[5];
    const float* wkv  = (const float*)d_in[6];
    const float* bkv  = (const float*)d_in[7];
    const float* wo   = (const float*)d_in[8];
    const float* bo   = (const float*)d_in[9];
    const float* w1   = (const float*)d_in[10];
    const float* b1   = (const float*)d_in[11];
    const float* w2   = (const float*)d_in[12];
    const float* b2   = (const float*)d_in[13];
    const float* wqf  = (const float*)d_in[14];
    const float* bqf  = (const float*)d_in[15];
    const float* wcf  = (const float*)d_in[16];
    const float* bcf  = (const float*)d_in[17];
    float* out = (float*)d_out;

    cudaFuncSetAttribute(dgemm_kernel,
                         cudaFuncAttributeMaxDynamicSharedMemorySize, DGEMM_SMEM);
    cudaFuncSetAttribute(mega_kernel,
                         cudaFuncAttributeMaxDynamicSharedMemorySize, MEGA_SMEM);

    prep_kernel<<<3, 256>>>(nc_w, nc_b, wkv, bkv, wcf, bcf);
    prepw_kernel<<<NTILES, 256>>>(wq, wo, w1, w2, wqf);
    trln_kernel<<<ND/32, 256>>>(feat_map);
    trx_kernel<<<NP/32, 256>>>(feat_map_up);
    dgemm_kernel<<<ND/128, 256, DGEMM_SMEM>>>();
    mega_kernel<<<NP/128, 256, MEGA_SMEM>>>(bq, bo, b1, b2, bqf, out);
}

// round 9
// speedup vs baseline: 3.2897x; 1.0958x over previous
#include <cuda_runtime.h>
#include <cuda_bf16.h>
#include <cuda_fp16.h>
#include <cstdint>

// ---------------- problem constants ----------------
#define DI   128
#define BATCH 2
#define HDm  64
#define WDm  96
#define HUm  128
#define WUm  192
#define SDL  (HDm*WDm)           // 6144
#define SPL  (HUm*WUm)           // 24576
#define ND   (BATCH*SDL)         // 12288
#define NP   (BATCH*SPL)         // 49152
#define KVP  640                 // kv0(256) | kv1(256) | ctxp(128)
#define NTILES 26                // 0-20 transformer, 21-25 folded kv/ctxp
#define WTS  17408               // fp16 per weight tile (128 x 136)

typedef unsigned long long u64;

// ---------------- device scratch ----------------
__device__ float g_ctxln[ND*DI];
__device__ float g_x[NP*DI];
__device__ float g_kvp[ND*KVP];
__device__ float g_W[DI*KVP];
__device__ float g_bias[KVP];
__device__ __half g_Whi[NTILES*WTS];   // [k][n] tiles, stride 136 (hi)
__device__ __half g_Wlo[NTILES*WTS];   // (lo)

// ---------------- HMMA helpers (plain PTX, sm_80+) ----------------
__device__ __forceinline__ uint32_t smem_u32(const void* p) {
    uint32_t a;
    asm("{ .reg .u64 t; cvta.to.shared.u64 t, %1; cvt.u32.u64 %0, t; }"
        : "=r"(a) : "l"(p));
    return a;
}
__device__ __forceinline__ void ldsm_x4(uint32_t r[4], uint32_t addr) {
    asm volatile("ldmatrix.sync.aligned.m8n8.x4.shared.b16 {%0,%1,%2,%3}, [%4];"
        : "=r"(r[0]), "=r"(r[1]), "=r"(r[2]), "=r"(r[3]) : "r"(addr));
}
__device__ __forceinline__ void ldsm_x4t(uint32_t r[4], uint32_t addr) {
    asm volatile("ldmatrix.sync.aligned.m8n8.x4.trans.shared.b16 {%0,%1,%2,%3}, [%4];"
        : "=r"(r[0]), "=r"(r[1]), "=r"(r[2]), "=r"(r[3]) : "r"(addr));
}
__device__ __forceinline__ void mma16816(float d[4], const uint32_t a[4],
                                         const uint32_t b[2]) {
    asm volatile(
        "mma.sync.aligned.m16n8k16.row.col.f32.f16.f16.f32 "
        "{%0,%1,%2,%3}, {%4,%5,%6,%7}, {%8,%9}, {%0,%1,%2,%3};"
        : "+f"(d[0]), "+f"(d[1]), "+f"(d[2]), "+f"(d[3])
        : "r"(a[0]), "r"(a[1]), "r"(a[2]), "r"(a[3]), "r"(b[0]), "r"(b[1]));
}

// write split-fp16 pair at (r, c..c+1), row stride 272 B
__device__ __forceinline__ void w2a(char* hi, char* lo, int r, int c,
                                    float v0, float v1) {
    __half h0 = __float2half_rn(v0), h1 = __float2half_rn(v1);
    float l0 = v0 - __half2float(h0);
    float l1 = v1 - __half2float(h1);
    __half2 H = __halves2half2(h0, h1);
    __half2 L = __halves2half2(__float2half_rn(l0), __float2half_rn(l1));
    int off = r*272 + c*2;
    *(uint32_t*)(hi + off) = *(uint32_t*)&H;
    *(uint32_t*)(lo + off) = *(uint32_t*)&L;
}

// warp GEMM: D[16x128] (warp w) = A[16x128] * B[128x128], split-fp16 3-term
__device__ __forceinline__ void wgemm(const char* Ahi, const char* Alo,
                                      const char* Bhi, const char* Blo,
                                      float acc[16][4], int w, int lane) {
    uint32_t aHi = smem_u32(Ahi), aLo = smem_u32(Alo);
    uint32_t bHi = smem_u32(Bhi), bLo = smem_u32(Blo);
    int mat = lane >> 3, r8 = lane & 7;
    uint32_t aRow = (uint32_t)((16*w + (mat & 1)*8 + r8) * 272
                               + ((mat >> 1) * 8) * 2);
    uint32_t bAddr = (uint32_t)(((mat & 1)*8 + r8) * 272 + (mat >> 1) * 16);
    #pragma unroll
    for (int ks = 0; ks < 8; ks++) {
        uint32_t Ah[4], Al[4];
        ldsm_x4(Ah, aHi + aRow + ks*32);
        ldsm_x4(Al, aLo + aRow + ks*32);
        uint32_t bko = bAddr + (uint32_t)(ks*16*272);
        #pragma unroll
        for (int np = 0; np < 8; np++) {
            uint32_t Bh[4], Bl[4];
            ldsm_x4t(Bh, bHi + bko + np*32);
            ldsm_x4t(Bl, bLo + bko + np*32);
            mma16816(acc[2*np],   Ah, Bh);
            mma16816(acc[2*np],   Ah, Bl);
            mma16816(acc[2*np],   Al, Bh);
            mma16816(acc[2*np+1], Ah, Bh+2);
            mma16816(acc[2*np+1], Ah, Bl+2);
            mma16816(acc[2*np+1], Al, Bh+2);
        }
    }
}

// copy pre-split weight tile into B smem (both hi and lo)
__device__ __forceinline__ void loadW_tile(char* Bhi, char* Blo, int tile,
                                           int t) {
    const float4* sh = (const float4*)(g_Whi + (size_t)tile*WTS);
    const float4* sl = (const float4*)(g_Wlo + (size_t)tile*WTS);
    float4* dh = (float4*)Bhi;
    float4* dl = (float4*)Blo;
    #pragma unroll
    for (int i = 0; i < 9; i++) {
        int f = t + i*256;
        if (f < 2176) {
            dh[f] = __ldg(sh + f);
            dl[f] = __ldg(sl + f);
        }
    }
}

// ========================================================================
// K1: fold nc_w/nc_b into combined kv/ctxp weight
// ========================================================================
__global__ void prep_kernel(const float* __restrict__ nc_w,
                            const float* __restrict__ nc_b,
                            const float* __restrict__ wkv,
                            const float* __restrict__ bkv,
                            const float* __restrict__ wcf,
                            const float* __restrict__ bcf) {
    int j = blockIdx.x * blockDim.x + threadIdx.x;
    if (j >= KVP) return;
    if (j < 512) {
        int l  = j >> 8;
        int jj = j & 255;
        const float* w = wkv + (size_t)l * DI * 256;
        float bias = bkv[l*256 + jj];
        for (int c = 0; c < DI; c++) {
            float wv = w[c*256 + jj];
            g_W[c*KVP + j] = nc_w[l*DI + c] * wv;
            bias += nc_b[l*DI + c] * wv;
        }
        g_bias[j] = bias;
    } else {
        int jj = j - 512;
        for (int c = 0; c < DI; c++)
            g_W[c*KVP + j] = wcf[c*DI + jj];
        g_bias[j] = bcf[jj];
    }
}

// ========================================================================
// K1b: split weights into fp16 hi/lo tiles, [k][n] stride 136
//  tiles 0-20: transformer (wq,wo,w1x4,w2x4 per layer, wqf)
//  tiles 21-25: folded g_W (kv layer0/1 + ctxp) -- must run AFTER prep
// ========================================================================
__global__ void prepw_kernel(const float* __restrict__ wq,
                             const float* __restrict__ wo,
                             const float* __restrict__ w1,
                             const float* __restrict__ w2,
                             const float* __restrict__ wqf) {
    int tile = blockIdx.x;
    for (int idx = threadIdx.x; idx < DI*DI; idx += blockDim.x) {
        int k = idx >> 7, n = idx & 127;
        float w;
        if (tile >= 21)      w = g_W[k*KVP + (tile-21)*128 + n];
        else if (tile == 20) w = wqf[k*DI + n];
        else {
            int l = tile / 10, s = tile % 10;
            if (s == 0)      w = wq[l*DI*DI + k*DI + n];
            else if (s == 1) w = wo[l*DI*DI + k*DI + n];
            else if (s < 6)  w = w1[l*DI*512 + k*512 + (s-2)*128 + n];
            else             w = w2[l*512*DI + ((s-6)*128 + k)*DI + n];
        }
        __half hi = __float2half_rn(w);
        __half lo = __float2half_rn(w - __half2float(hi));
        g_Whi[(size_t)tile*WTS + k*136 + n] = hi;
        g_Wlo[(size_t)tile*WTS + k*136 + n] = lo;
    }
}

// ========================================================================
// K2: transpose feat_map + fused LayerNorm (coalesced writes)
// ========================================================================
__global__ void trln_kernel(const float* __restrict__ fm) {
    __shared__ float st[DI][33];
    __shared__ float mu_s[32], rs_s[32];
    int dp0 = blockIdx.x * 32;
    int b = dp0 / SDL, hw0 = dp0 % SDL;
    const float* src = fm + (size_t)b * DI * SDL + hw0;
    int t = threadIdx.x;
    #pragma unroll
    for (int i = 0; i < 16; i++) {
        int e = t + i*256;
        int c = e >> 5, p = e & 31;
        st[c][p] = src[(size_t)c*SDL + p];
    }
    __syncthreads();
    int p = t >> 3, g = t & 7;
    float s = 0.f, s2 = 0.f;
    #pragma unroll
    for (int i = 0; i < 16; i++) {
        float v = st[g*16 + i][p];
        s += v; s2 += v*v;
    }
    #pragma unroll
    for (int off = 4; off; off >>= 1) {
        s  += __shfl_xor_sync(0xffffffffu, s,  off, 8);
        s2 += __shfl_xor_sync(0xffffffffu, s2, off, 8);
    }
    if (g == 0) {
        float mu = s * (1.f/128.f);
        mu_s[p] = mu;
        rs_s[p] = rsqrtf(s2*(1.f/128.f) - mu*mu + 1e-6f);
    }
    __syncthreads();
    #pragma unroll
    for (int i = 0; i < 16; i++) {
        int f = t + i*256;
        int r = f >> 7, c = f & 127;
        g_ctxln[(size_t)(dp0 + r)*DI + c] = (st[c][r] - mu_s[r]) * rs_s[r];
    }
}

// ========================================================================
// K3: transpose feat_map_up -> x rows (coalesced writes)
// ========================================================================
__global__ void trx_kernel(const float* __restrict__ fmu) {
    __shared__ float st[DI][33];
    int n0 = blockIdx.x * 32;
    int b = n0 / SPL, s0 = n0 % SPL;
    const float* src = fmu + (size_t)b * DI * SPL + s0;
    int t = threadIdx.x;
    #pragma unroll
    for (int i = 0; i < 16; i++) {
        int e = t + i*256;
        int c = e >> 5, p = e & 31;
        st[c][p] = src[(size_t)c*SPL + p];
    }
    __syncthreads();
    #pragma unroll
    for (int i = 0; i < 16; i++) {
        int f = t + i*256;
        int r = f >> 7, c = f & 127;
        g_x[(size_t)(n0 + r)*DI + c] = st[c][r];
    }
}

// ========================================================================
// K4: per-dpixel GEMM  g_kvp = g_ctxln @ g_W + g_bias  (HMMA engine)
// ========================================================================
#define DGEMM_SMEM (4*8704*4)
__global__ void __launch_bounds__(256, 1) dgemm_kernel() {
    extern __shared__ __align__(16) float smf[];
    char* sAhi = (char*)(smf);
    char* sAlo = (char*)(smf + 8704);
    char* sBhi = (char*)(smf + 17408);
    char* sBlo = (char*)(smf + 26112);
    const int t = threadIdx.x, lane = t & 31, w = t >> 5;
    const int gid = lane >> 2, tid = lane & 3;
    const int r0f = 16*w + gid, r1f = r0f + 8;
    const int n0 = blockIdx.x * 128;

    for (int f = t; f < 8192; f += 256) {
        int r = f >> 6, c2 = f & 63;
        const float* src = g_ctxln + (size_t)(n0 + r)*DI + 2*c2;
        w2a(sAhi, sAlo, r, 2*c2, src[0], src[1]);
    }
    __syncthreads();

    float acc[16][4];
    for (int i = 0; i < 5; i++) {
        loadW_tile(sBhi, sBlo, 21 + i, t);
        __syncthreads();
        #pragma unroll
        for (int nt = 0; nt < 16; nt++) { acc[nt][0]=acc[nt][1]=acc[nt][2]=acc[nt][3]=0.f; }
        wgemm(sAhi, sAlo, sBhi, sBlo, acc, w, lane);
        #pragma unroll
        for (int nt = 0; nt < 16; nt++) {
            int c = 8*nt + 2*tid;
            float2 b = *(const float2*)(g_bias + i*128 + c);
            *(float2*)(g_kvp + (size_t)(n0+r0f)*KVP + i*128 + c) =
                make_float2(acc[nt][0]+b.x, acc[nt][1]+b.y);
            *(float2*)(g_kvp + (size_t)(n0+r1f)*KVP + i*128 + c) =
                make_float2(acc[nt][2]+b.x, acc[nt][3]+b.y);
        }
        __syncthreads();
    }
}

// ========================================================================
// K5: HMMA mega kernel — 128 pixels/block, 256 threads (8 warps)
// SMEM float offsets (tile = 128x136 fp16 = 8704 floats):
//   0      sAhi    8704
//   8704   sAlo    8704
//   17408  sBhi    8704     (qbuf[128][132]=16896 aliases sBhi+sBlo)
//   26112  sBlo    8704
//   34816  xf [128][132]    16896
//   51712  stats   512
// total 52224 floats = 208896 B
// ========================================================================
#define MEGA_SMEM (52224*4)

__device__ __forceinline__ float gelu_tanh(float v) {
    float u = 0.7978845608028654f * (v + 0.044715f * v * v * v);
    u = fminf(fmaxf(u, -15.f), 15.f);
    float e = __expf(-2.f * u);
    float th = (1.f - e) / (1.f + e);
    return 0.5f * v * (1.f + th);
}

__device__ __forceinline__ void calc_dpix(int n, int dpix[9]) {
    int b  = n / SPL, s = n % SPL;
    int hu = s / WUm, wu = s % WUm;
    int hd = hu >> 1, wd = wu >> 1;
    #pragma unroll
    for (int i = 0; i < 3; i++)
        #pragma unroll
        for (int j = 0; j < 3; j++) {
            int hs = min(max(hd - 1 + i, 0), HDm - 1);
            int ws = min(max(wd - 1 + j, 0), WDm - 1);
            dpix[i*3 + j] = b*SDL + hs*WDm + ws;
        }
}

// LayerNorm xf rows -> split-fp16 A tile (internal syncthreads for stats)
__device__ __forceinline__ void ln_writeA(const float* xf, float* stats,
                                          char* Ahi, char* Alo, int r, int ch) {
    const float* xr = xf + r*132 + ch*64;
    float s = 0.f, s2 = 0.f;
    #pragma unroll
    for (int i = 0; i < 16; i++) {
        float4 v = *(const float4*)(xr + i*4);
        s  += (v.x + v.y) + (v.z + v.w);
        s2 += (v.x*v.x + v.y*v.y) + (v.z*v.z + v.w*v.w);
    }
    stats[ch*128 + r]       = s;
    stats[256 + ch*128 + r] = s2;
    __syncthreads();
    float mu  = (stats[r] + stats[128 + r]) * (1.f/128.f);
    float var = (stats[256 + r] + stats[384 + r]) * (1.f/128.f) - mu*mu;
    float rstd = rsqrtf(var + 1e-6f);
    #pragma unroll
    for (int j = 0; j < 64; j += 2) {
        float v0 = (xr[j]   - mu) * rstd;
        float v1 = (xr[j+1] - mu) * rstd;
        w2a(Ahi, Alo, r, ch*64 + j, v0, v1);
    }
}

__global__ void __launch_bounds__(256, 1) mega_kernel(
    const float* __restrict__ bq,  const float* __restrict__ bo,
    const float* __restrict__ b1,  const float* __restrict__ b2,
    const float* __restrict__ bqf, float* __restrict__ out)
{
    extern __shared__ __align__(16) float smf[];
    char*  sAhi = (char*)(smf);
    char*  sAlo = (char*)(smf + 8704);
    char*  sBhi = (char*)(smf + 17408);
    char*  sBlo = (char*)(smf + 26112);
    float* qbuf = smf + 17408;           // aliases sB (sequenced by syncs)
    float* xf   = smf + 34816;
    float* stats = smf + 51712;

    const int t    = threadIdx.x;
    const int lane = t & 31;
    const int w    = t >> 5;
    const int gid  = lane >> 2, tid = lane & 3;
    const int r0f  = 16*w + gid;          // fragment rows
    const int r1f  = r0f + 8;
    const int r    = t & 127;             // per-pixel row
    const int ch   = t >> 7;
    const int n0   = blockIdx.x * 128;

    float acc[16][4];

    // load x into xf (stride 132)
    #pragma unroll
    for (int i = 0; i < 8; i++) {
        int c0 = ch*64 + i*8;
        *(float4*)(xf + r*132 + c0) =
            *(const float4*)(g_x + (size_t)(n0 + r)*DI + c0);
        *(float4*)(xf + r*132 + c0 + 4) =
            *(const float4*)(g_x + (size_t)(n0 + r)*DI + c0 + 4);
    }
    __syncthreads();

    for (int l = 0; l < 2; l++) {
        int tb = l*10;

        // ===== q = LN(x) @ wq (bias added in attention) =====
        ln_writeA(xf, stats, sAhi, sAlo, r, ch);
        loadW_tile(sBhi, sBlo, tb + 0, t);
        __syncthreads();
        #pragma unroll
        for (int i = 0; i < 16; i++) { acc[i][0]=acc[i][1]=acc[i][2]=acc[i][3]=0.f; }
        wgemm(sAhi, sAlo, sBhi, sBlo, acc, w, lane);
        __syncthreads();                       // all LDSM done (sB free)
        #pragma unroll
        for (int nt = 0; nt < 16; nt++) {      // frag -> qbuf rows
            int c = 8*nt + 2*tid;
            *(float2*)(qbuf + r0f*132 + c) = make_float2(acc[nt][0], acc[nt][1]);
            *(float2*)(qbuf + r1f*132 + c) = make_float2(acc[nt][2], acc[nt][3]);
        }
        __syncthreads();

        // ===== attention (per pixel r, 2 heads per thread) =====
        {
            int dpix[9];
            calc_dpix(n0 + r, dpix);
            #pragma unroll
            for (int hh = 0; hh < 2; hh++) {
                int h = ch*2 + hh;
                const float* qrow = qbuf + r*132 + h*32;
                float q[32];
                #pragma unroll
                for (int j = 0; j < 32; j += 4) {
                    float4 v = *(const float4*)(qrow + j);
                    float4 b = *(const float4*)(bq + l*DI + h*32 + j);
                    q[j] = v.x + b.x; q[j+1] = v.y + b.y;
                    q[j+2] = v.z + b.z; q[j+3] = v.w + b.w;
                }
                float lo[9];
                float m = -1e30f;
                #pragma unroll
                for (int kk = 0; kk < 9; kk++) {
                    const float* kv = g_kvp + (size_t)dpix[kk]*KVP + l*256 + h*32;
                    float d = 0.f;
                    #pragma unroll
                    for (int i4 = 0; i4 < 8; i4++) {
                        float4 k4 = __ldg((const float4*)(kv + i4*4));
                        d += q[i4*4]*k4.x + q[i4*4+1]*k4.y
                           + q[i4*4+2]*k4.z + q[i4*4+3]*k4.w;
                    }
                    lo[kk] = d * 0.17677669529663687f;
                    m = fmaxf(m, lo[kk]);
                }
                float ssum = 0.f;
                #pragma unroll
                for (int kk = 0; kk < 9; kk++) {
                    lo[kk] = __expf(lo[kk] - m);
                    ssum += lo[kk];
                }
                float inv = 1.f / ssum;
                float o[32];
                #pragma unroll
                for (int j = 0; j < 32; j++) o[j] = 0.f;
                #pragma unroll
                for (int kk = 0; kk < 9; kk++) {
                    float wgt = lo[kk] * inv;
                    const float* vv = g_kvp + (size_t)dpix[kk]*KVP
                                      + l*256 + 128 + h*32;
                    #pragma unroll
                    for (int i4 = 0; i4 < 8; i4++) {
                        float4 v = __ldg((const float4*)(vv + i4*4));
                        o[i4*4]   += wgt*v.x; o[i4*4+1] += wgt*v.y;
                        o[i4*4+2] += wgt*v.z; o[i4*4+3] += wgt*v.w;
                    }
                }
                #pragma unroll
                for (int j = 0; j < 32; j += 2)
                    w2a(sAhi, sAlo, r, h*32 + j, o[j], o[j+1]);
            }
        }
        __syncthreads();                       // qbuf reads done

        // ===== x += o @ wo + bo =====
        loadW_tile(sBhi, sBlo, tb + 1, t);
        __syncthreads();
        #pragma unroll
        for (int i = 0; i < 16; i++) { acc[i][0]=acc[i][1]=acc[i][2]=acc[i][3]=0.f; }
        wgemm(sAhi, sAlo, sBhi, sBlo, acc, w, lane);
        #pragma unroll
        for (int nt = 0; nt < 16; nt++) {
            int c = 8*nt + 2*tid;
            float2 b = *(const float2*)(bo + l*DI + c);
            float2* p0 = (float2*)(xf + r0f*132 + c);
            float2* p1 = (float2*)(xf + r1f*132 + c);
            float2 v0 = *p0, v1 = *p1;
            v0.x += acc[nt][0] + b.x; v0.y += acc[nt][1] + b.y;
            v1.x += acc[nt][2] + b.x; v1.y += acc[nt][3] + b.y;
            *p0 = v0; *p1 = v1;
        }
        __syncthreads();

        // ===== MLP: 4 chunks, LN(x) recomputed per chunk; gelu(h) -> sA =====
        for (int hc = 0; hc < 4; hc++) {
            ln_writeA(xf, stats, sAhi, sAlo, r, ch);
            loadW_tile(sBhi, sBlo, tb + 2 + hc, t);
            __syncthreads();
            #pragma unroll
            for (int i = 0; i < 16; i++) { acc[i][0]=acc[i][1]=acc[i][2]=acc[i][3]=0.f; }
            wgemm(sAhi, sAlo, sBhi, sBlo, acc, w, lane);
            __syncthreads();                    // w1 LDSM done (sA free)
            #pragma unroll
            for (int nt = 0; nt < 16; nt++) {   // gelu -> sA (overwrite LN)
                int c = 8*nt + 2*tid;
                float2 b = *(const float2*)(b1 + l*512 + hc*128 + c);
                w2a(sAhi, sAlo, r0f, c,
                    gelu_tanh(acc[nt][0] + b.x), gelu_tanh(acc[nt][1] + b.y));
                w2a(sAhi, sAlo, r1f, c,
                    gelu_tanh(acc[nt][2] + b.x), gelu_tanh(acc[nt][3] + b.y));
            }
            loadW_tile(sBhi, sBlo, tb + 6 + hc, t);
            __syncthreads();                    // sA(h) + w2 ready
            #pragma unroll
            for (int i = 0; i < 16; i++) { acc[i][0]=acc[i][1]=acc[i][2]=acc[i][3]=0.f; }
            wgemm(sAhi, sAlo, sBhi, sBlo, acc, w, lane);
            #pragma unroll
            for (int nt = 0; nt < 16; nt++) {   // += into xf (+b2 on last)
                int c = 8*nt + 2*tid;
                float2 b = (hc == 3) ? *(const float2*)(b2 + l*DI + c)
                                     : make_float2(0.f, 0.f);
                float2* p0 = (float2*)(xf + r0f*132 + c);
                float2* p1 = (float2*)(xf + r1f*132 + c);
                float2 v0 = *p0, v1 = *p1;
                v0.x += acc[nt][0] + b.x; v0.y += acc[nt][1] + b.y;
                v1.x += acc[nt][2] + b.x; v1.y += acc[nt][3] + b.y;
                *p0 = v0; *p1 = v1;
            }
            __syncthreads();                    // w2 LDSM + xf adds done
        }
    }

    // ===== final: xq = LN(x) @ wqf + bqf =====
    ln_writeA(xf, stats, sAhi, sAlo, r, ch);
    loadW_tile(sBhi, sBlo, 20, t);
    __syncthreads();
    #pragma unroll
    for (int i = 0; i < 16; i++) { acc[i][0]=acc[i][1]=acc[i][2]=acc[i][3]=0.f; }
    wgemm(sAhi, sAlo, sBhi, sBlo, acc, w, lane);
    __syncthreads();
    #pragma unroll
    for (int nt = 0; nt < 16; nt++) {           // frag + bqf -> qbuf
        int c = 8*nt + 2*tid;
        float2 b = *(const float2*)(bqf + c);
        *(float2*)(qbuf + r0f*132 + c) = make_float2(acc[nt][0]+b.x, acc[nt][1]+b.y);
        *(float2*)(qbuf + r1f*132 + c) = make_float2(acc[nt][2]+b.x, acc[nt][3]+b.y);
    }
    __syncthreads();

    // ===== logits + 9-way softmax =====
    {
        int dpix[9];
        calc_dpix(n0 + r, dpix);
        float xq[64];
        #pragma unroll
        for (int j = 0; j < 64; j += 4) {
            float4 v = *(const float4*)(qbuf + r*132 + ch*64 + j);
            xq[j] = v.x; xq[j+1] = v.y; xq[j+2] = v.z; xq[j+3] = v.w;
        }
        float* part = smf;                      // reuse sAhi region
        #pragma unroll
        for (int kk = 0; kk < 9; kk++) {
            const float* cp = g_kvp + (size_t)dpix[kk]*KVP + 512 + ch*64;
            float d = 0.f;
            #pragma unroll
            for (int i4 = 0; i4 < 16; i4++) {
                float4 c4 = __ldg((const float4*)(cp + i4*4));
                d += xq[i4*4]*c4.x + xq[i4*4+1]*c4.y
                   + xq[i4*4+2]*c4.z + xq[i4*4+3]*c4.w;
            }
            part[(r*2 + ch)*9 + kk] = d;
        }
        __syncthreads();
        float* probs = smf + 8704;              // reuse sAlo region, [kk][132]
        if (ch == 0) {
            float lo[9];
            float m = -1e30f;
            #pragma unroll
            for (int kk = 0; kk < 9; kk++) {
                lo[kk] = (part[(r*2)*9 + kk] + part[(r*2+1)*9 + kk])
                         * 0.08838834764831845f;
                m = fmaxf(m, lo[kk]);
            }
            float ssum = 0.f;
            #pragma unroll
            for (int kk = 0; kk < 9; kk++) {
                lo[kk] = __expf(lo[kk] - m);
                ssum += lo[kk];
            }
            float inv = 1.f / ssum;
            #pragma unroll
            for (int kk = 0; kk < 9; kk++)
                probs[kk*132 + r] = lo[kk] * inv;
        }
        __syncthreads();
        int b = n0 / SPL, s0 = n0 % SPL;
        #pragma unroll
        for (int i = 0; i < 5; i++) {
            int f = t + i*256;
            if (f < 9*128) {
                int kk = f >> 7, p = f & 127;
                out[(size_t)b*9*SPL + (size_t)kk*SPL + s0 + p] =
                    probs[kk*132 + p];
            }
        }
    }
}

// ========================================================================
extern "C" void kernel_launch(void* const* d_in, const int* in_sizes, int n_in,
                              void* d_out, int out_size) {
    const float* feat_map    = (const float*)d_in[0];
    const float* feat_map_up = (const float*)d_in[1];
    const float* nc_w = (const float*)d_in[2];
    const float* nc_b = (const float*)d_in[3];
    const float* wq   = (const float*)d_in[4];
    const float* bq   = (const float*)d_in[5];
    const float* wkv  = (const float*)d_in[6];
    const float* bkv  = (const float*)d_in[7];
    const float* wo   = (const float*)d_in[8];
    const float* bo   = (const float*)d_in[9];
    const float* w1   = (const float*)d_in[10];
    const float* b1   = (const float*)d_in[11];
    const float* w2   = (const float*)d_in[12];
    const float* b2   = (const float*)d_in[13];
    const float* wqf  = (const float*)d_in[14];
    const float* bqf  = (const float*)d_in[15];
    const float* wcf  = (const float*)d_in[16];
    const float* bcf  = (const float*)d_in[17];
    float* out = (float*)d_out;

    cudaFuncSetAttribute(dgemm_kernel,
                         cudaFuncAttributeMaxDynamicSharedMemorySize, DGEMM_SMEM);
    cudaFuncSetAttribute(mega_kernel,
                         cudaFuncAttributeMaxDynamicSharedMemorySize, MEGA_SMEM);

    prep_kernel<<<3, 256>>>(nc_w, nc_b, wkv, bkv, wcf, bcf);
    prepw_kernel<<<NTILES, 256>>>(wq, wo, w1, w2, wqf);
    trln_kernel<<<ND/32, 256>>>(feat_map);
    trx_kernel<<<NP/32, 256>>>(feat_map_up);
    dgemm_kernel<<<ND/128, 256, DGEMM_SMEM>>>();
    mega_kernel<<<NP/128, 256, MEGA_SMEM>>>(bq, bo, b1, b2, bqf, out);
}

// round 12
// speedup vs baseline: 3.5686x; 1.0848x over previous
#include <cuda_runtime.h>
#include <cuda_bf16.h>
#include <cuda_fp16.h>
#include <cstdint>

// ---------------- problem constants ----------------
#define DI   128
#define BATCH 2
#define HDm  64
#define WDm  96
#define HUm  128
#define WUm  192
#define SDL  (HDm*WDm)           // 6144
#define SPL  (HUm*WUm)           // 24576
#define ND   (BATCH*SDL)         // 12288
#define NP   (BATCH*SPL)         // 49152
#define KVP  640                 // kv0(256) | kv1(256) | ctxp(128)
#define NTILES 26                // 0-20 transformer, 21-25 folded kv/ctxp
#define WTS  17408               // fp16 per weight tile (128 x 136)

typedef unsigned long long u64;

// ---------------- device scratch ----------------
__device__ float g_ctxln[ND*DI];
__device__ float g_x[NP*DI];
__device__ float g_kvp[ND*KVP];
__device__ float g_W[DI*KVP];
__device__ float g_bias[KVP];
__device__ __half g_Whi[NTILES*WTS];   // [k][n] tiles, stride 136 (hi)
__device__ __half g_Wlo[NTILES*WTS];   // (lo)

// ---------------- HMMA helpers (plain PTX, sm_80+) ----------------
__device__ __forceinline__ uint32_t smem_u32(const void* p) {
    uint32_t a;
    asm("{ .reg .u64 t; cvta.to.shared.u64 t, %1; cvt.u32.u64 %0, t; }"
        : "=r"(a) : "l"(p));
    return a;
}
__device__ __forceinline__ void ldsm_x4(uint32_t r[4], uint32_t addr) {
    asm volatile("ldmatrix.sync.aligned.m8n8.x4.shared.b16 {%0,%1,%2,%3}, [%4];"
        : "=r"(r[0]), "=r"(r[1]), "=r"(r[2]), "=r"(r[3]) : "r"(addr));
}
__device__ __forceinline__ void ldsm_x4t(uint32_t r[4], uint32_t addr) {
    asm volatile("ldmatrix.sync.aligned.m8n8.x4.trans.shared.b16 {%0,%1,%2,%3}, [%4];"
        : "=r"(r[0]), "=r"(r[1]), "=r"(r[2]), "=r"(r[3]) : "r"(addr));
}
__device__ __forceinline__ void mma16816(float d[4], const uint32_t a[4],
                                         const uint32_t b[2]) {
    asm volatile(
        "mma.sync.aligned.m16n8k16.row.col.f32.f16.f16.f32 "
        "{%0,%1,%2,%3}, {%4,%5,%6,%7}, {%8,%9}, {%0,%1,%2,%3};"
        : "+f"(d[0]), "+f"(d[1]), "+f"(d[2]), "+f"(d[3])
        : "r"(a[0]), "r"(a[1]), "r"(a[2]), "r"(a[3]), "r"(b[0]), "r"(b[1]));
}

// write split-fp16 pair at (r, c..c+1), row stride 272 B
__device__ __forceinline__ void w2a(char* hi, char* lo, int r, int c,
                                    float v0, float v1) {
    __half h0 = __float2half_rn(v0), h1 = __float2half_rn(v1);
    float l0 = v0 - __half2float(h0);
    float l1 = v1 - __half2float(h1);
    __half2 H = __halves2half2(h0, h1);
    __half2 L = __halves2half2(__float2half_rn(l0), __float2half_rn(l1));
    int off = r*272 + c*2;
    *(uint32_t*)(hi + off) = *(uint32_t*)&H;
    *(uint32_t*)(lo + off) = *(uint32_t*)&L;
}

// ---- full-width warp GEMM (dgemm): D[16x128] = A[16x128]*B[128x128] ----
__device__ __forceinline__ void wgemm128(const char* Ahi, const char* Alo,
                                         const char* Bhi, const char* Blo,
                                         float acc[16][4], int w, int lane) {
    uint32_t aHi = smem_u32(Ahi), aLo = smem_u32(Alo);
    uint32_t bHi = smem_u32(Bhi), bLo = smem_u32(Blo);
    int mat = lane >> 3, r8 = lane & 7;
    uint32_t aRow = (uint32_t)((16*w + (mat & 1)*8 + r8) * 272
                               + ((mat >> 1) * 8) * 2);
    uint32_t bAddr = (uint32_t)(((mat & 1)*8 + r8) * 272 + (mat >> 1) * 16);
    #pragma unroll
    for (int ks = 0; ks < 8; ks++) {
        uint32_t Ah[4], Al[4];
        ldsm_x4(Ah, aHi + aRow + ks*32);
        ldsm_x4(Al, aLo + aRow + ks*32);
        uint32_t bko = bAddr + (uint32_t)(ks*16*272);
        #pragma unroll
        for (int np = 0; np < 8; np++) {
            uint32_t Bh[4], Bl[4];
            ldsm_x4t(Bh, bHi + bko + np*32);
            ldsm_x4t(Bl, bLo + bko + np*32);
            mma16816(acc[2*np],   Ah, Bh);
            mma16816(acc[2*np],   Ah, Bl);
            mma16816(acc[2*np],   Al, Bh);
            mma16816(acc[2*np+1], Ah, Bh+2);
            mma16816(acc[2*np+1], Ah, Bl+2);
            mma16816(acc[2*np+1], Al, Bh+2);
        }
    }
}

// ---- half-K warp GEMM (mega): D[16x64] += A[16, kh*64..+63]*Bhalf ----
__device__ __forceinline__ void wgemm_half(const char* Ahi, const char* Alo,
                                           const char* Bhi, const char* Blo,
                                           float acc[8][4], int mrow, int nh,
                                           int lane, int kh) {
    uint32_t aHi = smem_u32(Ahi), aLo = smem_u32(Alo);
    uint32_t bHi = smem_u32(Bhi), bLo = smem_u32(Blo);
    int mat = lane >> 3, r8 = lane & 7;
    uint32_t aRow = (uint32_t)((mrow + (mat & 1)*8 + r8) * 272
                               + (mat >> 1) * 16 + kh*128);
    uint32_t bBase = (uint32_t)(((mat & 1)*8 + r8) * 272
                                + (mat >> 1) * 16 + nh*128);
    #pragma unroll
    for (int ks = 0; ks < 4; ks++) {
        uint32_t Ah[4], Al[4];
        ldsm_x4(Ah, aHi + aRow + ks*32);
        ldsm_x4(Al, aLo + aRow + ks*32);
        uint32_t bko = bBase + (uint32_t)(ks*16*272);
        #pragma unroll
        for (int np = 0; np < 4; np++) {
            uint32_t Bh[4], Bl[4];
            ldsm_x4t(Bh, bHi + bko + np*32);
            ldsm_x4t(Bl, bLo + bko + np*32);
            mma16816(acc[2*np],   Ah, Bh);
            mma16816(acc[2*np],   Ah, Bl);
            mma16816(acc[2*np],   Al, Bh);
            mma16816(acc[2*np+1], Ah, Bh+2);
            mma16816(acc[2*np+1], Ah, Bl+2);
            mma16816(acc[2*np+1], Al, Bh+2);
        }
    }
}

// full tile copy (dgemm): 2176 float4 per buffer
__device__ __forceinline__ void loadW_tile(char* Bhi, char* Blo, int tile,
                                           int t) {
    const float4* sh = (const float4*)(g_Whi + (size_t)tile*WTS);
    const float4* sl = (const float4*)(g_Wlo + (size_t)tile*WTS);
    float4* dh = (float4*)Bhi;
    float4* dl = (float4*)Blo;
    #pragma unroll
    for (int i = 0; i < 9; i++) {
        int f = t + i*256;
        if (f < 2176) {
            dh[f] = __ldg(sh + f);
            dl[f] = __ldg(sl + f);
        }
    }
}

// half tile copy (mega): 64 k-rows x 136 halves = 1088 float4 per buffer
__device__ __forceinline__ void loadW_half(char* Bhi, char* Blo, int tile,
                                           int kh, int t) {
    const float4* sh = (const float4*)(g_Whi + (size_t)tile*WTS + kh*64*136);
    const float4* sl = (const float4*)(g_Wlo + (size_t)tile*WTS + kh*64*136);
    float4* dh = (float4*)Bhi;
    float4* dl = (float4*)Blo;
    #pragma unroll
    for (int i = 0; i < 5; i++) {
        int f = t + i*256;
        if (f < 1088) {
            dh[f] = __ldg(sh + f);
            dl[f] = __ldg(sl + f);
        }
    }
}

// ========================================================================
// K1: fold nc_w/nc_b into combined kv/ctxp weight
// ========================================================================
__global__ void prep_kernel(const float* __restrict__ nc_w,
                            const float* __restrict__ nc_b,
                            const float* __restrict__ wkv,
                            const float* __restrict__ bkv,
                            const float* __restrict__ wcf,
                            const float* __restrict__ bcf) {
    int j = blockIdx.x * blockDim.x + threadIdx.x;
    if (j >= KVP) return;
    if (j < 512) {
        int l  = j >> 8;
        int jj = j & 255;
        const float* w = wkv + (size_t)l * DI * 256;
        float bias = bkv[l*256 + jj];
        for (int c = 0; c < DI; c++) {
            float wv = w[c*256 + jj];
            g_W[c*KVP + j] = nc_w[l*DI + c] * wv;
            bias += nc_b[l*DI + c] * wv;
        }
        g_bias[j] = bias;
    } else {
        int jj = j - 512;
        for (int c = 0; c < DI; c++)
            g_W[c*KVP + j] = wcf[c*DI + jj];
        g_bias[j] = bcf[jj];
    }
}

// ========================================================================
// K1b: split weights into fp16 hi/lo tiles, [k][n] stride 136
// ========================================================================
__global__ void prepw_kernel(const float* __restrict__ wq,
                             const float* __restrict__ wo,
                             const float* __restrict__ w1,
                             const float* __restrict__ w2,
                             const float* __restrict__ wqf) {
    int tile = blockIdx.x;
    for (int idx = threadIdx.x; idx < DI*DI; idx += blockDim.x) {
        int k = idx >> 7, n = idx & 127;
        float w;
        if (tile >= 21)      w = g_W[k*KVP + (tile-21)*128 + n];
        else if (tile == 20) w = wqf[k*DI + n];
        else {
            int l = tile / 10, s = tile % 10;
            if (s == 0)      w = wq[l*DI*DI + k*DI + n];
            else if (s == 1) w = wo[l*DI*DI + k*DI + n];
            else if (s < 6)  w = w1[l*DI*512 + k*512 + (s-2)*128 + n];
            else             w = w2[l*512*DI + ((s-6)*128 + k)*DI + n];
        }
        __half hi = __float2half_rn(w);
        __half lo = __float2half_rn(w - __half2float(hi));
        g_Whi[(size_t)tile*WTS + k*136 + n] = hi;
        g_Wlo[(size_t)tile*WTS + k*136 + n] = lo;
    }
}

// ========================================================================
// K2: transpose feat_map + fused LayerNorm (coalesced writes)
// ========================================================================
__global__ void trln_kernel(const float* __restrict__ fm) {
    __shared__ float st[DI][33];
    __shared__ float mu_s[32], rs_s[32];
    int dp0 = blockIdx.x * 32;
    int b = dp0 / SDL, hw0 = dp0 % SDL;
    const float* src = fm + (size_t)b * DI * SDL + hw0;
    int t = threadIdx.x;
    #pragma unroll
    for (int i = 0; i < 16; i++) {
        int e = t + i*256;
        int c = e >> 5, p = e & 31;
        st[c][p] = src[(size_t)c*SDL + p];
    }
    __syncthreads();
    int p = t >> 3, g = t & 7;
    float s = 0.f, s2 = 0.f;
    #pragma unroll
    for (int i = 0; i < 16; i++) {
        float v = st[g*16 + i][p];
        s += v; s2 += v*v;
    }
    #pragma unroll
    for (int off = 4; off; off >>= 1) {
        s  += __shfl_xor_sync(0xffffffffu, s,  off, 8);
        s2 += __shfl_xor_sync(0xffffffffu, s2, off, 8);
    }
    if (g == 0) {
        float mu = s * (1.f/128.f);
        mu_s[p] = mu;
        rs_s[p] = rsqrtf(s2*(1.f/128.f) - mu*mu + 1e-6f);
    }
    __syncthreads();
    #pragma unroll
    for (int i = 0; i < 16; i++) {
        int f = t + i*256;
        int r = f >> 7, c = f & 127;
        g_ctxln[(size_t)(dp0 + r)*DI + c] = (st[c][r] - mu_s[r]) * rs_s[r];
    }
}

// ========================================================================
// K3: transpose feat_map_up -> x rows (coalesced writes)
// ========================================================================
__global__ void trx_kernel(const float* __restrict__ fmu) {
    __shared__ float st[DI][33];
    int n0 = blockIdx.x * 32;
    int b = n0 / SPL, s0 = n0 % SPL;
    const float* src = fmu + (size_t)b * DI * SPL + s0;
    int t = threadIdx.x;
    #pragma unroll
    for (int i = 0; i < 16; i++) {
        int e = t + i*256;
        int c = e >> 5, p = e & 31;
        st[c][p] = src[(size_t)c*SPL + p];
    }
    __syncthreads();
    #pragma unroll
    for (int i = 0; i < 16; i++) {
        int f = t + i*256;
        int r = f >> 7, c = f & 127;
        g_x[(size_t)(n0 + r)*DI + c] = st[c][r];
    }
}

// ========================================================================
// K4: per-dpixel GEMM  g_kvp = g_ctxln @ g_W + g_bias  (HMMA engine)
// ========================================================================
#define DGEMM_SMEM (4*8704*4)
__global__ void __launch_bounds__(256, 1) dgemm_kernel() {
    extern __shared__ __align__(16) float smf[];
    char* sAhi = (char*)(smf);
    char* sAlo = (char*)(smf + 8704);
    char* sBhi = (char*)(smf + 17408);
    char* sBlo = (char*)(smf + 26112);
    const int t = threadIdx.x, lane = t & 31, w = t >> 5;
    const int gid = lane >> 2, tid = lane & 3;
    const int r0f = 16*w + gid, r1f = r0f + 8;
    const int n0 = blockIdx.x * 128;

    for (int f = t; f < 8192; f += 256) {
        int r = f >> 6, c2 = f & 63;
        const float* src = g_ctxln + (size_t)(n0 + r)*DI + 2*c2;
        w2a(sAhi, sAlo, r, 2*c2, src[0], src[1]);
    }
    __syncthreads();

    float acc[16][4];
    for (int i = 0; i < 5; i++) {
        loadW_tile(sBhi, sBlo, 21 + i, t);
        __syncthreads();
        #pragma unroll
        for (int nt = 0; nt < 16; nt++) { acc[nt][0]=acc[nt][1]=acc[nt][2]=acc[nt][3]=0.f; }
        wgemm128(sAhi, sAlo, sBhi, sBlo, acc, w, lane);
        #pragma unroll
        for (int nt = 0; nt < 16; nt++) {
            int c = 8*nt + 2*tid;
            float2 b = *(const float2*)(g_bias + i*128 + c);
            *(float2*)(g_kvp + (size_t)(n0+r0f)*KVP + i*128 + c) =
                make_float2(acc[nt][0]+b.x, acc[nt][1]+b.y);
            *(float2*)(g_kvp + (size_t)(n0+r1f)*KVP + i*128 + c) =
                make_float2(acc[nt][2]+b.x, acc[nt][3]+b.y);
        }
        __syncthreads();
    }
}

// ========================================================================
// K5: HMMA mega kernel — 64 pixels/block, 256 threads, 2 CTAs/SM
// SMEM float offsets (A/B tile = 64x136 fp16 = 8704 halves = 4352 floats):
//   0      sAhi   4352      (probs[9][68] aliases in tail)
//   4352   sAlo   4352
//   8704   sBhi   4352      (qbuf[64][132]=8448 aliases sBhi+sBlo)
//   13056  sBlo   4352
//   17408  xf [64][132]  8448
// total 25856 floats = 103424 B  -> 2 CTAs/SM
// ========================================================================
#define MEGA_SMEM (25856*4)

__device__ __forceinline__ float gelu_tanh(float v) {
    float u = 0.7978845608028654f * (v + 0.044715f * v * v * v);
    u = fminf(fmaxf(u, -15.f), 15.f);
    float e = __expf(-2.f * u);
    float th = (1.f - e) / (1.f + e);
    return 0.5f * v * (1.f + th);
}

__device__ __forceinline__ void calc_dpix(int n, int dpix[9]) {
    int b  = n / SPL, s = n % SPL;
    int hu = s / WUm, wu = s % WUm;
    int hd = hu >> 1, wd = wu >> 1;
    #pragma unroll
    for (int i = 0; i < 3; i++)
        #pragma unroll
        for (int j = 0; j < 3; j++) {
            int hs = min(max(hd - 1 + i, 0), HDm - 1);
            int ws = min(max(wd - 1 + j, 0), WDm - 1);
            dpix[i*3 + j] = b*SDL + hs*WDm + ws;
        }
}

// LayerNorm: 4 lanes per row (pure shfl reduce), write split-fp16 A tile
__device__ __forceinline__ void ln_writeA(const float* xf,
                                          char* Ahi, char* Alo, int rr, int c4) {
    const float* xr = xf + rr*132 + c4*32;
    float s = 0.f, s2 = 0.f;
    #pragma unroll
    for (int i = 0; i < 8; i++) {
        float4 v = *(const float4*)(xr + i*4);
        s  += (v.x + v.y) + (v.z + v.w);
        s2 += (v.x*v.x + v.y*v.y) + (v.z*v.z + v.w*v.w);
    }
    s  += __shfl_xor_sync(0xffffffffu, s, 1, 4);
    s  += __shfl_xor_sync(0xffffffffu, s, 2, 4);
    s2 += __shfl_xor_sync(0xffffffffu, s2, 1, 4);
    s2 += __shfl_xor_sync(0xffffffffu, s2, 2, 4);
    float mu   = s * (1.f/128.f);
    float rstd = rsqrtf(s2*(1.f/128.f) - mu*mu + 1e-6f);
    #pragma unroll
    for (int j = 0; j < 32; j += 2) {
        float v0 = (xr[j]   - mu) * rstd;
        float v1 = (xr[j+1] - mu) * rstd;
        w2a(Ahi, Alo, rr, c4*32 + j, v0, v1);
    }
}

// run one full 128-K GEMM tile via two streamed halves (internal syncs)
__device__ __forceinline__ void gemm_tile2(const char* sAhi, const char* sAlo,
                                           char* sBhi, char* sBlo,
                                           float acc[8][4], int tile,
                                           int mrow, int nh, int lane, int t) {
    loadW_half(sBhi, sBlo, tile, 0, t);
    __syncthreads();
    wgemm_half(sAhi, sAlo, sBhi, sBlo, acc, mrow, nh, lane, 0);
    __syncthreads();
    loadW_half(sBhi, sBlo, tile, 1, t);
    __syncthreads();
    wgemm_half(sAhi, sAlo, sBhi, sBlo, acc, mrow, nh, lane, 1);
    __syncthreads();
}

#define ZACC() do { _Pragma("unroll") \
    for (int _i = 0; _i < 8; _i++) { acc[_i][0]=acc[_i][1]=acc[_i][2]=acc[_i][3]=0.f; } } while(0)

__global__ void __launch_bounds__(256, 2) mega_kernel(
    const float* __restrict__ bq,  const float* __restrict__ bo,
    const float* __restrict__ b1,  const float* __restrict__ b2,
    const float* __restrict__ bqf, float* __restrict__ out)
{
    extern __shared__ __align__(16) float smf[];
    char*  sAhi = (char*)(smf);
    char*  sAlo = (char*)(smf + 4352);
    char*  sBhi = (char*)(smf + 8704);
    char*  sBlo = (char*)(smf + 13056);
    float* qbuf = smf + 8704;            // aliases sB (sequenced by syncs)
    float* xf   = smf + 17408;           // 64 x 132

    const int t    = threadIdx.x;
    const int lane = t & 31;
    const int w    = t >> 5;
    const int gid  = lane >> 2, tid = lane & 3;
    const int mrow = (w & 3) * 16;        // warp row block
    const int nh   = w >> 2;              // warp col half
    const int r0f  = mrow + gid;          // fragment rows
    const int r1f  = r0f + 8;
    const int rr   = t >> 2;              // pixel row (LN / attention)
    const int c4   = t & 3;               // col chunk / head
    const int n0   = blockIdx.x * 64;

    float acc[8][4];

    // load x into xf (stride 132)
    {
        const float* src = g_x + (size_t)(n0 + rr)*DI + c4*32;
        float* dst = xf + rr*132 + c4*32;
        #pragma unroll
        for (int i = 0; i < 8; i++)
            *(float4*)(dst + i*4) = *(const float4*)(src + i*4);
    }
    __syncthreads();

    for (int l = 0; l < 2; l++) {
        int tb = l*10;

        // ===== q = LN(x) @ wq (bias added in attention) =====
        ln_writeA(xf, sAhi, sAlo, rr, c4);
        ZACC();
        gemm_tile2(sAhi, sAlo, sBhi, sBlo, acc, tb + 0, mrow, nh, lane, t);
        #pragma unroll
        for (int nt = 0; nt < 8; nt++) {       // frag -> qbuf (sB free)
            int c = nh*64 + 8*nt + 2*tid;
            *(float2*)(qbuf + r0f*132 + c) = make_float2(acc[nt][0], acc[nt][1]);
            *(float2*)(qbuf + r1f*132 + c) = make_float2(acc[nt][2], acc[nt][3]);
        }
        __syncthreads();

        // ===== attention (pixel rr, head c4) =====
        {
            int dpix[9];
            calc_dpix(n0 + rr, dpix);
            const float* qrow = qbuf + rr*132 + c4*32;
            float q[32];
            #pragma unroll
            for (int j = 0; j < 32; j += 4) {
                float4 v = *(const float4*)(qrow + j);
                float4 b = *(const float4*)(bq + l*DI + c4*32 + j);
                q[j] = v.x + b.x; q[j+1] = v.y + b.y;
                q[j+2] = v.z + b.z; q[j+3] = v.w + b.w;
            }
            float lo[9];
            float m = -1e30f;
            #pragma unroll
            for (int kk = 0; kk < 9; kk++) {
                const float* kv = g_kvp + (size_t)dpix[kk]*KVP + l*256 + c4*32;
                float d = 0.f;
                #pragma unroll
                for (int i4 = 0; i4 < 8; i4++) {
                    float4 k4 = __ldg((const float4*)(kv + i4*4));
                    d += q[i4*4]*k4.x + q[i4*4+1]*k4.y
                       + q[i4*4+2]*k4.z + q[i4*4+3]*k4.w;
                }
                lo[kk] = d * 0.17677669529663687f;
                m = fmaxf(m, lo[kk]);
            }
            float ssum = 0.f;
            #pragma unroll
            for (int kk = 0; kk < 9; kk++) {
                lo[kk] = __expf(lo[kk] - m);
                ssum += lo[kk];
            }
            float inv = 1.f / ssum;
            float o[32];
            #pragma unroll
            for (int j = 0; j < 32; j++) o[j] = 0.f;
            #pragma unroll
            for (int kk = 0; kk < 9; kk++) {
                float wgt = lo[kk] * inv;
                const float* vv = g_kvp + (size_t)dpix[kk]*KVP
                                  + l*256 + 128 + c4*32;
                #pragma unroll
                for (int i4 = 0; i4 < 8; i4++) {
                    float4 v = __ldg((const float4*)(vv + i4*4));
                    o[i4*4]   += wgt*v.x; o[i4*4+1] += wgt*v.y;
                    o[i4*4+2] += wgt*v.z; o[i4*4+3] += wgt*v.w;
                }
            }
            #pragma unroll
            for (int j = 0; j < 32; j += 2)
                w2a(sAhi, sAlo, rr, c4*32 + j, o[j], o[j+1]);
        }
        __syncthreads();                     // qbuf reads done (sB reusable)

        // ===== x += o @ wo + bo =====
        ZACC();
        gemm_tile2(sAhi, sAlo, sBhi, sBlo, acc, tb + 1, mrow, nh, lane, t);
        #pragma unroll
        for (int nt = 0; nt < 8; nt++) {
            int c = nh*64 + 8*nt + 2*tid;
            float2 b = *(const float2*)(bo + l*DI + c);
            float2* p0 = (float2*)(xf + r0f*132 + c);
            float2* p1 = (float2*)(xf + r1f*132 + c);
            float2 v0 = *p0, v1 = *p1;
            v0.x += acc[nt][0] + b.x; v0.y += acc[nt][1] + b.y;
            v1.x += acc[nt][2] + b.x; v1.y += acc[nt][3] + b.y;
            *p0 = v0; *p1 = v1;
        }
        __syncthreads();

        // ===== MLP: 4 chunks; gelu(h) -> sA =====
        for (int hc = 0; hc < 4; hc++) {
            ln_writeA(xf, sAhi, sAlo, rr, c4);
            ZACC();
            gemm_tile2(sAhi, sAlo, sBhi, sBlo, acc, tb + 2 + hc,
                       mrow, nh, lane, t);
            #pragma unroll
            for (int nt = 0; nt < 8; nt++) {    // gelu -> sA (overwrite LN)
                int c = nh*64 + 8*nt + 2*tid;
                float2 b = *(const float2*)(b1 + l*512 + hc*128 + c);
                w2a(sAhi, sAlo, r0f, c,
                    gelu_tanh(acc[nt][0] + b.x), gelu_tanh(acc[nt][1] + b.y));
                w2a(sAhi, sAlo, r1f, c,
                    gelu_tanh(acc[nt][2] + b.x), gelu_tanh(acc[nt][3] + b.y));
            }
            __syncthreads();
            ZACC();
            gemm_tile2(sAhi, sAlo, sBhi, sBlo, acc, tb + 6 + hc,
                       mrow, nh, lane, t);
            #pragma unroll
            for (int nt = 0; nt < 8; nt++) {    // += into xf (+b2 on last)
                int c = nh*64 + 8*nt + 2*tid;
                float2 b = (hc == 3) ? *(const float2*)(b2 + l*DI + c)
                                     : make_float2(0.f, 0.f);
                float2* p0 = (float2*)(xf + r0f*132 + c);
                float2* p1 = (float2*)(xf + r1f*132 + c);
                float2 v0 = *p0, v1 = *p1;
                v0.x += acc[nt][0] + b.x; v0.y += acc[nt][1] + b.y;
                v1.x += acc[nt][2] + b.x; v1.y += acc[nt][3] + b.y;
                *p0 = v0; *p1 = v1;
            }
            __syncthreads();
        }
    }

    // ===== final: xq = LN(x) @ wqf + bqf -> qbuf =====
    ln_writeA(xf, sAhi, sAlo, rr, c4);
    ZACC();
    gemm_tile2(sAhi, sAlo, sBhi, sBlo, acc, 20, mrow, nh, lane, t);
    #pragma unroll
    for (int nt = 0; nt < 8; nt++) {
        int c = nh*64 + 8*nt + 2*tid;
        float2 b = *(const float2*)(bqf + c);
        *(float2*)(qbuf + r0f*132 + c) = make_float2(acc[nt][0]+b.x, acc[nt][1]+b.y);
        *(float2*)(qbuf + r1f*132 + c) = make_float2(acc[nt][2]+b.x, acc[nt][3]+b.y);
    }
    __syncthreads();

    // ===== logits + 9-way softmax (shfl-reduced over 4 lanes) =====
    {
        int dpix[9];
        calc_dpix(n0 + rr, dpix);
        float xq[32];
        const float* qrow = qbuf + rr*132 + c4*32;
        #pragma unroll
        for (int j = 0; j < 32; j += 4) {
            float4 v = *(const float4*)(qrow + j);
            xq[j] = v.x; xq[j+1] = v.y; xq[j+2] = v.z; xq[j+3] = v.w;
        }
        float lo[9];
        #pragma unroll
        for (int kk = 0; kk < 9; kk++) {
            const float* cp = g_kvp + (size_t)dpix[kk]*KVP + 512 + c4*32;
            float d = 0.f;
            #pragma unroll
            for (int i4 = 0; i4 < 8; i4++) {
                float4 c4v = __ldg((const float4*)(cp + i4*4));
                d += xq[i4*4]*c4v.x + xq[i4*4+1]*c4v.y
                   + xq[i4*4+2]*c4v.z + xq[i4*4+3]*c4v.w;
            }
            lo[kk] = d;
        }
        #pragma unroll
        for (int kk = 0; kk < 9; kk++) {
            lo[kk] += __shfl_xor_sync(0xffffffffu, lo[kk], 1, 4);
            lo[kk] += __shfl_xor_sync(0xffffffffu, lo[kk], 2, 4);
            lo[kk] *= 0.08838834764831845f;
        }
        float m = -1e30f;
        #pragma unroll
        for (int kk = 0; kk < 9; kk++) m = fmaxf(m, lo[kk]);
        float ssum = 0.f;
        #pragma unroll
        for (int kk = 0; kk < 9; kk++) {
            lo[kk] = __expf(lo[kk] - m);
            ssum += lo[kk];
        }
        float inv = 1.f / ssum;
        float* probs = smf;                  // reuse sA region, [kk][68]
        if (c4 == 0) {
            #pragma unroll
            for (int kk = 0; kk < 9; kk++)
                probs[kk*68 + rr] = lo[kk] * inv;
        }
        __syncthreads();
        int b = n0 / SPL, s0 = n0 % SPL;
        for (int f = t; f < 9*64; f += 256) {
            int kk = f >> 6, p = f & 63;
            out[(size_t)b*9*SPL + (size_t)kk*SPL + s0 + p] = probs[kk*68 + p];
        }
    }
}

// ========================================================================
extern "C" void kernel_launch(void* const* d_in, const int* in_sizes, int n_in,
                              void* d_out, int out_size) {
    const float* feat_map    = (const float*)d_in[0];
    const float* feat_map_up = (const float*)d_in[1];
    const float* nc_w = (const float*)d_in[2];
    const float* nc_b = (const float*)d_in[3];
    const float* wq   = (const float*)d_in[4];
    const float* bq   = (const float*)d_in[5];
    const float* wkv  = (const float*)d_in[6];
    const float* bkv  = (const float*)d_in[7];
    const float* wo   = (const float*)d_in[8];
    const float* bo   = (const float*)d_in[9];
    const float* w1   = (const float*)d_in[10];
    const float* b1   = (const float*)d_in[11];
    const float* w2   = (const float*)d_in[12];
    const float* b2   = (const float*)d_in[13];
    const float* wqf  = (const float*)d_in[14];
    const float* bqf  = (const float*)d_in[15];
    const float* wcf  = (const float*)d_in[16];
    const float* bcf  = (const float*)d_in[17];
    float* out = (float*)d_out;

    cudaFuncSetAttribute(dgemm_kernel,
                         cudaFuncAttributeMaxDynamicSharedMemorySize, DGEMM_SMEM);
    cudaFuncSetAttribute(mega_kernel,
                         cudaFuncAttributeMaxDynamicSharedMemorySize, MEGA_SMEM);

    prep_kernel<<<3, 256>>>(nc_w, nc_b, wkv, bkv, wcf, bcf);
    prepw_kernel<<<NTILES, 256>>>(wq, wo, w1, w2, wqf);
    trln_kernel<<<ND/32, 256>>>(feat_map);
    trx_kernel<<<NP/32, 256>>>(feat_map_up);
    dgemm_kernel<<<ND/128, 256, DGEMM_SMEM>>>();
    mega_kernel<<<NP/64, 256, MEGA_SMEM>>>(bq, bo, b1, b2, bqf, out);
}

// round 13
// speedup vs baseline: 3.5949x; 1.0074x over previous
#include <cuda_runtime.h>
#include <cuda_bf16.h>
#include <cuda_fp16.h>
#include <cstdint>

// ---------------- problem constants ----------------
#define DI   128
#define BATCH 2
#define HDm  64
#define WDm  96
#define HUm  128
#define WUm  192
#define SDL  (HDm*WDm)           // 6144
#define SPL  (HUm*WUm)           // 24576
#define ND   (BATCH*SDL)         // 12288
#define NP   (BATCH*SPL)         // 49152
#define KVP  640                 // kv0(256) | kv1(256) | ctxp(128)
#define NTILES 26                // 0-20 transformer, 21-25 folded kv/ctxp
#define WTS  17408               // fp16 per weight tile (128 x 136)

typedef unsigned long long u64;

// ---------------- device scratch ----------------
__device__ float g_ctxln[ND*DI];
__device__ float g_x[NP*DI];
__device__ float g_kvp[ND*KVP];
__device__ float g_W[DI*KVP];
__device__ float g_bias[KVP];
__device__ __half g_Whi[NTILES*WTS];   // [k][n] tiles, stride 136 (hi)
__device__ __half g_Wlo[NTILES*WTS];   // (lo)

// ---------------- HMMA helpers (plain PTX, sm_80+) ----------------
__device__ __forceinline__ uint32_t smem_u32(const void* p) {
    uint32_t a;
    asm("{ .reg .u64 t; cvta.to.shared.u64 t, %1; cvt.u32.u64 %0, t; }"
        : "=r"(a) : "l"(p));
    return a;
}
__device__ __forceinline__ void ldsm_x4(uint32_t r[4], uint32_t addr) {
    asm volatile("ldmatrix.sync.aligned.m8n8.x4.shared.b16 {%0,%1,%2,%3}, [%4];"
        : "=r"(r[0]), "=r"(r[1]), "=r"(r[2]), "=r"(r[3]) : "r"(addr));
}
__device__ __forceinline__ void ldsm_x4t(uint32_t r[4], uint32_t addr) {
    asm volatile("ldmatrix.sync.aligned.m8n8.x4.trans.shared.b16 {%0,%1,%2,%3}, [%4];"
        : "=r"(r[0]), "=r"(r[1]), "=r"(r[2]), "=r"(r[3]) : "r"(addr));
}
__device__ __forceinline__ void mma16816(float d[4], const uint32_t a[4],
                                         const uint32_t b[2]) {
    asm volatile(
        "mma.sync.aligned.m16n8k16.row.col.f32.f16.f16.f32 "
        "{%0,%1,%2,%3}, {%4,%5,%6,%7}, {%8,%9}, {%0,%1,%2,%3};"
        : "+f"(d[0]), "+f"(d[1]), "+f"(d[2]), "+f"(d[3])
        : "r"(a[0]), "r"(a[1]), "r"(a[2]), "r"(a[3]), "r"(b[0]), "r"(b[1]));
}

// write split-fp16 pair at (r, c..c+1), row stride 272 B
__device__ __forceinline__ void w2a(char* hi, char* lo, int r, int c,
                                    float v0, float v1) {
    __half h0 = __float2half_rn(v0), h1 = __float2half_rn(v1);
    float l0 = v0 - __half2float(h0);
    float l1 = v1 - __half2float(h1);
    __half2 H = __halves2half2(h0, h1);
    __half2 L = __halves2half2(__float2half_rn(l0), __float2half_rn(l1));
    int off = r*272 + c*2;
    *(uint32_t*)(hi + off) = *(uint32_t*)&H;
    *(uint32_t*)(lo + off) = *(uint32_t*)&L;
}

// ---- half-K warp GEMM: D[16x64] += A[16, kh*64..+63] * Bhalf ----
__device__ __forceinline__ void wgemm_half(const char* Ahi, const char* Alo,
                                           const char* Bhi, const char* Blo,
                                           float acc[8][4], int mrow, int nh,
                                           int lane, int kh) {
    uint32_t aHi = smem_u32(Ahi), aLo = smem_u32(Alo);
    uint32_t bHi = smem_u32(Bhi), bLo = smem_u32(Blo);
    int mat = lane >> 3, r8 = lane & 7;
    uint32_t aRow = (uint32_t)((mrow + (mat & 1)*8 + r8) * 272
                               + (mat >> 1) * 16 + kh*128);
    uint32_t bBase = (uint32_t)(((mat & 1)*8 + r8) * 272
                                + (mat >> 1) * 16 + nh*128);
    #pragma unroll
    for (int ks = 0; ks < 4; ks++) {
        uint32_t Ah[4], Al[4];
        ldsm_x4(Ah, aHi + aRow + ks*32);
        ldsm_x4(Al, aLo + aRow + ks*32);
        uint32_t bko = bBase + (uint32_t)(ks*16*272);
        #pragma unroll
        for (int np = 0; np < 4; np++) {
            uint32_t Bh[4], Bl[4];
            ldsm_x4t(Bh, bHi + bko + np*32);
            ldsm_x4t(Bl, bLo + bko + np*32);
            mma16816(acc[2*np],   Ah, Bh);
            mma16816(acc[2*np],   Ah, Bl);
            mma16816(acc[2*np],   Al, Bh);
            mma16816(acc[2*np+1], Ah, Bh+2);
            mma16816(acc[2*np+1], Ah, Bl+2);
            mma16816(acc[2*np+1], Al, Bh+2);
        }
    }
}

// ---- register prefetch of one B half (64 k-rows = 1088 float4/buffer) ----
struct PF { float4 h[5], l[5]; };

__device__ __forceinline__ void pf_load(PF& pf, int tile, int kh, int t) {
    const float4* sh = (const float4*)(g_Whi + (size_t)tile*WTS + kh*64*136);
    const float4* sl = (const float4*)(g_Wlo + (size_t)tile*WTS + kh*64*136);
    #pragma unroll
    for (int i = 0; i < 5; i++) {
        int f = t + i*256;
        if (f < 1088) {
            pf.h[i] = __ldg(sh + f);
            pf.l[i] = __ldg(sl + f);
        }
    }
}
__device__ __forceinline__ void pf_store(const PF& pf, char* Bhi, char* Blo,
                                         int t) {
    float4* dh = (float4*)Bhi;
    float4* dl = (float4*)Blo;
    #pragma unroll
    for (int i = 0; i < 5; i++) {
        int f = t + i*256;
        if (f < 1088) {
            dh[f] = pf.h[i];
            dl[f] = pf.l[i];
        }
    }
}

// pipelined 128-K GEMM tile: pf holds half0 of `tile` on entry;
// on exit pf holds half0 of `next_tile` (if >=0). Internal syncs.
__device__ __forceinline__ void gemm_tile_pf(PF& pf,
                                             const char* sAhi, const char* sAlo,
                                             char* sBhi, char* sBlo,
                                             float acc[8][4], int tile,
                                             int next_tile,
                                             int mrow, int nh, int lane, int t) {
    pf_store(pf, sBhi, sBlo, t);
    __syncthreads();
    pf_load(pf, tile, 1, t);               // LDG hidden behind MMA half0
    wgemm_half(sAhi, sAlo, sBhi, sBlo, acc, mrow, nh, lane, 0);
    __syncthreads();
    pf_store(pf, sBhi, sBlo, t);
    __syncthreads();
    if (next_tile >= 0) pf_load(pf, next_tile, 0, t);  // hidden behind MMA h1+
    wgemm_half(sAhi, sAlo, sBhi, sBlo, acc, mrow, nh, lane, 1);
    __syncthreads();
}

// ========================================================================
// K1: fold nc_w/nc_b into combined kv/ctxp weight
// ========================================================================
__global__ void prep_kernel(const float* __restrict__ nc_w,
                            const float* __restrict__ nc_b,
                            const float* __restrict__ wkv,
                            const float* __restrict__ bkv,
                            const float* __restrict__ wcf,
                            const float* __restrict__ bcf) {
    int j = blockIdx.x * blockDim.x + threadIdx.x;
    if (j >= KVP) return;
    if (j < 512) {
        int l  = j >> 8;
        int jj = j & 255;
        const float* w = wkv + (size_t)l * DI * 256;
        float bias = bkv[l*256 + jj];
        for (int c = 0; c < DI; c++) {
            float wv = w[c*256 + jj];
            g_W[c*KVP + j] = nc_w[l*DI + c] * wv;
            bias += nc_b[l*DI + c] * wv;
        }
        g_bias[j] = bias;
    } else {
        int jj = j - 512;
        for (int c = 0; c < DI; c++)
            g_W[c*KVP + j] = wcf[c*DI + jj];
        g_bias[j] = bcf[jj];
    }
}

// ========================================================================
// K1b: split weights into fp16 hi/lo tiles, [k][n] stride 136
// ========================================================================
__global__ void prepw_kernel(const float* __restrict__ wq,
                             const float* __restrict__ wo,
                             const float* __restrict__ w1,
                             const float* __restrict__ w2,
                             const float* __restrict__ wqf) {
    int tile = blockIdx.x;
    for (int idx = threadIdx.x; idx < DI*DI; idx += blockDim.x) {
        int k = idx >> 7, n = idx & 127;
        float w;
        if (tile >= 21)      w = g_W[k*KVP + (tile-21)*128 + n];
        else if (tile == 20) w = wqf[k*DI + n];
        else {
            int l = tile / 10, s = tile % 10;
            if (s == 0)      w = wq[l*DI*DI + k*DI + n];
            else if (s == 1) w = wo[l*DI*DI + k*DI + n];
            else if (s < 6)  w = w1[l*DI*512 + k*512 + (s-2)*128 + n];
            else             w = w2[l*512*DI + ((s-6)*128 + k)*DI + n];
        }
        __half hi = __float2half_rn(w);
        __half lo = __float2half_rn(w - __half2float(hi));
        g_Whi[(size_t)tile*WTS + k*136 + n] = hi;
        g_Wlo[(size_t)tile*WTS + k*136 + n] = lo;
    }
}

// ========================================================================
// K2: transpose feat_map + fused LayerNorm (coalesced writes)
// ========================================================================
__global__ void trln_kernel(const float* __restrict__ fm) {
    __shared__ float st[DI][33];
    __shared__ float mu_s[32], rs_s[32];
    int dp0 = blockIdx.x * 32;
    int b = dp0 / SDL, hw0 = dp0 % SDL;
    const float* src = fm + (size_t)b * DI * SDL + hw0;
    int t = threadIdx.x;
    #pragma unroll
    for (int i = 0; i < 16; i++) {
        int e = t + i*256;
        int c = e >> 5, p = e & 31;
        st[c][p] = src[(size_t)c*SDL + p];
    }
    __syncthreads();
    int p = t >> 3, g = t & 7;
    float s = 0.f, s2 = 0.f;
    #pragma unroll
    for (int i = 0; i < 16; i++) {
        float v = st[g*16 + i][p];
        s += v; s2 += v*v;
    }
    #pragma unroll
    for (int off = 4; off; off >>= 1) {
        s  += __shfl_xor_sync(0xffffffffu, s,  off, 8);
        s2 += __shfl_xor_sync(0xffffffffu, s2, off, 8);
    }
    if (g == 0) {
        float mu = s * (1.f/128.f);
        mu_s[p] = mu;
        rs_s[p] = rsqrtf(s2*(1.f/128.f) - mu*mu + 1e-6f);
    }
    __syncthreads();
    #pragma unroll
    for (int i = 0; i < 16; i++) {
        int f = t + i*256;
        int r = f >> 7, c = f & 127;
        g_ctxln[(size_t)(dp0 + r)*DI + c] = (st[c][r] - mu_s[r]) * rs_s[r];
    }
}

// ========================================================================
// K3: transpose feat_map_up -> x rows (coalesced writes)
// ========================================================================
__global__ void trx_kernel(const float* __restrict__ fmu) {
    __shared__ float st[DI][33];
    int n0 = blockIdx.x * 32;
    int b = n0 / SPL, s0 = n0 % SPL;
    const float* src = fmu + (size_t)b * DI * SPL + s0;
    int t = threadIdx.x;
    #pragma unroll
    for (int i = 0; i < 16; i++) {
        int e = t + i*256;
        int c = e >> 5, p = e & 31;
        st[c][p] = src[(size_t)c*SPL + p];
    }
    __syncthreads();
    #pragma unroll
    for (int i = 0; i < 16; i++) {
        int f = t + i*256;
        int r = f >> 7, c = f & 127;
        g_x[(size_t)(n0 + r)*DI + c] = st[c][r];
    }
}

// ========================================================================
// K4: per-dpixel GEMM  g_kvp = g_ctxln @ g_W + g_bias
//     64 rows/block, 192 blocks, 2 CTAs/SM, prefetch pipeline
// SMEM: sAhi 4352 | sAlo 4352 | sBhi 4352 | sBlo 4352 = 17408 floats (69.6KB)
// ========================================================================
#define DGEMM_SMEM (17408*4)
__global__ void __launch_bounds__(256, 2) dgemm_kernel() {
    extern __shared__ __align__(16) float smf[];
    char* sAhi = (char*)(smf);
    char* sAlo = (char*)(smf + 4352);
    char* sBhi = (char*)(smf + 8704);
    char* sBlo = (char*)(smf + 13056);
    const int t = threadIdx.x, lane = t & 31, w = t >> 5;
    const int gid = lane >> 2, tid = lane & 3;
    const int mrow = (w & 3) * 16;
    const int nh   = w >> 2;
    const int r0f = mrow + gid, r1f = r0f + 8;
    const int n0 = blockIdx.x * 64;

    PF pf;
    pf_load(pf, 21, 0, t);
    for (int f = t; f < 4096; f += 256) {
        int r = f >> 6, c2 = f & 63;
        const float* src = g_ctxln + (size_t)(n0 + r)*DI + 2*c2;
        w2a(sAhi, sAlo, r, 2*c2, src[0], src[1]);
    }
    __syncthreads();

    float acc[8][4];
    for (int i = 0; i < 5; i++) {
        #pragma unroll
        for (int nt = 0; nt < 8; nt++) { acc[nt][0]=acc[nt][1]=acc[nt][2]=acc[nt][3]=0.f; }
        gemm_tile_pf(pf, sAhi, sAlo, sBhi, sBlo, acc, 21 + i,
                     (i < 4) ? 22 + i : -1, mrow, nh, lane, t);
        #pragma unroll
        for (int nt = 0; nt < 8; nt++) {
            int c = nh*64 + 8*nt + 2*tid;
            float2 b = *(const float2*)(g_bias + i*128 + c);
            *(float2*)(g_kvp + (size_t)(n0+r0f)*KVP + i*128 + c) =
                make_float2(acc[nt][0]+b.x, acc[nt][1]+b.y);
            *(float2*)(g_kvp + (size_t)(n0+r1f)*KVP + i*128 + c) =
                make_float2(acc[nt][2]+b.x, acc[nt][3]+b.y);
        }
    }
}

// ========================================================================
// K5: HMMA mega kernel — 64 pixels/block, 256 threads, 2 CTAs/SM
// SMEM float offsets (A/B tile = 64x136 fp16 = 4352 floats):
//   0      sAhi   4352      (probs[9][68] aliases in tail)
//   4352   sAlo   4352
//   8704   sBhi   4352      (qbuf[64][132]=8448 aliases sBhi+sBlo)
//   13056  sBlo   4352
//   17408  xf [64][132]  8448
// total 25856 floats = 103424 B  -> 2 CTAs/SM
// ========================================================================
#define MEGA_SMEM (25856*4)

__device__ __forceinline__ float gelu_tanh(float v) {
    float u = 0.7978845608028654f * (v + 0.044715f * v * v * v);
    u = fminf(fmaxf(u, -15.f), 15.f);
    float e = __expf(-2.f * u);
    float th = (1.f - e) / (1.f + e);
    return 0.5f * v * (1.f + th);
}

__device__ __forceinline__ void calc_dpix(int n, int dpix[9]) {
    int b  = n / SPL, s = n % SPL;
    int hu = s / WUm, wu = s % WUm;
    int hd = hu >> 1, wd = wu >> 1;
    #pragma unroll
    for (int i = 0; i < 3; i++)
        #pragma unroll
        for (int j = 0; j < 3; j++) {
            int hs = min(max(hd - 1 + i, 0), HDm - 1);
            int ws = min(max(wd - 1 + j, 0), WDm - 1);
            dpix[i*3 + j] = b*SDL + hs*WDm + ws;
        }
}

// LayerNorm: 4 lanes per row (pure shfl reduce), write split-fp16 A tile
__device__ __forceinline__ void ln_writeA(const float* xf,
                                          char* Ahi, char* Alo, int rr, int c4) {
    const float* xr = xf + rr*132 + c4*32;
    float s = 0.f, s2 = 0.f;
    #pragma unroll
    for (int i = 0; i < 8; i++) {
        float4 v = *(const float4*)(xr + i*4);
        s  += (v.x + v.y) + (v.z + v.w);
        s2 += (v.x*v.x + v.y*v.y) + (v.z*v.z + v.w*v.w);
    }
    s  += __shfl_xor_sync(0xffffffffu, s, 1, 4);
    s  += __shfl_xor_sync(0xffffffffu, s, 2, 4);
    s2 += __shfl_xor_sync(0xffffffffu, s2, 1, 4);
    s2 += __shfl_xor_sync(0xffffffffu, s2, 2, 4);
    float mu   = s * (1.f/128.f);
    float rstd = rsqrtf(s2*(1.f/128.f) - mu*mu + 1e-6f);
    #pragma unroll
    for (int j = 0; j < 32; j += 2) {
        float v0 = (xr[j]   - mu) * rstd;
        float v1 = (xr[j+1] - mu) * rstd;
        w2a(Ahi, Alo, rr, c4*32 + j, v0, v1);
    }
}

#define ZACC() do { _Pragma("unroll") \
    for (int _i = 0; _i < 8; _i++) { acc[_i][0]=acc[_i][1]=acc[_i][2]=acc[_i][3]=0.f; } } while(0)

__global__ void __launch_bounds__(256, 2) mega_kernel(
    const float* __restrict__ bq,  const float* __restrict__ bo,
    const float* __restrict__ b1,  const float* __restrict__ b2,
    const float* __restrict__ bqf, float* __restrict__ out)
{
    extern __shared__ __align__(16) float smf[];
    char*  sAhi = (char*)(smf);
    char*  sAlo = (char*)(smf + 4352);
    char*  sBhi = (char*)(smf + 8704);
    char*  sBlo = (char*)(smf + 13056);
    float* qbuf = smf + 8704;            // aliases sB (sequenced by syncs)
    float* xf   = smf + 17408;           // 64 x 132

    const int t    = threadIdx.x;
    const int lane = t & 31;
    const int w    = t >> 5;
    const int gid  = lane >> 2, tid = lane & 3;
    const int mrow = (w & 3) * 16;        // warp row block
    const int nh   = w >> 2;              // warp col half
    const int r0f  = mrow + gid;          // fragment rows
    const int r1f  = r0f + 8;
    const int rr   = t >> 2;              // pixel row (LN / attention)
    const int c4   = t & 3;               // col chunk / head
    const int n0   = blockIdx.x * 64;

    float acc[8][4];
    PF pf;
    pf_load(pf, 0, 0, t);                 // prefetch wq[l=0] half0

    // load x into xf (stride 132)
    {
        const float* src = g_x + (size_t)(n0 + rr)*DI + c4*32;
        float* dst = xf + rr*132 + c4*32;
        #pragma unroll
        for (int i = 0; i < 8; i++)
            *(float4*)(dst + i*4) = *(const float4*)(src + i*4);
    }
    __syncthreads();

    for (int l = 0; l < 2; l++) {
        int tb = l*10;

        // ===== q = LN(x) @ wq (bias added in attention) =====
        ln_writeA(xf, sAhi, sAlo, rr, c4);
        ZACC();
        gemm_tile_pf(pf, sAhi, sAlo, sBhi, sBlo, acc, tb + 0, tb + 1,
                     mrow, nh, lane, t);
        #pragma unroll
        for (int nt = 0; nt < 8; nt++) {       // frag -> qbuf (sB free)
            int c = nh*64 + 8*nt + 2*tid;
            *(float2*)(qbuf + r0f*132 + c) = make_float2(acc[nt][0], acc[nt][1]);
            *(float2*)(qbuf + r1f*132 + c) = make_float2(acc[nt][2], acc[nt][3]);
        }
        __syncthreads();

        // ===== attention (pixel rr, head c4) =====
        {
            int dpix[9];
            calc_dpix(n0 + rr, dpix);
            const float* qrow = qbuf + rr*132 + c4*32;
            float q[32];
            #pragma unroll
            for (int j = 0; j < 32; j += 4) {
                float4 v = *(const float4*)(qrow + j);
                float4 b = *(const float4*)(bq + l*DI + c4*32 + j);
                q[j] = v.x + b.x; q[j+1] = v.y + b.y;
                q[j+2] = v.z + b.z; q[j+3] = v.w + b.w;
            }
            float lo[9];
            float m = -1e30f;
            #pragma unroll
            for (int kk = 0; kk < 9; kk++) {
                const float* kv = g_kvp + (size_t)dpix[kk]*KVP + l*256 + c4*32;
                float d = 0.f;
                #pragma unroll
                for (int i4 = 0; i4 < 8; i4++) {
                    float4 k4 = __ldg((const float4*)(kv + i4*4));
                    d += q[i4*4]*k4.x + q[i4*4+1]*k4.y
                       + q[i4*4+2]*k4.z + q[i4*4+3]*k4.w;
                }
                lo[kk] = d * 0.17677669529663687f;
                m = fmaxf(m, lo[kk]);
            }
            float ssum = 0.f;
            #pragma unroll
            for (int kk = 0; kk < 9; kk++) {
                lo[kk] = __expf(lo[kk] - m);
                ssum += lo[kk];
            }
            float inv = 1.f / ssum;
            float o[32];
            #pragma unroll
            for (int j = 0; j < 32; j++) o[j] = 0.f;
            #pragma unroll
            for (int kk = 0; kk < 9; kk++) {
                float wgt = lo[kk] * inv;
                const float* vv = g_kvp + (size_t)dpix[kk]*KVP
                                  + l*256 + 128 + c4*32;
                #pragma unroll
                for (int i4 = 0; i4 < 8; i4++) {
                    float4 v = __ldg((const float4*)(vv + i4*4));
                    o[i4*4]   += wgt*v.x; o[i4*4+1] += wgt*v.y;
                    o[i4*4+2] += wgt*v.z; o[i4*4+3] += wgt*v.w;
                }
            }
            #pragma unroll
            for (int j = 0; j < 32; j += 2)
                w2a(sAhi, sAlo, rr, c4*32 + j, o[j], o[j+1]);
        }
        __syncthreads();                     // qbuf reads done (sB reusable)

        // ===== x += o @ wo + bo =====
        ZACC();
        gemm_tile_pf(pf, sAhi, sAlo, sBhi, sBlo, acc, tb + 1, tb + 2,
                     mrow, nh, lane, t);
        #pragma unroll
        for (int nt = 0; nt < 8; nt++) {
            int c = nh*64 + 8*nt + 2*tid;
            float2 b = *(const float2*)(bo + l*DI + c);
            float2* p0 = (float2*)(xf + r0f*132 + c);
            float2* p1 = (float2*)(xf + r1f*132 + c);
            float2 v0 = *p0, v1 = *p1;
            v0.x += acc[nt][0] + b.x; v0.y += acc[nt][1] + b.y;
            v1.x += acc[nt][2] + b.x; v1.y += acc[nt][3] + b.y;
            *p0 = v0; *p1 = v1;
        }
        __syncthreads();

        // ===== MLP: 4 chunks; gelu(h) -> sA =====
        for (int hc = 0; hc < 4; hc++) {
            ln_writeA(xf, sAhi, sAlo, rr, c4);
            ZACC();
            gemm_tile_pf(pf, sAhi, sAlo, sBhi, sBlo, acc, tb + 2 + hc,
                         tb + 6 + hc, mrow, nh, lane, t);
            #pragma unroll
            for (int nt = 0; nt < 8; nt++) {    // gelu -> sA (overwrite LN)
                int c = nh*64 + 8*nt + 2*tid;
                float2 b = *(const float2*)(b1 + l*512 + hc*128 + c);
                w2a(sAhi, sAlo, r0f, c,
                    gelu_tanh(acc[nt][0] + b.x), gelu_tanh(acc[nt][1] + b.y));
                w2a(sAhi, sAlo, r1f, c,
                    gelu_tanh(acc[nt][2] + b.x), gelu_tanh(acc[nt][3] + b.y));
            }
            __syncthreads();
            int nxt = (hc < 3) ? (tb + 3 + hc) : ((l == 0) ? 10 : 20);
            ZACC();
            gemm_tile_pf(pf, sAhi, sAlo, sBhi, sBlo, acc, tb + 6 + hc,
                         nxt, mrow, nh, lane, t);
            #pragma unroll
            for (int nt = 0; nt < 8; nt++) {    // += into xf (+b2 on last)
                int c = nh*64 + 8*nt + 2*tid;
                float2 b = (hc == 3) ? *(const float2*)(b2 + l*DI + c)
                                     : make_float2(0.f, 0.f);
                float2* p0 = (float2*)(xf + r0f*132 + c);
                float2* p1 = (float2*)(xf + r1f*132 + c);
                float2 v0 = *p0, v1 = *p1;
                v0.x += acc[nt][0] + b.x; v0.y += acc[nt][1] + b.y;
                v1.x += acc[nt][2] + b.x; v1.y += acc[nt][3] + b.y;
                *p0 = v0; *p1 = v1;
            }
            __syncthreads();
        }
    }

    // ===== final: xq = LN(x) @ wqf + bqf -> qbuf =====
    ln_writeA(xf, sAhi, sAlo, rr, c4);
    ZACC();
    gemm_tile_pf(pf, sAhi, sAlo, sBhi, sBlo, acc, 20, -1, mrow, nh, lane, t);
    #pragma unroll
    for (int nt = 0; nt < 8; nt++) {
        int c = nh*64 + 8*nt + 2*tid;
        float2 b = *(const float2*)(bqf + c);
        *(float2*)(qbuf + r0f*132 + c) = make_float2(acc[nt][0]+b.x, acc[nt][1]+b.y);
        *(float2*)(qbuf + r1f*132 + c) = make_float2(acc[nt][2]+b.x, acc[nt][3]+b.y);
    }
    __syncthreads();

    // ===== logits + 9-way softmax (shfl-reduced over 4 lanes) =====
    {
        int dpix[9];
        calc_dpix(n0 + rr, dpix);
        float xq[32];
        const float* qrow = qbuf + rr*132 + c4*32;
        #pragma unroll
        for (int j = 0; j < 32; j += 4) {
            float4 v = *(const float4*)(qrow + j);
            xq[j] = v.x; xq[j+1] = v.y; xq[j+2] = v.z; xq[j+3] = v.w;
        }
        float lo[9];
        #pragma unroll
        for (int kk = 0; kk < 9; kk++) {
            const float* cp = g_kvp + (size_t)dpix[kk]*KVP + 512 + c4*32;
            float d = 0.f;
            #pragma unroll
            for (int i4 = 0; i4 < 8; i4++) {
                float4 c4v = __ldg((const float4*)(cp + i4*4));
                d += xq[i4*4]*c4v.x + xq[i4*4+1]*c4v.y
                   + xq[i4*4+2]*c4v.z + xq[i4*4+3]*c4v.w;
            }
            lo[kk] = d;
        }
        #pragma unroll
        for (int kk = 0; kk < 9; kk++) {
            lo[kk] += __shfl_xor_sync(0xffffffffu, lo[kk], 1, 4);
            lo[kk] += __shfl_xor_sync(0xffffffffu, lo[kk], 2, 4);
            lo[kk] *= 0.08838834764831845f;
        }
        float m = -1e30f;
        #pragma unroll
        for (int kk = 0; kk < 9; kk++) m = fmaxf(m, lo[kk]);
        float ssum = 0.f;
        #pragma unroll
        for (int kk = 0; kk < 9; kk++) {
            lo[kk] = __expf(lo[kk] - m);
            ssum += lo[kk];
        }
        float inv = 1.f / ssum;
        float* probs = smf;                  // reuse sA region, [kk][68]
        if (c4 == 0) {
            #pragma unroll
            for (int kk = 0; kk < 9; kk++)
                probs[kk*68 + rr] = lo[kk] * inv;
        }
        __syncthreads();
        int b = n0 / SPL, s0 = n0 % SPL;
        for (int f = t; f < 9*64; f += 256) {
            int kk = f >> 6, p = f & 63;
            out[(size_t)b*9*SPL + (size_t)kk*SPL + s0 + p] = probs[kk*68 + p];
        }
    }
}

// ========================================================================
extern "C" void kernel_launch(void* const* d_in, const int* in_sizes, int n_in,
                              void* d_out, int out_size) {
    const float* feat_map    = (const float*)d_in[0];
    const float* feat_map_up = (const float*)d_in[1];
    const float* nc_w = (const float*)d_in[2];
    const float* nc_b = (const float*)d_in[3];
    const float* wq   = (const float*)d_in[4];
    const float* bq   = (const float*)d_in[5];
    const float* wkv  = (const float*)d_in[6];
    const float* bkv  = (const float*)d_in[7];
    const float* wo   = (const float*)d_in[8];
    const float* bo   = (const float*)d_in[9];
    const float* w1   = (const float*)d_in[10];
    const float* b1   = (const float*)d_in[11];
    const float* w2   = (const float*)d_in[12];
    const float* b2   = (const float*)d_in[13];
    const float* wqf  = (const float*)d_in[14];
    const float* bqf  = (const float*)d_in[15];
    const float* wcf  = (const float*)d_in[16];
    const float* bcf  = (const float*)d_in[17];
    float* out = (float*)d_out;

    cudaFuncSetAttribute(dgemm_kernel,
                         cudaFuncAttributeMaxDynamicSharedMemorySize, DGEMM_SMEM);
    cudaFuncSetAttribute(mega_kernel,
                         cudaFuncAttributeMaxDynamicSharedMemorySize, MEGA_SMEM);

    prep_kernel<<<3, 256>>>(nc_w, nc_b, wkv, bkv, wcf, bcf);
    prepw_kernel<<<NTILES, 256>>>(wq, wo, w1, w2, wqf);
    trln_kernel<<<ND/32, 256>>>(feat_map);
    trx_kernel<<<NP/32, 256>>>(feat_map_up);
    dgemm_kernel<<<ND/64, 256, DGEMM_SMEM>>>();
    mega_kernel<<<NP/64, 256, MEGA_SMEM>>>(bq, bo, b1, b2, bqf, out);
}

// round 14
// speedup vs baseline: 4.8279x; 1.3430x over previous
#include <cuda_runtime.h>
#include <cuda_bf16.h>
#include <cuda_fp16.h>
#include <cstdint>

// ---------------- problem constants ----------------
#define DI   128
#define BATCH 2
#define HDm  64
#define WDm  96
#define HUm  128
#define WUm  192
#define SDL  (HDm*WDm)           // 6144
#define SPL  (HUm*WUm)           // 24576
#define ND   (BATCH*SDL)         // 12288
#define NP   (BATCH*SPL)         // 49152
#define KVP  640                 // kv0(256) | kv1(256) | ctxp(128)
#define NTILES 26                // 0-20 transformer, 21-25 folded kv/ctxp
#define WTS  17408               // fp16 per weight tile (128 x 136)

typedef unsigned long long u64;

// ---------------- device scratch ----------------
__device__ float g_ctxln[ND*DI];
__device__ float g_x[NP*DI];
__device__ float g_kvp[ND*KVP];
__device__ float g_W[DI*KVP];
__device__ float g_bias[KVP];
__device__ __half g_Whi[NTILES*WTS];   // [k][n] tiles, stride 136 (hi only)

// ---------------- HMMA helpers (plain PTX, sm_80+) ----------------
__device__ __forceinline__ uint32_t smem_u32(const void* p) {
    uint32_t a;
    asm("{ .reg .u64 t; cvta.to.shared.u64 t, %1; cvt.u32.u64 %0, t; }"
        : "=r"(a) : "l"(p));
    return a;
}
__device__ __forceinline__ void ldsm_x4(uint32_t r[4], uint32_t addr) {
    asm volatile("ldmatrix.sync.aligned.m8n8.x4.shared.b16 {%0,%1,%2,%3}, [%4];"
        : "=r"(r[0]), "=r"(r[1]), "=r"(r[2]), "=r"(r[3]) : "r"(addr));
}
__device__ __forceinline__ void ldsm_x4t(uint32_t r[4], uint32_t addr) {
    asm volatile("ldmatrix.sync.aligned.m8n8.x4.trans.shared.b16 {%0,%1,%2,%3}, [%4];"
        : "=r"(r[0]), "=r"(r[1]), "=r"(r[2]), "=r"(r[3]) : "r"(addr));
}
__device__ __forceinline__ void mma16816(float d[4], const uint32_t a[4],
                                         const uint32_t b[2]) {
    asm volatile(
        "mma.sync.aligned.m16n8k16.row.col.f32.f16.f16.f32 "
        "{%0,%1,%2,%3}, {%4,%5,%6,%7}, {%8,%9}, {%0,%1,%2,%3};"
        : "+f"(d[0]), "+f"(d[1]), "+f"(d[2]), "+f"(d[3])
        : "r"(a[0]), "r"(a[1]), "r"(a[2]), "r"(a[3]), "r"(b[0]), "r"(b[1]));
}

// write split-fp16 pair at (r, c..c+1), row stride 272 B
__device__ __forceinline__ void w2a(char* hi, char* lo, int r, int c,
                                    float v0, float v1) {
    __half h0 = __float2half_rn(v0), h1 = __float2half_rn(v1);
    float l0 = v0 - __half2float(h0);
    float l1 = v1 - __half2float(h1);
    __half2 H = __halves2half2(h0, h1);
    __half2 L = __halves2half2(__float2half_rn(l0), __float2half_rn(l1));
    int off = r*272 + c*2;
    *(uint32_t*)(hi + off) = *(uint32_t*)&H;
    *(uint32_t*)(lo + off) = *(uint32_t*)&L;
}

// ---- half-K warp GEMM (2-term): D[16x64] += (Ah+Al)[16,kh*64..] * Bh ----
__device__ __forceinline__ void wgemm_half(const char* Ahi, const char* Alo,
                                           const char* Bhi,
                                           float acc[8][4], int mrow, int nh,
                                           int lane, int kh) {
    uint32_t aHi = smem_u32(Ahi), aLo = smem_u32(Alo);
    uint32_t bHi = smem_u32(Bhi);
    int mat = lane >> 3, r8 = lane & 7;
    uint32_t aRow = (uint32_t)((mrow + (mat & 1)*8 + r8) * 272
                               + (mat >> 1) * 16 + kh*128);
    uint32_t bBase = (uint32_t)(((mat & 1)*8 + r8) * 272
                                + (mat >> 1) * 16 + nh*128);
    #pragma unroll
    for (int ks = 0; ks < 4; ks++) {
        uint32_t Ah[4], Al[4];
        ldsm_x4(Ah, aHi + aRow + ks*32);
        ldsm_x4(Al, aLo + aRow + ks*32);
        uint32_t bko = bBase + (uint32_t)(ks*16*272);
        #pragma unroll
        for (int np = 0; np < 4; np++) {
            uint32_t Bh[4];
            ldsm_x4t(Bh, bHi + bko + np*32);
            mma16816(acc[2*np],   Ah, Bh);
            mma16816(acc[2*np],   Al, Bh);
            mma16816(acc[2*np+1], Ah, Bh+2);
            mma16816(acc[2*np+1], Al, Bh+2);
        }
    }
}

// ---- register prefetch of one B half (1088 float4) ----
struct PF { float4 h[5]; };

__device__ __forceinline__ void pf_load(PF& pf, int tile, int kh, int t) {
    const float4* sh = (const float4*)(g_Whi + (size_t)tile*WTS + kh*64*136);
    #pragma unroll
    for (int i = 0; i < 5; i++) {
        int f = t + i*256;
        if (f < 1088) pf.h[i] = __ldg(sh + f);
    }
}
__device__ __forceinline__ void pf_store(const PF& pf, char* Bhi, int t) {
    float4* dh = (float4*)Bhi;
    #pragma unroll
    for (int i = 0; i < 5; i++) {
        int f = t + i*256;
        if (f < 1088) dh[f] = pf.h[i];
    }
}

// pipelined 128-K GEMM tile; pf holds half0 of `tile` on entry,
// half0 of `next_tile` on exit (if >=0). Internal syncs.
__device__ __forceinline__ void gemm_tile_pf(PF& pf,
                                             const char* sAhi, const char* sAlo,
                                             char* sBhi,
                                             float acc[8][4], int tile,
                                             int next_tile,
                                             int mrow, int nh, int lane, int t) {
    pf_store(pf, sBhi, t);
    __syncthreads();
    pf_load(pf, tile, 1, t);
    wgemm_half(sAhi, sAlo, sBhi, acc, mrow, nh, lane, 0);
    __syncthreads();
    pf_store(pf, sBhi, t);
    __syncthreads();
    if (next_tile >= 0) pf_load(pf, next_tile, 0, t);
    wgemm_half(sAhi, sAlo, sBhi, acc, mrow, nh, lane, 1);
    __syncthreads();
}

// ========================================================================
// K1: fold nc_w/nc_b into combined kv/ctxp weight
// ========================================================================
__global__ void prep_kernel(const float* __restrict__ nc_w,
                            const float* __restrict__ nc_b,
                            const float* __restrict__ wkv,
                            const float* __restrict__ bkv,
                            const float* __restrict__ wcf,
                            const float* __restrict__ bcf) {
    int j = blockIdx.x * blockDim.x + threadIdx.x;
    if (j >= KVP) return;
    if (j < 512) {
        int l  = j >> 8;
        int jj = j & 255;
        const float* w = wkv + (size_t)l * DI * 256;
        float bias = bkv[l*256 + jj];
        for (int c = 0; c < DI; c++) {
            float wv = w[c*256 + jj];
            g_W[c*KVP + j] = nc_w[l*DI + c] * wv;
            bias += nc_b[l*DI + c] * wv;
        }
        g_bias[j] = bias;
    } else {
        int jj = j - 512;
        for (int c = 0; c < DI; c++)
            g_W[c*KVP + j] = wcf[c*DI + jj];
        g_bias[j] = bcf[jj];
    }
}

// ========================================================================
// K1b: fp16(hi) weight tiles, [k][n] stride 136
// ========================================================================
__global__ void prepw_kernel(const float* __restrict__ wq,
                             const float* __restrict__ wo,
                             const float* __restrict__ w1,
                             const float* __restrict__ w2,
                             const float* __restrict__ wqf) {
    int tile = blockIdx.x;
    for (int idx = threadIdx.x; idx < DI*DI; idx += blockDim.x) {
        int k = idx >> 7, n = idx & 127;
        float w;
        if (tile >= 21)      w = g_W[k*KVP + (tile-21)*128 + n];
        else if (tile == 20) w = wqf[k*DI + n];
        else {
            int l = tile / 10, s = tile % 10;
            if (s == 0)      w = wq[l*DI*DI + k*DI + n];
            else if (s == 1) w = wo[l*DI*DI + k*DI + n];
            else if (s < 6)  w = w1[l*DI*512 + k*512 + (s-2)*128 + n];
            else             w = w2[l*512*DI + ((s-6)*128 + k)*DI + n];
        }
        g_Whi[(size_t)tile*WTS + k*136 + n] = __float2half_rn(w);
    }
}

// ========================================================================
// K2: transpose feat_map + fused LayerNorm (coalesced writes)
// ========================================================================
__global__ void trln_kernel(const float* __restrict__ fm) {
    __shared__ float st[DI][33];
    __shared__ float mu_s[32], rs_s[32];
    int dp0 = blockIdx.x * 32;
    int b = dp0 / SDL, hw0 = dp0 % SDL;
    const float* src = fm + (size_t)b * DI * SDL + hw0;
    int t = threadIdx.x;
    #pragma unroll
    for (int i = 0; i < 16; i++) {
        int e = t + i*256;
        int c = e >> 5, p = e & 31;
        st[c][p] = src[(size_t)c*SDL + p];
    }
    __syncthreads();
    int p = t >> 3, g = t & 7;
    float s = 0.f, s2 = 0.f;
    #pragma unroll
    for (int i = 0; i < 16; i++) {
        float v = st[g*16 + i][p];
        s += v; s2 += v*v;
    }
    #pragma unroll
    for (int off = 4; off; off >>= 1) {
        s  += __shfl_xor_sync(0xffffffffu, s,  off, 8);
        s2 += __shfl_xor_sync(0xffffffffu, s2, off, 8);
    }
    if (g == 0) {
        float mu = s * (1.f/128.f);
        mu_s[p] = mu;
        rs_s[p] = rsqrtf(s2*(1.f/128.f) - mu*mu + 1e-6f);
    }
    __syncthreads();
    #pragma unroll
    for (int i = 0; i < 16; i++) {
        int f = t + i*256;
        int r = f >> 7, c = f & 127;
        g_ctxln[(size_t)(dp0 + r)*DI + c] = (st[c][r] - mu_s[r]) * rs_s[r];
    }
}

// ========================================================================
// K3: transpose feat_map_up -> x rows (coalesced writes)
// ========================================================================
__global__ void trx_kernel(const float* __restrict__ fmu) {
    __shared__ float st[DI][33];
    int n0 = blockIdx.x * 32;
    int b = n0 / SPL, s0 = n0 % SPL;
    const float* src = fmu + (size_t)b * DI * SPL + s0;
    int t = threadIdx.x;
    #pragma unroll
    for (int i = 0; i < 16; i++) {
        int e = t + i*256;
        int c = e >> 5, p = e & 31;
        st[c][p] = src[(size_t)c*SPL + p];
    }
    __syncthreads();
    #pragma unroll
    for (int i = 0; i < 16; i++) {
        int f = t + i*256;
        int r = f >> 7, c = f & 127;
        g_x[(size_t)(n0 + r)*DI + c] = st[c][r];
    }
}

// ========================================================================
// K4: per-dpixel GEMM  g_kvp = g_ctxln @ g_W + g_bias
// SMEM: sAhi 4352 | sAlo 4352 | sBhi 4352 = 13056 floats (52.2KB), 2 CTAs/SM
// ========================================================================
#define DGEMM_SMEM (13056*4)
__global__ void __launch_bounds__(256, 2) dgemm_kernel() {
    extern __shared__ __align__(16) float smf[];
    char* sAhi = (char*)(smf);
    char* sAlo = (char*)(smf + 4352);
    char* sBhi = (char*)(smf + 8704);
    const int t = threadIdx.x, lane = t & 31, w = t >> 5;
    const int gid = lane >> 2, tid = lane & 3;
    const int mrow = (w & 3) * 16;
    const int nh   = w >> 2;
    const int r0f = mrow + gid, r1f = r0f + 8;
    const int n0 = blockIdx.x * 64;

    PF pf;
    pf_load(pf, 21, 0, t);
    for (int f = t; f < 4096; f += 256) {
        int r = f >> 6, c2 = f & 63;
        const float* src = g_ctxln + (size_t)(n0 + r)*DI + 2*c2;
        w2a(sAhi, sAlo, r, 2*c2, src[0], src[1]);
    }
    __syncthreads();

    float acc[8][4];
    for (int i = 0; i < 5; i++) {
        #pragma unroll
        for (int nt = 0; nt < 8; nt++) { acc[nt][0]=acc[nt][1]=acc[nt][2]=acc[nt][3]=0.f; }
        gemm_tile_pf(pf, sAhi, sAlo, sBhi, acc, 21 + i,
                     (i < 4) ? 22 + i : -1, mrow, nh, lane, t);
        #pragma unroll
        for (int nt = 0; nt < 8; nt++) {
            int c = nh*64 + 8*nt + 2*tid;
            float2 b = *(const float2*)(g_bias + i*128 + c);
            *(float2*)(g_kvp + (size_t)(n0+r0f)*KVP + i*128 + c) =
                make_float2(acc[nt][0]+b.x, acc[nt][1]+b.y);
            *(float2*)(g_kvp + (size_t)(n0+r1f)*KVP + i*128 + c) =
                make_float2(acc[nt][2]+b.x, acc[nt][3]+b.y);
        }
    }
}

// ========================================================================
// K5: HMMA mega kernel — 64 pixels/block, 256 threads, 2 CTAs/SM
// SMEM float offsets (A tile = 4352 floats):
//   0      sAhi   4352      (probs[9][68] aliases in tail)
//   4352   sAlo   4352
//   8704   sBhi   4352      (qbuf[64][132]=8448 aliases 8704..17152)
//   13056  (qbuf overflow)  4352
//   17408  xf [64][132]  8448
// total 25856 floats = 103424 B  -> 2 CTAs/SM
// ========================================================================
#define MEGA_SMEM (25856*4)

__device__ __forceinline__ float gelu_tanh(float v) {
    float u = 0.7978845608028654f * (v + 0.044715f * v * v * v);
    u = fminf(fmaxf(u, -15.f), 15.f);
    float e = __expf(-2.f * u);
    float th = (1.f - e) / (1.f + e);
    return 0.5f * v * (1.f + th);
}

__device__ __forceinline__ void calc_dpix(int n, int dpix[9]) {
    int b  = n / SPL, s = n % SPL;
    int hu = s / WUm, wu = s % WUm;
    int hd = hu >> 1, wd = wu >> 1;
    #pragma unroll
    for (int i = 0; i < 3; i++)
        #pragma unroll
        for (int j = 0; j < 3; j++) {
            int hs = min(max(hd - 1 + i, 0), HDm - 1);
            int ws = min(max(wd - 1 + j, 0), WDm - 1);
            dpix[i*3 + j] = b*SDL + hs*WDm + ws;
        }
}

// LayerNorm: 4 lanes per row (pure shfl reduce), write split-fp16 A tile
__device__ __forceinline__ void ln_writeA(const float* xf,
                                          char* Ahi, char* Alo, int rr, int c4) {
    const float* xr = xf + rr*132 + c4*32;
    float s = 0.f, s2 = 0.f;
    #pragma unroll
    for (int i = 0; i < 8; i++) {
        float4 v = *(const float4*)(xr + i*4);
        s  += (v.x + v.y) + (v.z + v.w);
        s2 += (v.x*v.x + v.y*v.y) + (v.z*v.z + v.w*v.w);
    }
    s  += __shfl_xor_sync(0xffffffffu, s, 1, 4);
    s  += __shfl_xor_sync(0xffffffffu, s, 2, 4);
    s2 += __shfl_xor_sync(0xffffffffu, s2, 1, 4);
    s2 += __shfl_xor_sync(0xffffffffu, s2, 2, 4);
    float mu   = s * (1.f/128.f);
    float rstd = rsqrtf(s2*(1.f/128.f) - mu*mu + 1e-6f);
    #pragma unroll
    for (int j = 0; j < 32; j += 2) {
        float v0 = (xr[j]   - mu) * rstd;
        float v1 = (xr[j+1] - mu) * rstd;
        w2a(Ahi, Alo, rr, c4*32 + j, v0, v1);
    }
}

#define ZACC() do { _Pragma("unroll") \
    for (int _i = 0; _i < 8; _i++) { acc[_i][0]=acc[_i][1]=acc[_i][2]=acc[_i][3]=0.f; } } while(0)

__global__ void __launch_bounds__(256, 2) mega_kernel(
    const float* __restrict__ bq,  const float* __restrict__ bo,
    const float* __restrict__ b1,  const float* __restrict__ b2,
    const float* __restrict__ bqf, float* __restrict__ out)
{
    extern __shared__ __align__(16) float smf[];
    char*  sAhi = (char*)(smf);
    char*  sAlo = (char*)(smf + 4352);
    char*  sBhi = (char*)(smf + 8704);
    float* qbuf = smf + 8704;            // aliases sBhi + spare (sequenced)
    float* xf   = smf + 17408;           // 64 x 132

    const int t    = threadIdx.x;
    const int lane = t & 31;
    const int w    = t >> 5;
    const int gid  = lane >> 2, tid = lane & 3;
    const int mrow = (w & 3) * 16;        // warp row block
    const int nh   = w >> 2;              // warp col half
    const int r0f  = mrow + gid;          // fragment rows
    const int r1f  = r0f + 8;
    const int rr   = t >> 2;              // pixel row (LN)
    const int c4   = t & 3;               // col chunk (LN)
    const int j8   = lane >> 3;           // gather group in warp
    const int l8   = lane & 7;            // lane in gather group
    const int n0   = blockIdx.x * 64;

    float acc[8][4];
    PF pf;
    pf_load(pf, 0, 0, t);                 // prefetch wq[l=0] half0

    // load x into xf (stride 132)
    {
        const float* src = g_x + (size_t)(n0 + rr)*DI + c4*32;
        float* dst = xf + rr*132 + c4*32;
        #pragma unroll
        for (int i = 0; i < 8; i++)
            *(float4*)(dst + i*4) = *(const float4*)(src + i*4);
    }
    __syncthreads();

    for (int l = 0; l < 2; l++) {
        int tb = l*10;

        // ===== q = LN(x) @ wq (bias added in attention) =====
        ln_writeA(xf, sAhi, sAlo, rr, c4);
        ZACC();
        gemm_tile_pf(pf, sAhi, sAlo, sBhi, acc, tb + 0, tb + 1,
                     mrow, nh, lane, t);
        #pragma unroll
        for (int nt = 0; nt < 8; nt++) {       // frag -> qbuf (sB free)
            int c = nh*64 + 8*nt + 2*tid;
            *(float2*)(qbuf + r0f*132 + c) = make_float2(acc[nt][0], acc[nt][1]);
            *(float2*)(qbuf + r1f*132 + c) = make_float2(acc[nt][2], acc[nt][3]);
        }
        __syncthreads();

        // ===== attention: 8-lane cooperative gathers, 8 rounds =====
        for (int ro = 0; ro < 8; ro++) {
            int g = ro*32 + w*4 + j8;          // pixel-head 0..255
            int p = g >> 2, h = g & 3;
            int dpix[9];
            calc_dpix(n0 + p, dpix);
            float4 qv = *(const float4*)(qbuf + p*132 + h*32 + l8*4);
            float4 bv = *(const float4*)(bq + l*DI + h*32 + l8*4);
            float q0 = qv.x + bv.x, q1 = qv.y + bv.y;
            float q2 = qv.z + bv.z, q3 = qv.w + bv.w;
            float lo[9];
            float m = -1e30f;
            #pragma unroll
            for (int kk = 0; kk < 9; kk++) {
                const float* kv = g_kvp + (size_t)dpix[kk]*KVP + l*256
                                  + h*32 + l8*4;
                float4 k4 = __ldg((const float4*)kv);
                float d = q0*k4.x + q1*k4.y + q2*k4.z + q3*k4.w;
                d += __shfl_xor_sync(0xffffffffu, d, 1, 8);
                d += __shfl_xor_sync(0xffffffffu, d, 2, 8);
                d += __shfl_xor_sync(0xffffffffu, d, 4, 8);
                lo[kk] = d * 0.17677669529663687f;
                m = fmaxf(m, lo[kk]);
            }
            float ssum = 0.f;
            #pragma unroll
            for (int kk = 0; kk < 9; kk++) {
                lo[kk] = __expf(lo[kk] - m);
                ssum += lo[kk];
            }
            float inv = 1.f / ssum;
            float o0 = 0.f, o1 = 0.f, o2 = 0.f, o3 = 0.f;
            #pragma unroll
            for (int kk = 0; kk < 9; kk++) {
                float wgt = lo[kk] * inv;
                const float* vv = g_kvp + (size_t)dpix[kk]*KVP + l*256 + 128
                                  + h*32 + l8*4;
                float4 v = __ldg((const float4*)vv);
                o0 += wgt*v.x; o1 += wgt*v.y; o2 += wgt*v.z; o3 += wgt*v.w;
            }
            w2a(sAhi, sAlo, p, h*32 + l8*4,     o0, o1);
            w2a(sAhi, sAlo, p, h*32 + l8*4 + 2, o2, o3);
        }
        __syncthreads();                     // qbuf reads done (sB reusable)

        // ===== x += o @ wo + bo =====
        ZACC();
        gemm_tile_pf(pf, sAhi, sAlo, sBhi, acc, tb + 1, tb + 2,
                     mrow, nh, lane, t);
        #pragma unroll
        for (int nt = 0; nt < 8; nt++) {
            int c = nh*64 + 8*nt + 2*tid;
            float2 b = *(const float2*)(bo + l*DI + c);
            float2* p0 = (float2*)(xf + r0f*132 + c);
            float2* p1 = (float2*)(xf + r1f*132 + c);
            float2 v0 = *p0, v1 = *p1;
            v0.x += acc[nt][0] + b.x; v0.y += acc[nt][1] + b.y;
            v1.x += acc[nt][2] + b.x; v1.y += acc[nt][3] + b.y;
            *p0 = v0; *p1 = v1;
        }
        __syncthreads();

        // ===== MLP: 4 chunks; gelu(h) -> sA =====
        for (int hc = 0; hc < 4; hc++) {
            ln_writeA(xf, sAhi, sAlo, rr, c4);
            ZACC();
            gemm_tile_pf(pf, sAhi, sAlo, sBhi, acc, tb + 2 + hc,
                         tb + 6 + hc, mrow, nh, lane, t);
            #pragma unroll
            for (int nt = 0; nt < 8; nt++) {    // gelu -> sA (overwrite LN)
                int c = nh*64 + 8*nt + 2*tid;
                float2 b = *(const float2*)(b1 + l*512 + hc*128 + c);
                w2a(sAhi, sAlo, r0f, c,
                    gelu_tanh(acc[nt][0] + b.x), gelu_tanh(acc[nt][1] + b.y));
                w2a(sAhi, sAlo, r1f, c,
                    gelu_tanh(acc[nt][2] + b.x), gelu_tanh(acc[nt][3] + b.y));
            }
            __syncthreads();
            int nxt = (hc < 3) ? (tb + 3 + hc) : ((l == 0) ? 10 : 20);
            ZACC();
            gemm_tile_pf(pf, sAhi, sAlo, sBhi, acc, tb + 6 + hc,
                         nxt, mrow, nh, lane, t);
            #pragma unroll
            for (int nt = 0; nt < 8; nt++) {    // += into xf (+b2 on last)
                int c = nh*64 + 8*nt + 2*tid;
                float2 b = (hc == 3) ? *(const float2*)(b2 + l*DI + c)
                                     : make_float2(0.f, 0.f);
                float2* p0 = (float2*)(xf + r0f*132 + c);
                float2* p1 = (float2*)(xf + r1f*132 + c);
                float2 v0 = *p0, v1 = *p1;
                v0.x += acc[nt][0] + b.x; v0.y += acc[nt][1] + b.y;
                v1.x += acc[nt][2] + b.x; v1.y += acc[nt][3] + b.y;
                *p0 = v0; *p1 = v1;
            }
            __syncthreads();
        }
    }

    // ===== final: xq = LN(x) @ wqf + bqf -> qbuf =====
    ln_writeA(xf, sAhi, sAlo, rr, c4);
    ZACC();
    gemm_tile_pf(pf, sAhi, sAlo, sBhi, acc, 20, -1, mrow, nh, lane, t);
    #pragma unroll
    for (int nt = 0; nt < 8; nt++) {
        int c = nh*64 + 8*nt + 2*tid;
        float2 b = *(const float2*)(bqf + c);
        *(float2*)(qbuf + r0f*132 + c) = make_float2(acc[nt][0]+b.x, acc[nt][1]+b.y);
        *(float2*)(qbuf + r1f*132 + c) = make_float2(acc[nt][2]+b.x, acc[nt][3]+b.y);
    }
    __syncthreads();

    // ===== logits + 9-way softmax: warp w round ro -> pixel ro*8+w =====
    {
        float* probs = smf;                  // reuse sAhi region, [kk][68]
        for (int ro = 0; ro < 8; ro++) {
            int p = ro*8 + w;
            int dpix[9];
            calc_dpix(n0 + p, dpix);
            int cidx = j8*32 + l8*4;
            float4 xv = *(const float4*)(qbuf + p*132 + cidx);
            float lo[9];
            #pragma unroll
            for (int kk = 0; kk < 9; kk++) {
                const float* cp = g_kvp + (size_t)dpix[kk]*KVP + 512 + cidx;
                float4 c4v = __ldg((const float4*)cp);
                float d = xv.x*c4v.x + xv.y*c4v.y + xv.z*c4v.z + xv.w*c4v.w;
                d += __shfl_xor_sync(0xffffffffu, d, 1);
                d += __shfl_xor_sync(0xffffffffu, d, 2);
                d += __shfl_xor_sync(0xffffffffu, d, 4);
                d += __shfl_xor_sync(0xffffffffu, d, 8);
                d += __shfl_xor_sync(0xffffffffu, d, 16);
                lo[kk] = d * 0.08838834764831845f;
            }
            float m = -1e30f;
            #pragma unroll
            for (int kk = 0; kk < 9; kk++) m = fmaxf(m, lo[kk]);
            float ssum = 0.f;
            #pragma unroll
            for (int kk = 0; kk < 9; kk++) {
                lo[kk] = __expf(lo[kk] - m);
                ssum += lo[kk];
            }
            float inv = 1.f / ssum;
            if (lane == 0) {
                #pragma unroll
                for (int kk = 0; kk < 9; kk++)
                    probs[kk*68 + p] = lo[kk] * inv;
            }
        }
        __syncthreads();
        int b = n0 / SPL, s0 = n0 % SPL;
        for (int f = t; f < 9*64; f += 256) {
            int kk = f >> 6, p = f & 63;
            out[(size_t)b*9*SPL + (size_t)kk*SPL + s0 + p] = probs[kk*68 + p];
        }
    }
}

// ========================================================================
extern "C" void kernel_launch(void* const* d_in, const int* in_sizes, int n_in,
                              void* d_out, int out_size) {
    const float* feat_map    = (const float*)d_in[0];
    const float* feat_map_up = (const float*)d_in[1];
    const float* nc_w = (const float*)d_in[2];
    const float* nc_b = (const float*)d_in[3];
    const float* wq   = (const float*)d_in[4];
    const float* bq   = (const float*)d_in[5];
    const float* wkv  = (const float*)d_in[6];
    const float* bkv  = (const float*)d_in[7];
    const float* wo   = (const float*)d_in[8];
    const float* bo   = (const float*)d_in[9];
    const float* w1   = (const float*)d_in[10];
    const float* b1   = (const float*)d_in[11];
    const float* w2   = (const float*)d_in[12];
    const float* b2   = (const float*)d_in[13];
    const float* wqf  = (const float*)d_in[14];
    const float* bqf  = (const float*)d_in[15];
    const float* wcf  = (const float*)d_in[16];
    const float* bcf  = (const float*)d_in[17];
    float* out = (float*)d_out;

    cudaFuncSetAttribute(dgemm_kernel,
                         cudaFuncAttributeMaxDynamicSharedMemorySize, DGEMM_SMEM);
    cudaFuncSetAttribute(mega_kernel,
                         cudaFuncAttributeMaxDynamicSharedMemorySize, MEGA_SMEM);

    prep_kernel<<<3, 256>>>(nc_w, nc_b, wkv, bkv, wcf, bcf);
    prepw_kernel<<<NTILES, 256>>>(wq, wo, w1, w2, wqf);
    trln_kernel<<<ND/32, 256>>>(feat_map);
    trx_kernel<<<NP/32, 256>>>(feat_map_up);
    dgemm_kernel<<<ND/64, 256, DGEMM_SMEM>>>();
    mega_kernel<<<NP/64, 256, MEGA_SMEM>>>(bq, bo, b1, b2, bqf, out);
}

// round 15
// speedup vs baseline: 5.4809x; 1.1353x over previous
#include <cuda_runtime.h>
#include <cuda_bf16.h>
#include <cuda_fp16.h>
#include <cstdint>

// ---------------- problem constants ----------------
#define DI   128
#define BATCH 2
#define HDm  64
#define WDm  96
#define HUm  128
#define WUm  192
#define SDL  (HDm*WDm)           // 6144
#define SPL  (HUm*WUm)           // 24576
#define ND   (BATCH*SDL)         // 12288
#define NP   (BATCH*SPL)         // 49152
#define KVP  640                 // kv0(256) | kv1(256) | ctxp(128)
#define NTILES 26                // 0-20 transformer, 21-25 folded kv/ctxp
#define WTS  17408               // fp16 per weight tile (128 x 136)

typedef unsigned long long u64;

// ---------------- device scratch ----------------
__device__ float g_ctxln[ND*DI];
__device__ float g_x[NP*DI];
__device__ float g_kvp[ND*KVP];
__device__ float g_W[DI*KVP];
__device__ float g_bias[KVP];
__device__ __half g_Whi[NTILES*WTS];   // [k][n] tiles, stride 136 (hi only)

// ---------------- HMMA helpers (plain PTX, sm_80+) ----------------
__device__ __forceinline__ uint32_t smem_u32(const void* p) {
    uint32_t a;
    asm("{ .reg .u64 t; cvta.to.shared.u64 t, %1; cvt.u32.u64 %0, t; }"
        : "=r"(a) : "l"(p));
    return a;
}
__device__ __forceinline__ void ldsm_x4(uint32_t r[4], uint32_t addr) {
    asm volatile("ldmatrix.sync.aligned.m8n8.x4.shared.b16 {%0,%1,%2,%3}, [%4];"
        : "=r"(r[0]), "=r"(r[1]), "=r"(r[2]), "=r"(r[3]) : "r"(addr));
}
__device__ __forceinline__ void ldsm_x4t(uint32_t r[4], uint32_t addr) {
    asm volatile("ldmatrix.sync.aligned.m8n8.x4.trans.shared.b16 {%0,%1,%2,%3}, [%4];"
        : "=r"(r[0]), "=r"(r[1]), "=r"(r[2]), "=r"(r[3]) : "r"(addr));
}
__device__ __forceinline__ void mma16816(float d[4], const uint32_t a[4],
                                         const uint32_t b[2]) {
    asm volatile(
        "mma.sync.aligned.m16n8k16.row.col.f32.f16.f16.f32 "
        "{%0,%1,%2,%3}, {%4,%5,%6,%7}, {%8,%9}, {%0,%1,%2,%3};"
        : "+f"(d[0]), "+f"(d[1]), "+f"(d[2]), "+f"(d[3])
        : "r"(a[0]), "r"(a[1]), "r"(a[2]), "r"(a[3]), "r"(b[0]), "r"(b[1]));
}

// write split-fp16 pair at (r, c..c+1), row stride 272 B (hi+lo, dgemm)
__device__ __forceinline__ void w2a(char* hi, char* lo, int r, int c,
                                    float v0, float v1) {
    __half h0 = __float2half_rn(v0), h1 = __float2half_rn(v1);
    float l0 = v0 - __half2float(h0);
    float l1 = v1 - __half2float(h1);
    __half2 H = __halves2half2(h0, h1);
    __half2 L = __halves2half2(__float2half_rn(l0), __float2half_rn(l1));
    int off = r*272 + c*2;
    *(uint32_t*)(hi + off) = *(uint32_t*)&H;
    *(uint32_t*)(lo + off) = *(uint32_t*)&L;
}
// hi-only variant (mega)
__device__ __forceinline__ void w2a_hi(char* hi, int r, int c,
                                       float v0, float v1) {
    __half2 H = __halves2half2(__float2half_rn(v0), __float2half_rn(v1));
    *(uint32_t*)(hi + r*272 + c*2) = *(uint32_t*)&H;
}

// ---- half-K warp GEMM, split-A 2-term (dgemm) ----
__device__ __forceinline__ void wgemm_half(const char* Ahi, const char* Alo,
                                           const char* Bhi,
                                           float acc[8][4], int mrow, int nh,
                                           int lane, int kh) {
    uint32_t aHi = smem_u32(Ahi), aLo = smem_u32(Alo);
    uint32_t bHi = smem_u32(Bhi);
    int mat = lane >> 3, r8 = lane & 7;
    uint32_t aRow = (uint32_t)((mrow + (mat & 1)*8 + r8) * 272
                               + (mat >> 1) * 16 + kh*128);
    uint32_t bBase = (uint32_t)(((mat & 1)*8 + r8) * 272
                                + (mat >> 1) * 16 + nh*128);
    #pragma unroll
    for (int ks = 0; ks < 4; ks++) {
        uint32_t Ah[4], Al[4];
        ldsm_x4(Ah, aHi + aRow + ks*32);
        ldsm_x4(Al, aLo + aRow + ks*32);
        uint32_t bko = bBase + (uint32_t)(ks*16*272);
        #pragma unroll
        for (int np = 0; np < 4; np++) {
            uint32_t Bh[4];
            ldsm_x4t(Bh, bHi + bko + np*32);
            mma16816(acc[2*np],   Ah, Bh);
            mma16816(acc[2*np],   Al, Bh);
            mma16816(acc[2*np+1], Ah, Bh+2);
            mma16816(acc[2*np+1], Al, Bh+2);
        }
    }
}

// ---- half-K warp GEMM, pure fp16 single-term (mega) ----
__device__ __forceinline__ void wgemm_half1(const char* Ahi, const char* Bhi,
                                            float acc[8][4], int mrow, int nh,
                                            int lane, int kh) {
    uint32_t aHi = smem_u32(Ahi);
    uint32_t bHi = smem_u32(Bhi);
    int mat = lane >> 3, r8 = lane & 7;
    uint32_t aRow = (uint32_t)((mrow + (mat & 1)*8 + r8) * 272
                               + (mat >> 1) * 16 + kh*128);
    uint32_t bBase = (uint32_t)(((mat & 1)*8 + r8) * 272
                                + (mat >> 1) * 16 + nh*128);
    #pragma unroll
    for (int ks = 0; ks < 4; ks++) {
        uint32_t Ah[4];
        ldsm_x4(Ah, aHi + aRow + ks*32);
        uint32_t bko = bBase + (uint32_t)(ks*16*272);
        #pragma unroll
        for (int np = 0; np < 4; np++) {
            uint32_t Bh[4];
            ldsm_x4t(Bh, bHi + bko + np*32);
            mma16816(acc[2*np],   Ah, Bh);
            mma16816(acc[2*np+1], Ah, Bh+2);
        }
    }
}

// ---- register prefetch of one B half (1088 float4) ----
struct PF { float4 h[5]; };

__device__ __forceinline__ void pf_load(PF& pf, int tile, int kh, int t) {
    const float4* sh = (const float4*)(g_Whi + (size_t)tile*WTS + kh*64*136);
    #pragma unroll
    for (int i = 0; i < 5; i++) {
        int f = t + i*256;
        if (f < 1088) pf.h[i] = __ldg(sh + f);
    }
}
__device__ __forceinline__ void pf_store(const PF& pf, char* Bhi, int t) {
    float4* dh = (float4*)Bhi;
    #pragma unroll
    for (int i = 0; i < 5; i++) {
        int f = t + i*256;
        if (f < 1088) dh[f] = pf.h[i];
    }
}

// pipelined tile, 2-term (dgemm)
__device__ __forceinline__ void gemm_tile_pf(PF& pf,
                                             const char* sAhi, const char* sAlo,
                                             char* sBhi,
                                             float acc[8][4], int tile,
                                             int next_tile,
                                             int mrow, int nh, int lane, int t) {
    pf_store(pf, sBhi, t);
    __syncthreads();
    pf_load(pf, tile, 1, t);
    wgemm_half(sAhi, sAlo, sBhi, acc, mrow, nh, lane, 0);
    __syncthreads();
    pf_store(pf, sBhi, t);
    __syncthreads();
    if (next_tile >= 0) pf_load(pf, next_tile, 0, t);
    wgemm_half(sAhi, sAlo, sBhi, acc, mrow, nh, lane, 1);
    __syncthreads();
}

// pipelined tile, single-term (mega)
__device__ __forceinline__ void gemm_tile_pf1(PF& pf,
                                              const char* sAhi, char* sBhi,
                                              float acc[8][4], int tile,
                                              int next_tile,
                                              int mrow, int nh, int lane, int t) {
    pf_store(pf, sBhi, t);
    __syncthreads();
    pf_load(pf, tile, 1, t);
    wgemm_half1(sAhi, sBhi, acc, mrow, nh, lane, 0);
    __syncthreads();
    pf_store(pf, sBhi, t);
    __syncthreads();
    if (next_tile >= 0) pf_load(pf, next_tile, 0, t);
    wgemm_half1(sAhi, sBhi, acc, mrow, nh, lane, 1);
    __syncthreads();
}

// ========================================================================
// K1: fold nc_w/nc_b into combined kv/ctxp weight
// ========================================================================
__global__ void prep_kernel(const float* __restrict__ nc_w,
                            const float* __restrict__ nc_b,
                            const float* __restrict__ wkv,
                            const float* __restrict__ bkv,
                            const float* __restrict__ wcf,
                            const float* __restrict__ bcf) {
    int j = blockIdx.x * blockDim.x + threadIdx.x;
    if (j >= KVP) return;
    if (j < 512) {
        int l  = j >> 8;
        int jj = j & 255;
        const float* w = wkv + (size_t)l * DI * 256;
        float bias = bkv[l*256 + jj];
        for (int c = 0; c < DI; c++) {
            float wv = w[c*256 + jj];
            g_W[c*KVP + j] = nc_w[l*DI + c] * wv;
            bias += nc_b[l*DI + c] * wv;
        }
        g_bias[j] = bias;
    } else {
        int jj = j - 512;
        for (int c = 0; c < DI; c++)
            g_W[c*KVP + j] = wcf[c*DI + jj];
        g_bias[j] = bcf[jj];
    }
}

// ========================================================================
// K1b: fp16(hi) weight tiles, [k][n] stride 136
// ========================================================================
__global__ void prepw_kernel(const float* __restrict__ wq,
                             const float* __restrict__ wo,
                             const float* __restrict__ w1,
                             const float* __restrict__ w2,
                             const float* __restrict__ wqf) {
    int tile = blockIdx.x;
    for (int idx = threadIdx.x; idx < DI*DI; idx += blockDim.x) {
        int k = idx >> 7, n = idx & 127;
        float w;
        if (tile >= 21)      w = g_W[k*KVP + (tile-21)*128 + n];
        else if (tile == 20) w = wqf[k*DI + n];
        else {
            int l = tile / 10, s = tile % 10;
            if (s == 0)      w = wq[l*DI*DI + k*DI + n];
            else if (s == 1) w = wo[l*DI*DI + k*DI + n];
            else if (s < 6)  w = w1[l*DI*512 + k*512 + (s-2)*128 + n];
            else             w = w2[l*512*DI + ((s-6)*128 + k)*DI + n];
        }
        g_Whi[(size_t)tile*WTS + k*136 + n] = __float2half_rn(w);
    }
}

// ========================================================================
// K2: transpose feat_map + fused LayerNorm (coalesced writes)
// ========================================================================
__global__ void trln_kernel(const float* __restrict__ fm) {
    __shared__ float st[DI][33];
    __shared__ float mu_s[32], rs_s[32];
    int dp0 = blockIdx.x * 32;
    int b = dp0 / SDL, hw0 = dp0 % SDL;
    const float* src = fm + (size_t)b * DI * SDL + hw0;
    int t = threadIdx.x;
    #pragma unroll
    for (int i = 0; i < 16; i++) {
        int e = t + i*256;
        int c = e >> 5, p = e & 31;
        st[c][p] = src[(size_t)c*SDL + p];
    }
    __syncthreads();
    int p = t >> 3, g = t & 7;
    float s = 0.f, s2 = 0.f;
    #pragma unroll
    for (int i = 0; i < 16; i++) {
        float v = st[g*16 + i][p];
        s += v; s2 += v*v;
    }
    #pragma unroll
    for (int off = 4; off; off >>= 1) {
        s  += __shfl_xor_sync(0xffffffffu, s,  off, 8);
        s2 += __shfl_xor_sync(0xffffffffu, s2, off, 8);
    }
    if (g == 0) {
        float mu = s * (1.f/128.f);
        mu_s[p] = mu;
        rs_s[p] = rsqrtf(s2*(1.f/128.f) - mu*mu + 1e-6f);
    }
    __syncthreads();
    #pragma unroll
    for (int i = 0; i < 16; i++) {
        int f = t + i*256;
        int r = f >> 7, c = f & 127;
        g_ctxln[(size_t)(dp0 + r)*DI + c] = (st[c][r] - mu_s[r]) * rs_s[r];
    }
}

// ========================================================================
// K3: transpose feat_map_up -> x rows (coalesced writes)
// ========================================================================
__global__ void trx_kernel(const float* __restrict__ fmu) {
    __shared__ float st[DI][33];
    int n0 = blockIdx.x * 32;
    int b = n0 / SPL, s0 = n0 % SPL;
    const float* src = fmu + (size_t)b * DI * SPL + s0;
    int t = threadIdx.x;
    #pragma unroll
    for (int i = 0; i < 16; i++) {
        int e = t + i*256;
        int c = e >> 5, p = e & 31;
        st[c][p] = src[(size_t)c*SPL + p];
    }
    __syncthreads();
    #pragma unroll
    for (int i = 0; i < 16; i++) {
        int f = t + i*256;
        int r = f >> 7, c = f & 127;
        g_x[(size_t)(n0 + r)*DI + c] = st[c][r];
    }
}

// ========================================================================
// K4: per-dpixel GEMM  g_kvp = g_ctxln @ g_W + g_bias  (split-A 2-term)
// SMEM: sAhi 4352 | sAlo 4352 | sBhi 4352 = 13056 floats (52.2KB), 2 CTAs/SM
// ========================================================================
#define DGEMM_SMEM (13056*4)
__global__ void __launch_bounds__(256, 2) dgemm_kernel() {
    extern __shared__ __align__(16) float smf[];
    char* sAhi = (char*)(smf);
    char* sAlo = (char*)(smf + 4352);
    char* sBhi = (char*)(smf + 8704);
    const int t = threadIdx.x, lane = t & 31, w = t >> 5;
    const int gid = lane >> 2, tid = lane & 3;
    const int mrow = (w & 3) * 16;
    const int nh   = w >> 2;
    const int r0f = mrow + gid, r1f = r0f + 8;
    const int n0 = blockIdx.x * 64;

    PF pf;
    pf_load(pf, 21, 0, t);
    for (int f = t; f < 4096; f += 256) {
        int r = f >> 6, c2 = f & 63;
        const float* src = g_ctxln + (size_t)(n0 + r)*DI + 2*c2;
        w2a(sAhi, sAlo, r, 2*c2, src[0], src[1]);
    }
    __syncthreads();

    float acc[8][4];
    for (int i = 0; i < 5; i++) {
        #pragma unroll
        for (int nt = 0; nt < 8; nt++) { acc[nt][0]=acc[nt][1]=acc[nt][2]=acc[nt][3]=0.f; }
        gemm_tile_pf(pf, sAhi, sAlo, sBhi, acc, 21 + i,
                     (i < 4) ? 22 + i : -1, mrow, nh, lane, t);
        #pragma unroll
        for (int nt = 0; nt < 8; nt++) {
            int c = nh*64 + 8*nt + 2*tid;
            float2 b = *(const float2*)(g_bias + i*128 + c);
            *(float2*)(g_kvp + (size_t)(n0+r0f)*KVP + i*128 + c) =
                make_float2(acc[nt][0]+b.x, acc[nt][1]+b.y);
            *(float2*)(g_kvp + (size_t)(n0+r1f)*KVP + i*128 + c) =
                make_float2(acc[nt][2]+b.x, acc[nt][3]+b.y);
        }
    }
}

// ========================================================================
// K5: HMMA mega kernel — 64 pixels/block, 256 threads, pure-fp16 A
// SMEM float offsets:
//   0      sAhi   4352      (probs[9][68] aliases in tail)
//   4352   sBhi   4352      (qbuf[64][132]=8448 spans 4352..12800)
//   8704   (qbuf overflow)  4096
//   12800  xf [64][132]     8448
// total 21248 floats = 84992 B  -> 2 CTAs/SM
// ========================================================================
#define MEGA_SMEM (21248*4)

__device__ __forceinline__ float gelu_tanh(float v) {
    float u = 0.7978845608028654f * (v + 0.044715f * v * v * v);
    u = fminf(fmaxf(u, -15.f), 15.f);
    float e = __expf(-2.f * u);
    float th = (1.f - e) / (1.f + e);
    return 0.5f * v * (1.f + th);
}

__device__ __forceinline__ void calc_dpix(int n, int dpix[9]) {
    int b  = n / SPL, s = n % SPL;
    int hu = s / WUm, wu = s % WUm;
    int hd = hu >> 1, wd = wu >> 1;
    #pragma unroll
    for (int i = 0; i < 3; i++)
        #pragma unroll
        for (int j = 0; j < 3; j++) {
            int hs = min(max(hd - 1 + i, 0), HDm - 1);
            int ws = min(max(wd - 1 + j, 0), WDm - 1);
            dpix[i*3 + j] = b*SDL + hs*WDm + ws;
        }
}

// LayerNorm: 4 lanes per row (shfl reduce), write fp16 A tile (hi only)
__device__ __forceinline__ void ln_writeA(const float* xf,
                                          char* Ahi, int rr, int c4) {
    const float* xr = xf + rr*132 + c4*32;
    float s = 0.f, s2 = 0.f;
    #pragma unroll
    for (int i = 0; i < 8; i++) {
        float4 v = *(const float4*)(xr + i*4);
        s  += (v.x + v.y) + (v.z + v.w);
        s2 += (v.x*v.x + v.y*v.y) + (v.z*v.z + v.w*v.w);
    }
    s  += __shfl_xor_sync(0xffffffffu, s, 1, 4);
    s  += __shfl_xor_sync(0xffffffffu, s, 2, 4);
    s2 += __shfl_xor_sync(0xffffffffu, s2, 1, 4);
    s2 += __shfl_xor_sync(0xffffffffu, s2, 2, 4);
    float mu   = s * (1.f/128.f);
    float rstd = rsqrtf(s2*(1.f/128.f) - mu*mu + 1e-6f);
    #pragma unroll
    for (int j = 0; j < 32; j += 2) {
        float v0 = (xr[j]   - mu) * rstd;
        float v1 = (xr[j+1] - mu) * rstd;
        w2a_hi(Ahi, rr, c4*32 + j, v0, v1);
    }
}

#define ZACC() do { _Pragma("unroll") \
    for (int _i = 0; _i < 8; _i++) { acc[_i][0]=acc[_i][1]=acc[_i][2]=acc[_i][3]=0.f; } } while(0)

__global__ void __launch_bounds__(256, 2) mega_kernel(
    const float* __restrict__ bq,  const float* __restrict__ bo,
    const float* __restrict__ b1,  const float* __restrict__ b2,
    const float* __restrict__ bqf, float* __restrict__ out)
{
    extern __shared__ __align__(16) float smf[];
    char*  sAhi = (char*)(smf);
    char*  sBhi = (char*)(smf + 4352);
    float* qbuf = smf + 4352;            // aliases sBhi + spare (sequenced)
    float* xf   = smf + 12800;           // 64 x 132

    const int t    = threadIdx.x;
    const int lane = t & 31;
    const int w    = t >> 5;
    const int gid  = lane >> 2, tid = lane & 3;
    const int mrow = (w & 3) * 16;        // warp row block
    const int nh   = w >> 2;              // warp col half
    const int r0f  = mrow + gid;          // fragment rows
    const int r1f  = r0f + 8;
    const int rr   = t >> 2;              // pixel row (LN)
    const int c4   = t & 3;               // col chunk (LN)
    const int j8   = lane >> 3;           // gather group in warp
    const int l8   = lane & 7;            // lane in gather group
    const int n0   = blockIdx.x * 64;

    float acc[8][4];
    PF pf;
    pf_load(pf, 0, 0, t);                 // prefetch wq[l=0] half0

    // load x into xf (stride 132)
    {
        const float* src = g_x + (size_t)(n0 + rr)*DI + c4*32;
        float* dst = xf + rr*132 + c4*32;
        #pragma unroll
        for (int i = 0; i < 8; i++)
            *(float4*)(dst + i*4) = *(const float4*)(src + i*4);
    }
    __syncthreads();

    for (int l = 0; l < 2; l++) {
        int tb = l*10;

        // ===== q = LN(x) @ wq (bias added in attention) =====
        ln_writeA(xf, sAhi, rr, c4);
        ZACC();
        gemm_tile_pf1(pf, sAhi, sBhi, acc, tb + 0, tb + 1, mrow, nh, lane, t);
        #pragma unroll
        for (int nt = 0; nt < 8; nt++) {       // frag -> qbuf (sB free)
            int c = nh*64 + 8*nt + 2*tid;
            *(float2*)(qbuf + r0f*132 + c) = make_float2(acc[nt][0], acc[nt][1]);
            *(float2*)(qbuf + r1f*132 + c) = make_float2(acc[nt][2], acc[nt][3]);
        }
        __syncthreads();

        // ===== attention: 8-lane cooperative gathers, 8 rounds =====
        for (int ro = 0; ro < 8; ro++) {
            int g = ro*32 + w*4 + j8;          // pixel-head 0..255
            int p = g >> 2, h = g & 3;
            int dpix[9];
            calc_dpix(n0 + p, dpix);
            float4 qv = *(const float4*)(qbuf + p*132 + h*32 + l8*4);
            float4 bv = *(const float4*)(bq + l*DI + h*32 + l8*4);
            float q0 = qv.x + bv.x, q1 = qv.y + bv.y;
            float q2 = qv.z + bv.z, q3 = qv.w + bv.w;
            float lo[9];
            float m = -1e30f;
            #pragma unroll
            for (int kk = 0; kk < 9; kk++) {
                const float* kv = g_kvp + (size_t)dpix[kk]*KVP + l*256
                                  + h*32 + l8*4;
                float4 k4 = __ldg((const float4*)kv);
                float d = q0*k4.x + q1*k4.y + q2*k4.z + q3*k4.w;
                d += __shfl_xor_sync(0xffffffffu, d, 1, 8);
                d += __shfl_xor_sync(0xffffffffu, d, 2, 8);
                d += __shfl_xor_sync(0xffffffffu, d, 4, 8);
                lo[kk] = d * 0.17677669529663687f;
                m = fmaxf(m, lo[kk]);
            }
            float ssum = 0.f;
            #pragma unroll
            for (int kk = 0; kk < 9; kk++) {
                lo[kk] = __expf(lo[kk] - m);
                ssum += lo[kk];
            }
            float inv = 1.f / ssum;
            float o0 = 0.f, o1 = 0.f, o2 = 0.f, o3 = 0.f;
            #pragma unroll
            for (int kk = 0; kk < 9; kk++) {
                float wgt = lo[kk] * inv;
                const float* vv = g_kvp + (size_t)dpix[kk]*KVP + l*256 + 128
                                  + h*32 + l8*4;
                float4 v = __ldg((const float4*)vv);
                o0 += wgt*v.x; o1 += wgt*v.y; o2 += wgt*v.z; o3 += wgt*v.w;
            }
            w2a_hi(sAhi, p, h*32 + l8*4,     o0, o1);
            w2a_hi(sAhi, p, h*32 + l8*4 + 2, o2, o3);
        }
        __syncthreads();                     // qbuf reads done (sB reusable)

        // ===== x += o @ wo + bo =====
        ZACC();
        gemm_tile_pf1(pf, sAhi, sBhi, acc, tb + 1, tb + 2, mrow, nh, lane, t);
        #pragma unroll
        for (int nt = 0; nt < 8; nt++) {
            int c = nh*64 + 8*nt + 2*tid;
            float2 b = *(const float2*)(bo + l*DI + c);
            float2* p0 = (float2*)(xf + r0f*132 + c);
            float2* p1 = (float2*)(xf + r1f*132 + c);
            float2 v0 = *p0, v1 = *p1;
            v0.x += acc[nt][0] + b.x; v0.y += acc[nt][1] + b.y;
            v1.x += acc[nt][2] + b.x; v1.y += acc[nt][3] + b.y;
            *p0 = v0; *p1 = v1;
        }
        __syncthreads();

        // ===== MLP: 4 chunks; gelu(h) -> sA =====
        for (int hc = 0; hc < 4; hc++) {
            ln_writeA(xf, sAhi, rr, c4);
            ZACC();
            gemm_tile_pf1(pf, sAhi, sBhi, acc, tb + 2 + hc,
                          tb + 6 + hc, mrow, nh, lane, t);
            #pragma unroll
            for (int nt = 0; nt < 8; nt++) {    // gelu -> sA (overwrite LN)
                int c = nh*64 + 8*nt + 2*tid;
                float2 b = *(const float2*)(b1 + l*512 + hc*128 + c);
                w2a_hi(sAhi, r0f, c,
                       gelu_tanh(acc[nt][0] + b.x), gelu_tanh(acc[nt][1] + b.y));
                w2a_hi(sAhi, r1f, c,
                       gelu_tanh(acc[nt][2] + b.x), gelu_tanh(acc[nt][3] + b.y));
            }
            __syncthreads();
            int nxt = (hc < 3) ? (tb + 3 + hc) : ((l == 0) ? 10 : 20);
            ZACC();
            gemm_tile_pf1(pf, sAhi, sBhi, acc, tb + 6 + hc,
                          nxt, mrow, nh, lane, t);
            #pragma unroll
            for (int nt = 0; nt < 8; nt++) {    // += into xf (+b2 on last)
                int c = nh*64 + 8*nt + 2*tid;
                float2 b = (hc == 3) ? *(const float2*)(b2 + l*DI + c)
                                     : make_float2(0.f, 0.f);
                float2* p0 = (float2*)(xf + r0f*132 + c);
                float2* p1 = (float2*)(xf + r1f*132 + c);
                float2 v0 = *p0, v1 = *p1;
                v0.x += acc[nt][0] + b.x; v0.y += acc[nt][1] + b.y;
                v1.x += acc[nt][2] + b.x; v1.y += acc[nt][3] + b.y;
                *p0 = v0; *p1 = v1;
            }
            __syncthreads();
        }
    }

    // ===== final: xq = LN(x) @ wqf + bqf -> qbuf =====
    ln_writeA(xf, sAhi, rr, c4);
    ZACC();
    gemm_tile_pf1(pf, sAhi, sBhi, acc, 20, -1, mrow, nh, lane, t);
    #pragma unroll
    for (int nt = 0; nt < 8; nt++) {
        int c = nh*64 + 8*nt + 2*tid;
        float2 b = *(const float2*)(bqf + c);
        *(float2*)(qbuf + r0f*132 + c) = make_float2(acc[nt][0]+b.x, acc[nt][1]+b.y);
        *(float2*)(qbuf + r1f*132 + c) = make_float2(acc[nt][2]+b.x, acc[nt][3]+b.y);
    }
    __syncthreads();

    // ===== logits + 9-way softmax: warp w round ro -> pixel ro*8+w =====
    {
        float* probs = smf;                  // reuse sAhi region, [kk][68]
        for (int ro = 0; ro < 8; ro++) {
            int p = ro*8 + w;
            int dpix[9];
            calc_dpix(n0 + p, dpix);
            int cidx = j8*32 + l8*4;
            float4 xv = *(const float4*)(qbuf + p*132 + cidx);
            float lo[9];
            #pragma unroll
            for (int kk = 0; kk < 9; kk++) {
                const float* cp = g_kvp + (size_t)dpix[kk]*KVP + 512 + cidx;
                float4 c4v = __ldg((const float4*)cp);
                float d = xv.x*c4v.x + xv.y*c4v.y + xv.z*c4v.z + xv.w*c4v.w;
                d += __shfl_xor_sync(0xffffffffu, d, 1);
                d += __shfl_xor_sync(0xffffffffu, d, 2);
                d += __shfl_xor_sync(0xffffffffu, d, 4);
                d += __shfl_xor_sync(0xffffffffu, d, 8);
                d += __shfl_xor_sync(0xffffffffu, d, 16);
                lo[kk] = d * 0.08838834764831845f;
            }
            float m = -1e30f;
            #pragma unroll
            for (int kk = 0; kk < 9; kk++) m = fmaxf(m, lo[kk]);
            float ssum = 0.f;
            #pragma unroll
            for (int kk = 0; kk < 9; kk++) {
                lo[kk] = __expf(lo[kk] - m);
                ssum += lo[kk];
            }
            float inv = 1.f / ssum;
            if (lane == 0) {
                #pragma unroll
                for (int kk = 0; kk < 9; kk++)
                    probs[kk*68 + p] = lo[kk] * inv;
            }
        }
        __syncthreads();
        int b = n0 / SPL, s0 = n0 % SPL;
        for (int f = t; f < 9*64; f += 256) {
            int kk = f >> 6, p = f & 63;
            out[(size_t)b*9*SPL + (size_t)kk*SPL + s0 + p] = probs[kk*68 + p];
        }
    }
}

// ========================================================================
extern "C" void kernel_launch(void* const* d_in, const int* in_sizes, int n_in,
                              void* d_out, int out_size) {
    const float* feat_map    = (const float*)d_in[0];
    const float* feat_map_up = (const float*)d_in[1];
    const float* nc_w = (const float*)d_in[2];
    const float* nc_b = (const float*)d_in[3];
    const float* wq   = (const float*)d_in[4];
    const float* bq   = (const float*)d_in[5];
    const float* wkv  = (const float*)d_in[6];
    const float* bkv  = (const float*)d_in[7];
    const float* wo   = (const float*)d_in[8];
    const float* bo   = (const float*)d_in[9];
    const float* w1   = (const float*)d_in[10];
    const float* b1   = (const float*)d_in[11];
    const float* w2   = (const float*)d_in[12];
    const float* b2   = (const float*)d_in[13];
    const float* wqf  = (const float*)d_in[14];
    const float* bqf  = (const float*)d_in[15];
    const float* wcf  = (const float*)d_in[16];
    const float* bcf  = (const float*)d_in[17];
    float* out = (float*)d_out;

    cudaFuncSetAttribute(dgemm_kernel,
                         cudaFuncAttributeMaxDynamicSharedMemorySize, DGEMM_SMEM);
    cudaFuncSetAttribute(mega_kernel,
                         cudaFuncAttributeMaxDynamicSharedMemorySize, MEGA_SMEM);

    prep_kernel<<<3, 256>>>(nc_w, nc_b, wkv, bkv, wcf, bcf);
    prepw_kernel<<<NTILES, 256>>>(wq, wo, w1, w2, wqf);
    trln_kernel<<<ND/32, 256>>>(feat_map);
    trx_kernel<<<NP/32, 256>>>(feat_map_up);
    dgemm_kernel<<<ND/64, 256, DGEMM_SMEM>>>();
    mega_kernel<<<NP/64, 256, MEGA_SMEM>>>(bq, bo, b1, b2, bqf, out);
}

// round 16
// speedup vs baseline: 6.1243x; 1.1174x over previous
#include <cuda_runtime.h>
#include <cuda_bf16.h>
#include <cuda_fp16.h>
#include <cstdint>

// ---------------- problem constants ----------------
#define DI   128
#define BATCH 2
#define HDm  64
#define WDm  96
#define HUm  128
#define WUm  192
#define SDL  (HDm*WDm)           // 6144
#define SPL  (HUm*WUm)           // 24576
#define ND   (BATCH*SDL)         // 12288
#define NP   (BATCH*SPL)         // 49152
#define KVP  640                 // kv0(256) | kv1(256) | ctxp(128)
#define NTILES 26                // 0-20 transformer, 21-25 folded kv/ctxp
#define WTS  17408               // fp16 per weight tile (128 x 136)

typedef unsigned long long u64;

// ---------------- device scratch ----------------
__device__ float g_ctxln[ND*DI];
__device__ float g_x[NP*DI];
__device__ float g_kvp[ND*KVP];
__device__ float g_W[DI*KVP];
__device__ float g_bias[KVP];
__device__ __half g_Whi[NTILES*WTS];   // [k][n] tiles, stride 136

// ---------------- HMMA helpers (plain PTX, sm_80+) ----------------
__device__ __forceinline__ uint32_t smem_u32(const void* p) {
    uint32_t a;
    asm("{ .reg .u64 t; cvta.to.shared.u64 t, %1; cvt.u32.u64 %0, t; }"
        : "=r"(a) : "l"(p));
    return a;
}
__device__ __forceinline__ void ldsm_x4(uint32_t r[4], uint32_t addr) {
    asm volatile("ldmatrix.sync.aligned.m8n8.x4.shared.b16 {%0,%1,%2,%3}, [%4];"
        : "=r"(r[0]), "=r"(r[1]), "=r"(r[2]), "=r"(r[3]) : "r"(addr));
}
__device__ __forceinline__ void ldsm_x4t(uint32_t r[4], uint32_t addr) {
    asm volatile("ldmatrix.sync.aligned.m8n8.x4.trans.shared.b16 {%0,%1,%2,%3}, [%4];"
        : "=r"(r[0]), "=r"(r[1]), "=r"(r[2]), "=r"(r[3]) : "r"(addr));
}
__device__ __forceinline__ void mma16816(float d[4], const uint32_t a[4],
                                         const uint32_t b[2]) {
    asm volatile(
        "mma.sync.aligned.m16n8k16.row.col.f32.f16.f16.f32 "
        "{%0,%1,%2,%3}, {%4,%5,%6,%7}, {%8,%9}, {%0,%1,%2,%3};"
        : "+f"(d[0]), "+f"(d[1]), "+f"(d[2]), "+f"(d[3])
        : "r"(a[0]), "r"(a[1]), "r"(a[2]), "r"(a[3]), "r"(b[0]), "r"(b[1]));
}

// write split-fp16 pair at (r, c..c+1), row stride 272 B (hi+lo, dgemm)
__device__ __forceinline__ void w2a(char* hi, char* lo, int r, int c,
                                    float v0, float v1) {
    __half h0 = __float2half_rn(v0), h1 = __float2half_rn(v1);
    float l0 = v0 - __half2float(h0);
    float l1 = v1 - __half2float(h1);
    __half2 H = __halves2half2(h0, h1);
    __half2 L = __halves2half2(__float2half_rn(l0), __float2half_rn(l1));
    int off = r*272 + c*2;
    *(uint32_t*)(hi + off) = *(uint32_t*)&H;
    *(uint32_t*)(lo + off) = *(uint32_t*)&L;
}
// hi-only variant (mega)
__device__ __forceinline__ void w2a_hi(char* hi, int r, int c,
                                       float v0, float v1) {
    __half2 H = __halves2half2(__float2half_rn(v0), __float2half_rn(v1));
    *(uint32_t*)(hi + r*272 + c*2) = *(uint32_t*)&H;
}

// ---- half-K warp GEMM, split-A 2-term (dgemm) ----
__device__ __forceinline__ void wgemm_half(const char* Ahi, const char* Alo,
                                           const char* Bhi,
                                           float acc[8][4], int mrow, int nh,
                                           int lane, int kh) {
    uint32_t aHi = smem_u32(Ahi), aLo = smem_u32(Alo);
    uint32_t bHi = smem_u32(Bhi);
    int mat = lane >> 3, r8 = lane & 7;
    uint32_t aRow = (uint32_t)((mrow + (mat & 1)*8 + r8) * 272
                               + (mat >> 1) * 16 + kh*128);
    uint32_t bBase = (uint32_t)(((mat & 1)*8 + r8) * 272
                                + (mat >> 1) * 16 + nh*128);
    #pragma unroll
    for (int ks = 0; ks < 4; ks++) {
        uint32_t Ah[4], Al[4];
        ldsm_x4(Ah, aHi + aRow + ks*32);
        ldsm_x4(Al, aLo + aRow + ks*32);
        uint32_t bko = bBase + (uint32_t)(ks*16*272);
        #pragma unroll
        for (int np = 0; np < 4; np++) {
            uint32_t Bh[4];
            ldsm_x4t(Bh, bHi + bko + np*32);
            mma16816(acc[2*np],   Ah, Bh);
            mma16816(acc[2*np],   Al, Bh);
            mma16816(acc[2*np+1], Ah, Bh+2);
            mma16816(acc[2*np+1], Al, Bh+2);
        }
    }
}

// ---- half-K warp GEMM, pure fp16 single-term (mega) ----
__device__ __forceinline__ void wgemm_half1(const char* Ahi, const char* Bhi,
                                            float acc[8][4], int mrow, int nh,
                                            int lane, int kh) {
    uint32_t aHi = smem_u32(Ahi);
    uint32_t bHi = smem_u32(Bhi);
    int mat = lane >> 3, r8 = lane & 7;
    uint32_t aRow = (uint32_t)((mrow + (mat & 1)*8 + r8) * 272
                               + (mat >> 1) * 16 + kh*128);
    uint32_t bBase = (uint32_t)(((mat & 1)*8 + r8) * 272
                                + (mat >> 1) * 16 + nh*128);
    #pragma unroll
    for (int ks = 0; ks < 4; ks++) {
        uint32_t Ah[4];
        ldsm_x4(Ah, aHi + aRow + ks*32);
        uint32_t bko = bBase + (uint32_t)(ks*16*272);
        #pragma unroll
        for (int np = 0; np < 4; np++) {
            uint32_t Bh[4];
            ldsm_x4t(Bh, bHi + bko + np*32);
            mma16816(acc[2*np],   Ah, Bh);
            mma16816(acc[2*np+1], Ah, Bh+2);
        }
    }
}

// ---- register prefetch of one B half (1088 float4) ----
struct PF { float4 h[5]; };

__device__ __forceinline__ void pf_load(PF& pf, int tile, int kh, int t) {
    const float4* sh = (const float4*)(g_Whi + (size_t)tile*WTS + kh*64*136);
    #pragma unroll
    for (int i = 0; i < 5; i++) {
        int f = t + i*256;
        if (f < 1088) pf.h[i] = __ldg(sh + f);
    }
}
__device__ __forceinline__ void pf_store(const PF& pf, char* Bhi, int t) {
    float4* dh = (float4*)Bhi;
    #pragma unroll
    for (int i = 0; i < 5; i++) {
        int f = t + i*256;
        if (f < 1088) dh[f] = pf.h[i];
    }
}

// pipelined tile, 2-term single buffer (dgemm, unchanged from R15)
__device__ __forceinline__ void gemm_tile_pf(PF& pf,
                                             const char* sAhi, const char* sAlo,
                                             char* sBhi,
                                             float acc[8][4], int tile,
                                             int next_tile,
                                             int mrow, int nh, int lane, int t) {
    pf_store(pf, sBhi, t);
    __syncthreads();
    pf_load(pf, tile, 1, t);
    wgemm_half(sAhi, sAlo, sBhi, acc, mrow, nh, lane, 0);
    __syncthreads();
    pf_store(pf, sBhi, t);
    __syncthreads();
    if (next_tile >= 0) pf_load(pf, next_tile, 0, t);
    wgemm_half(sAhi, sAlo, sBhi, acc, mrow, nh, lane, 1);
    __syncthreads();
}

// double-buffered single-term tile (mega): 2 syncs, NO trailing sync.
// pf holds half0 of `tile` on entry; half0 of `next_tile` on exit.
__device__ __forceinline__ void gemm_tile_db1(PF& pf, const char* sAhi,
                                              char* sB0, char* sB1,
                                              float acc[8][4], int tile,
                                              int next_tile,
                                              int mrow, int nh, int lane, int t) {
    pf_store(pf, sB0, t);
    pf_load(pf, tile, 1, t);
    __syncthreads();                       // sB0 ready
    wgemm_half1(sAhi, sB0, acc, mrow, nh, lane, 0);
    pf_store(pf, sB1, t);                  // B1 readers retired pre-sync
    if (next_tile >= 0) pf_load(pf, next_tile, 0, t);
    __syncthreads();                       // sB1 ready, B0 reads done
    wgemm_half1(sAhi, sB1, acc, mrow, nh, lane, 1);
}

// ========================================================================
// K1: fold nc_w/nc_b into combined kv/ctxp weight
// ========================================================================
__global__ void prep_kernel(const float* __restrict__ nc_w,
                            const float* __restrict__ nc_b,
                            const float* __restrict__ wkv,
                            const float* __restrict__ bkv,
                            const float* __restrict__ wcf,
                            const float* __restrict__ bcf) {
    int j = blockIdx.x * blockDim.x + threadIdx.x;
    if (j >= KVP) return;
    if (j < 512) {
        int l  = j >> 8;
        int jj = j & 255;
        const float* w = wkv + (size_t)l * DI * 256;
        float bias = bkv[l*256 + jj];
        for (int c = 0; c < DI; c++) {
            float wv = w[c*256 + jj];
            g_W[c*KVP + j] = nc_w[l*DI + c] * wv;
            bias += nc_b[l*DI + c] * wv;
        }
        g_bias[j] = bias;
    } else {
        int jj = j - 512;
        for (int c = 0; c < DI; c++)
            g_W[c*KVP + j] = wcf[c*DI + jj];
        g_bias[j] = bcf[jj];
    }
}

// ========================================================================
// K1b: fp16(hi) weight tiles, [k][n] stride 136
// ========================================================================
__global__ void prepw_kernel(const float* __restrict__ wq,
                             const float* __restrict__ wo,
                             const float* __restrict__ w1,
                             const float* __restrict__ w2,
                             const float* __restrict__ wqf) {
    int tile = blockIdx.x;
    for (int idx = threadIdx.x; idx < DI*DI; idx += blockDim.x) {
        int k = idx >> 7, n = idx & 127;
        float w;
        if (tile >= 21)      w = g_W[k*KVP + (tile-21)*128 + n];
        else if (tile == 20) w = wqf[k*DI + n];
        else {
            int l = tile / 10, s = tile % 10;
            if (s == 0)      w = wq[l*DI*DI + k*DI + n];
            else if (s == 1) w = wo[l*DI*DI + k*DI + n];
            else if (s < 6)  w = w1[l*DI*512 + k*512 + (s-2)*128 + n];
            else             w = w2[l*512*DI + ((s-6)*128 + k)*DI + n];
        }
        g_Whi[(size_t)tile*WTS + k*136 + n] = __float2half_rn(w);
    }
}

// ========================================================================
// K2: transpose feat_map + fused LayerNorm (coalesced writes)
// ========================================================================
__global__ void trln_kernel(const float* __restrict__ fm) {
    __shared__ float st[DI][33];
    __shared__ float mu_s[32], rs_s[32];
    int dp0 = blockIdx.x * 32;
    int b = dp0 / SDL, hw0 = dp0 % SDL;
    const float* src = fm + (size_t)b * DI * SDL + hw0;
    int t = threadIdx.x;
    #pragma unroll
    for (int i = 0; i < 16; i++) {
        int e = t + i*256;
        int c = e >> 5, p = e & 31;
        st[c][p] = src[(size_t)c*SDL + p];
    }
    __syncthreads();
    int p = t >> 3, g = t & 7;
    float s = 0.f, s2 = 0.f;
    #pragma unroll
    for (int i = 0; i < 16; i++) {
        float v = st[g*16 + i][p];
        s += v; s2 += v*v;
    }
    #pragma unroll
    for (int off = 4; off; off >>= 1) {
        s  += __shfl_xor_sync(0xffffffffu, s,  off, 8);
        s2 += __shfl_xor_sync(0xffffffffu, s2, off, 8);
    }
    if (g == 0) {
        float mu = s * (1.f/128.f);
        mu_s[p] = mu;
        rs_s[p] = rsqrtf(s2*(1.f/128.f) - mu*mu + 1e-6f);
    }
    __syncthreads();
    #pragma unroll
    for (int i = 0; i < 16; i++) {
        int f = t + i*256;
        int r = f >> 7, c = f & 127;
        g_ctxln[(size_t)(dp0 + r)*DI + c] = (st[c][r] - mu_s[r]) * rs_s[r];
    }
}

// ========================================================================
// K3: transpose feat_map_up -> x rows (coalesced writes)
// ========================================================================
__global__ void trx_kernel(const float* __restrict__ fmu) {
    __shared__ float st[DI][33];
    int n0 = blockIdx.x * 32;
    int b = n0 / SPL, s0 = n0 % SPL;
    const float* src = fmu + (size_t)b * DI * SPL + s0;
    int t = threadIdx.x;
    #pragma unroll
    for (int i = 0; i < 16; i++) {
        int e = t + i*256;
        int c = e >> 5, p = e & 31;
        st[c][p] = src[(size_t)c*SPL + p];
    }
    __syncthreads();
    #pragma unroll
    for (int i = 0; i < 16; i++) {
        int f = t + i*256;
        int r = f >> 7, c = f & 127;
        g_x[(size_t)(n0 + r)*DI + c] = st[c][r];
    }
}

// ========================================================================
// K4: per-dpixel GEMM  g_kvp = g_ctxln @ g_W + g_bias  (split-A 2-term)
// SMEM: sAhi 4352 | sAlo 4352 | sBhi 4352 = 13056 floats (52.2KB), 2 CTAs/SM
// ========================================================================
#define DGEMM_SMEM (13056*4)
__global__ void __launch_bounds__(256, 2) dgemm_kernel() {
    extern __shared__ __align__(16) float smf[];
    char* sAhi = (char*)(smf);
    char* sAlo = (char*)(smf + 4352);
    char* sBhi = (char*)(smf + 8704);
    const int t = threadIdx.x, lane = t & 31, w = t >> 5;
    const int gid = lane >> 2, tid = lane & 3;
    const int mrow = (w & 3) * 16;
    const int nh   = w >> 2;
    const int r0f = mrow + gid, r1f = r0f + 8;
    const int n0 = blockIdx.x * 64;

    PF pf;
    pf_load(pf, 21, 0, t);
    for (int f = t; f < 4096; f += 256) {
        int r = f >> 6, c2 = f & 63;
        const float* src = g_ctxln + (size_t)(n0 + r)*DI + 2*c2;
        w2a(sAhi, sAlo, r, 2*c2, src[0], src[1]);
    }
    __syncthreads();

    float acc[8][4];
    for (int i = 0; i < 5; i++) {
        #pragma unroll
        for (int nt = 0; nt < 8; nt++) { acc[nt][0]=acc[nt][1]=acc[nt][2]=acc[nt][3]=0.f; }
        gemm_tile_pf(pf, sAhi, sAlo, sBhi, acc, 21 + i,
                     (i < 4) ? 22 + i : -1, mrow, nh, lane, t);
        #pragma unroll
        for (int nt = 0; nt < 8; nt++) {
            int c = nh*64 + 8*nt + 2*tid;
            float2 b = *(const float2*)(g_bias + i*128 + c);
            *(float2*)(g_kvp + (size_t)(n0+r0f)*KVP + i*128 + c) =
                make_float2(acc[nt][0]+b.x, acc[nt][1]+b.y);
            *(float2*)(g_kvp + (size_t)(n0+r1f)*KVP + i*128 + c) =
                make_float2(acc[nt][2]+b.x, acc[nt][3]+b.y);
        }
    }
}

// ========================================================================
// K5: HMMA mega kernel — 64 pixels/block, 256 threads, db-sB + sAg
// SMEM float offsets:
//   0      sAhi   4352      (probs[9][68] aliases in tail)
//   4352   sAg    4352      (gelu output A tile)
//   8704   sB0    4352      (qbuf[64][132]=8448 spans 8704..17152)
//   13056  sB1    4352
//   17408  xf [64][132]     8448
// total 25856 floats = 103424 B  -> 2 CTAs/SM
// ========================================================================
#define MEGA_SMEM (25856*4)

__device__ __forceinline__ float gelu_tanh(float v) {
    float u = 0.7978845608028654f * (v + 0.044715f * v * v * v);
    u = fminf(fmaxf(u, -15.f), 15.f);
    float e = __expf(-2.f * u);
    float th = (1.f - e) / (1.f + e);
    return 0.5f * v * (1.f + th);
}

__device__ __forceinline__ void calc_dpix(int n, int dpix[9]) {
    int b  = n / SPL, s = n % SPL;
    int hu = s / WUm, wu = s % WUm;
    int hd = hu >> 1, wd = wu >> 1;
    #pragma unroll
    for (int i = 0; i < 3; i++)
        #pragma unroll
        for (int j = 0; j < 3; j++) {
            int hs = min(max(hd - 1 + i, 0), HDm - 1);
            int ws = min(max(wd - 1 + j, 0), WDm - 1);
            dpix[i*3 + j] = b*SDL + hs*WDm + ws;
        }
}

// LayerNorm: 4 lanes per row (shfl reduce), write fp16 A tile (hi only)
__device__ __forceinline__ void ln_writeA(const float* xf,
                                          char* Ahi, int rr, int c4) {
    const float* xr = xf + rr*132 + c4*32;
    float s = 0.f, s2 = 0.f;
    #pragma unroll
    for (int i = 0; i < 8; i++) {
        float4 v = *(const float4*)(xr + i*4);
        s  += (v.x + v.y) + (v.z + v.w);
        s2 += (v.x*v.x + v.y*v.y) + (v.z*v.z + v.w*v.w);
    }
    s  += __shfl_xor_sync(0xffffffffu, s, 1, 4);
    s  += __shfl_xor_sync(0xffffffffu, s, 2, 4);
    s2 += __shfl_xor_sync(0xffffffffu, s2, 1, 4);
    s2 += __shfl_xor_sync(0xffffffffu, s2, 2, 4);
    float mu   = s * (1.f/128.f);
    float rstd = rsqrtf(s2*(1.f/128.f) - mu*mu + 1e-6f);
    #pragma unroll
    for (int j = 0; j < 32; j += 2) {
        float v0 = (xr[j]   - mu) * rstd;
        float v1 = (xr[j+1] - mu) * rstd;
        w2a_hi(Ahi, rr, c4*32 + j, v0, v1);
    }
}

#define ZACC() do { _Pragma("unroll") \
    for (int _i = 0; _i < 8; _i++) { acc[_i][0]=acc[_i][1]=acc[_i][2]=acc[_i][3]=0.f; } } while(0)

__global__ void __launch_bounds__(256, 2) mega_kernel(
    const float* __restrict__ bq,  const float* __restrict__ bo,
    const float* __restrict__ b1,  const float* __restrict__ b2,
    const float* __restrict__ bqf, float* __restrict__ out)
{
    extern __shared__ __align__(16) float smf[];
    char*  sAhi = (char*)(smf);
    char*  sAg  = (char*)(smf + 4352);
    char*  sB0  = (char*)(smf + 8704);
    char*  sB1  = (char*)(smf + 13056);
    float* qbuf = smf + 8704;            // aliases sB0+sB1 (sequenced)
    float* xf   = smf + 17408;           // 64 x 132

    const int t    = threadIdx.x;
    const int lane = t & 31;
    const int w    = t >> 5;
    const int gid  = lane >> 2, tid = lane & 3;
    const int mrow = (w & 3) * 16;        // warp row block
    const int nh   = w >> 2;              // warp col half
    const int r0f  = mrow + gid;          // fragment rows
    const int r1f  = r0f + 8;
    const int rr   = t >> 2;              // pixel row (LN)
    const int c4   = t & 3;               // col chunk (LN)
    const int j8   = lane >> 3;           // gather group in warp
    const int l8   = lane & 7;            // lane in gather group
    const int n0   = blockIdx.x * 64;

    float acc[8][4];
    PF pf;
    pf_load(pf, 0, 0, t);                 // prefetch wq[l=0] half0

    // load x into xf (stride 132)
    {
        const float* src = g_x + (size_t)(n0 + rr)*DI + c4*32;
        float* dst = xf + rr*132 + c4*32;
        #pragma unroll
        for (int i = 0; i < 8; i++)
            *(float4*)(dst + i*4) = *(const float4*)(src + i*4);
    }
    __syncthreads();

    for (int l = 0; l < 2; l++) {
        int tb = l*10;

        // ===== q = LN(x) @ wq (bias added in attention) =====
        ln_writeA(xf, sAhi, rr, c4);
        ZACC();
        gemm_tile_db1(pf, sAhi, sB0, sB1, acc, tb + 0, tb + 1,
                      mrow, nh, lane, t);
        __syncthreads();                       // mma B1 done -> qbuf writable
        #pragma unroll
        for (int nt = 0; nt < 8; nt++) {       // frag -> qbuf
            int c = nh*64 + 8*nt + 2*tid;
            *(float2*)(qbuf + r0f*132 + c) = make_float2(acc[nt][0], acc[nt][1]);
            *(float2*)(qbuf + r1f*132 + c) = make_float2(acc[nt][2], acc[nt][3]);
        }
        __syncthreads();

        // ===== attention: 8-lane cooperative gathers, 8 rounds =====
        for (int ro = 0; ro < 8; ro++) {
            int g = ro*32 + w*4 + j8;          // pixel-head 0..255
            int p = g >> 2, h = g & 3;
            int dpix[9];
            calc_dpix(n0 + p, dpix);
            float4 qv = *(const float4*)(qbuf + p*132 + h*32 + l8*4);
            float4 bv = *(const float4*)(bq + l*DI + h*32 + l8*4);
            float q0 = qv.x + bv.x, q1 = qv.y + bv.y;
            float q2 = qv.z + bv.z, q3 = qv.w + bv.w;
            float lo[9];
            float m = -1e30f;
            #pragma unroll
            for (int kk = 0; kk < 9; kk++) {
                const float* kv = g_kvp + (size_t)dpix[kk]*KVP + l*256
                                  + h*32 + l8*4;
                float4 k4 = __ldg((const float4*)kv);
                float d = q0*k4.x + q1*k4.y + q2*k4.z + q3*k4.w;
                d += __shfl_xor_sync(0xffffffffu, d, 1, 8);
                d += __shfl_xor_sync(0xffffffffu, d, 2, 8);
                d += __shfl_xor_sync(0xffffffffu, d, 4, 8);
                lo[kk] = d * 0.17677669529663687f;
                m = fmaxf(m, lo[kk]);
            }
            float ssum = 0.f;
            #pragma unroll
            for (int kk = 0; kk < 9; kk++) {
                lo[kk] = __expf(lo[kk] - m);
                ssum += lo[kk];
            }
            float inv = 1.f / ssum;
            float o0 = 0.f, o1 = 0.f, o2 = 0.f, o3 = 0.f;
            #pragma unroll
            for (int kk = 0; kk < 9; kk++) {
                float wgt = lo[kk] * inv;
                const float* vv = g_kvp + (size_t)dpix[kk]*KVP + l*256 + 128
                                  + h*32 + l8*4;
                float4 v = __ldg((const float4*)vv);
                o0 += wgt*v.x; o1 += wgt*v.y; o2 += wgt*v.z; o3 += wgt*v.w;
            }
            w2a_hi(sAhi, p, h*32 + l8*4,     o0, o1);
            w2a_hi(sAhi, p, h*32 + l8*4 + 2, o2, o3);
        }
        __syncthreads();                     // qbuf reads + sAhi writes done

        // ===== x += o @ wo + bo =====
        ZACC();
        gemm_tile_db1(pf, sAhi, sB0, sB1, acc, tb + 1, tb + 2,
                      mrow, nh, lane, t);
        #pragma unroll
        for (int nt = 0; nt < 8; nt++) {     // xf-only epilogue, no hazard
            int c = nh*64 + 8*nt + 2*tid;
            float2 b = *(const float2*)(bo + l*DI + c);
            float2* p0 = (float2*)(xf + r0f*132 + c);
            float2* p1 = (float2*)(xf + r1f*132 + c);
            float2 v0 = *p0, v1 = *p1;
            v0.x += acc[nt][0] + b.x; v0.y += acc[nt][1] + b.y;
            v1.x += acc[nt][2] + b.x; v1.y += acc[nt][3] + b.y;
            *p0 = v0; *p1 = v1;
        }
        __syncthreads();                     // xf ready for LN

        // ===== MLP: LN once; w1 reads sAhi, gelu -> sAg, w2 reads sAg =====
        ln_writeA(xf, sAhi, rr, c4);
        for (int hc = 0; hc < 4; hc++) {
            ZACC();
            gemm_tile_db1(pf, sAhi, sB0, sB1, acc, tb + 2 + hc,
                          tb + 6 + hc, mrow, nh, lane, t);
            #pragma unroll
            for (int nt = 0; nt < 8; nt++) {    // gelu -> sAg (no hazard)
                int c = nh*64 + 8*nt + 2*tid;
                float2 b = *(const float2*)(b1 + l*512 + hc*128 + c);
                w2a_hi(sAg, r0f, c,
                       gelu_tanh(acc[nt][0] + b.x), gelu_tanh(acc[nt][1] + b.y));
                w2a_hi(sAg, r1f, c,
                       gelu_tanh(acc[nt][2] + b.x), gelu_tanh(acc[nt][3] + b.y));
            }
            int nxt = (hc < 3) ? (tb + 3 + hc) : ((l == 0) ? 10 : 20);
            ZACC();
            gemm_tile_db1(pf, sAg, sB0, sB1, acc, tb + 6 + hc,
                          nxt, mrow, nh, lane, t);
            #pragma unroll
            for (int nt = 0; nt < 8; nt++) {    // += into xf (+b2 on last)
                int c = nh*64 + 8*nt + 2*tid;
                float2 b = (hc == 3) ? *(const float2*)(b2 + l*DI + c)
                                     : make_float2(0.f, 0.f);
                float2* p0 = (float2*)(xf + r0f*132 + c);
                float2* p1 = (float2*)(xf + r1f*132 + c);
                float2 v0 = *p0, v1 = *p1;
                v0.x += acc[nt][0] + b.x; v0.y += acc[nt][1] + b.y;
                v1.x += acc[nt][2] + b.x; v1.y += acc[nt][3] + b.y;
                *p0 = v0; *p1 = v1;
            }
        }
        __syncthreads();                     // xf complete for next LN
    }

    // ===== final: xq = LN(x) @ wqf + bqf -> qbuf =====
    ln_writeA(xf, sAhi, rr, c4);
    ZACC();
    gemm_tile_db1(pf, sAhi, sB0, sB1, acc, 20, -1, mrow, nh, lane, t);
    __syncthreads();                         // mma done -> qbuf writable
    #pragma unroll
    for (int nt = 0; nt < 8; nt++) {
        int c = nh*64 + 8*nt + 2*tid;
        float2 b = *(const float2*)(bqf + c);
        *(float2*)(qbuf + r0f*132 + c) = make_float2(acc[nt][0]+b.x, acc[nt][1]+b.y);
        *(float2*)(qbuf + r1f*132 + c) = make_float2(acc[nt][2]+b.x, acc[nt][3]+b.y);
    }
    __syncthreads();

    // ===== logits + 9-way softmax: warp w round ro -> pixel ro*8+w =====
    {
        float* probs = smf;                  // reuse sAhi region, [kk][68]
        for (int ro = 0; ro < 8; ro++) {
            int p = ro*8 + w;
            int dpix[9];
            calc_dpix(n0 + p, dpix);
            int cidx = j8*32 + l8*4;
            float4 xv = *(const float4*)(qbuf + p*132 + cidx);
            float lo[9];
            #pragma unroll
            for (int kk = 0; kk < 9; kk++) {
                const float* cp = g_kvp + (size_t)dpix[kk]*KVP + 512 + cidx;
                float4 c4v = __ldg((const float4*)cp);
                float d = xv.x*c4v.x + xv.y*c4v.y + xv.z*c4v.z + xv.w*c4v.w;
                d += __shfl_xor_sync(0xffffffffu, d, 1);
                d += __shfl_xor_sync(0xffffffffu, d, 2);
                d += __shfl_xor_sync(0xffffffffu, d, 4);
                d += __shfl_xor_sync(0xffffffffu, d, 8);
                d += __shfl_xor_sync(0xffffffffu, d, 16);
                lo[kk] = d * 0.08838834764831845f;
            }
            float m = -1e30f;
            #pragma unroll
            for (int kk = 0; kk < 9; kk++) m = fmaxf(m, lo[kk]);
            float ssum = 0.f;
            #pragma unroll
            for (int kk = 0; kk < 9; kk++) {
                lo[kk] = __expf(lo[kk] - m);
                ssum += lo[kk];
            }
            float inv = 1.f / ssum;
            if (lane == 0) {
                #pragma unroll
                for (int kk = 0; kk < 9; kk++)
                    probs[kk*68 + p] = lo[kk] * inv;
            }
        }
        __syncthreads();
        int b = n0 / SPL, s0 = n0 % SPL;
        for (int f = t; f < 9*64; f += 256) {
            int kk = f >> 6, p = f & 63;
            out[(size_t)b*9*SPL + (size_t)kk*SPL + s0 + p] = probs[kk*68 + p];
        }
    }
}

// ========================================================================
extern "C" void kernel_launch(void* const* d_in, const int* in_sizes, int n_in,
                              void* d_out, int out_size) {
    const float* feat_map    = (const float*)d_in[0];
    const float* feat_map_up = (const float*)d_in[1];
    const float* nc_w = (const float*)d_in[2];
    const float* nc_b = (const float*)d_in[3];
    const float* wq   = (const float*)d_in[4];
    const float* bq   = (const float*)d_in[5];
    const float* wkv  = (const float*)d_in[6];
    const float* bkv  = (const float*)d_in[7];
    const float* wo   = (const float*)d_in[8];
    const float* bo   = (const float*)d_in[9];
    const float* w1   = (const float*)d_in[10];
    const float* b1   = (const float*)d_in[11];
    const float* w2   = (const float*)d_in[12];
    const float* b2   = (const float*)d_in[13];
    const float* wqf  = (const float*)d_in[14];
    const float* bqf  = (const float*)d_in[15];
    const float* wcf  = (const float*)d_in[16];
    const float* bcf  = (const float*)d_in[17];
    float* out = (float*)d_out;

    cudaFuncSetAttribute(dgemm_kernel,
                         cudaFuncAttributeMaxDynamicSharedMemorySize, DGEMM_SMEM);
    cudaFuncSetAttribute(mega_kernel,
                         cudaFuncAttributeMaxDynamicSharedMemorySize, MEGA_SMEM);

    prep_kernel<<<3, 256>>>(nc_w, nc_b, wkv, bkv, wcf, bcf);
    prepw_kernel<<<NTILES, 256>>>(wq, wo, w1, w2, wqf);
    trln_kernel<<<ND/32, 256>>>(feat_map);
    trx_kernel<<<NP/32, 256>>>(feat_map_up);
    dgemm_kernel<<<ND/64, 256, DGEMM_SMEM>>>();
    mega_kernel<<<NP/64, 256, MEGA_SMEM>>>(bq, bo, b1, b2, bqf, out);
}